// round 11
// baseline (speedup 1.0000x reference)
#include <cuda_runtime.h>
#include <cuda_bf16.h>
#include <math.h>
#include <stdint.h>
#include <stddef.h>

#define T_LEN 256
#define B_SZ  256
#define H_DIM 512
#define R_ROWS 768
#define G_COLS 2048
#define M_ALL  196608
#define V_SZ   32000
#define H5 102
#define RH 393216            // R_ROWS * H_DIM

// ---------------- static device scratch --------------------------------------
__device__ float d_Gbuf[402653184];   // [T][768][2048] h@Wx + b (layers 2,3)
__device__ float d_tab[65536000];     // [32000][2048] emb@Wx0 + b0
__device__ float d_cst[393216];
__device__ float d_rbuf[393216];
__device__ float d_h1buf[262144];
__device__ float d_h2buf[26112];
__device__ int   d_toks[196608];      // [3][256][256]
__device__ unsigned d_barGen;
__device__ unsigned d_barCnt;
__device__ __nv_bfloat16 d_Ehi[16384000];           // emb split [32000][512]
__device__ __nv_bfloat16 d_Elo[16384000];
__device__ __nv_bfloat16 d_WhPhi[3 * 2048 * 512];   // Wh permuted [n'][k] hi
__device__ __nv_bfloat16 d_WhPlo[3 * 2048 * 512];
__device__ __nv_bfloat16 d_WxThi[3 * 2048 * 512];   // Wx transposed [n][k] hi
__device__ __nv_bfloat16 d_WxTlo[3 * 2048 * 512];
__device__ __nv_bfloat16 d_sAhi[100663296];         // h seq splits (ping)
__device__ __nv_bfloat16 d_sAlo[100663296];
__device__ __nv_bfloat16 d_sBhi[100663296];         // (pong)
__device__ __nv_bfloat16 d_sBlo[100663296];

// ---------------- helpers ------------------------------------------------------
__device__ __forceinline__ uint32_t smem_to_u32(const void* p) {
    uint32_t a;
    asm("{ .reg .u64 t; cvta.to.shared.u64 t, %1; cvt.u32.u64 %0, t; }"
        : "=r"(a) : "l"(p));
    return a;
}
__device__ __forceinline__ void ldmx4(uint32_t* r, uint32_t addr) {
    asm volatile("ldmatrix.sync.aligned.m8n8.x4.shared.b16 {%0,%1,%2,%3}, [%4];"
                 : "=r"(r[0]), "=r"(r[1]), "=r"(r[2]), "=r"(r[3]) : "r"(addr));
}
__device__ __forceinline__ void mma_bf16(float* c, const uint32_t* a,
                                         uint32_t b0, uint32_t b1) {
    asm volatile(
        "mma.sync.aligned.m16n8k16.row.col.f32.bf16.bf16.f32 "
        "{%0,%1,%2,%3}, {%4,%5,%6,%7}, {%8,%9}, {%0,%1,%2,%3};"
        : "+f"(c[0]), "+f"(c[1]), "+f"(c[2]), "+f"(c[3])
        : "r"(a[0]), "r"(a[1]), "r"(a[2]), "r"(a[3]), "r"(b0), "r"(b1));
}
#define CP_ASYNC16(dst, src) \
    asm volatile("cp.async.cg.shared.global [%0], [%1], 16;" :: "r"(dst), "l"(src))
#define CP_COMMIT()  asm volatile("cp.async.commit_group;" ::: "memory")
#define CP_WAIT0()   asm volatile("cp.async.wait_group 0;" ::: "memory")
#define CP_WAIT1()   asm volatile("cp.async.wait_group 1;" ::: "memory")

// ---- 64-row kernel smem (vocab table GEMM) ----
#define STAGE_B 55296
#define MMA_SMEM 110592
// ---- 96-row kernels ----
#define S96_AP 13824          // 96*144
#define S96_BP 18432          // 128*144
#define S96_STAGE 64512       // 2*AP + 2*BP
#define GSM_HALF 12672        // 96*132 floats per k-split gate buffer
#define GEMM96_SMEM 129024    // 2 stages (>= 2*GSM_HALF*4 = 101376)
#define GOFF 129024           // gates prefetch region (96*128 f32 = 49152 B)
#define COFF 178176           // c state prefetch (96*32 f32 = 12288 B)
#define SEQ_SMEM 190464

// ---------------- emb -> bf16 split ---------------------------------------------
__global__ void clstm_splitemb(const float* __restrict__ emb,
                               __nv_bfloat16* __restrict__ Ehi,
                               __nv_bfloat16* __restrict__ Elo) {
    size_t base = (size_t)blockIdx.x * H_DIM + threadIdx.x * 4;
    float4 v = *(const float4*)(emb + base);
    float vv[4] = { v.x, v.y, v.z, v.w };
#pragma unroll
    for (int e = 0; e < 4; e++) {
        __nv_bfloat16 h = __float2bfloat16(vv[e]);
        Ehi[base + e] = h;
        Elo[base + e] = __float2bfloat16(vv[e] - __bfloat162float(h));
    }
}

// ---------------- W [k][n] -> [n'][k] bf16 split (optional gate permute) --------
__global__ void clstm_makeWsplit(const float* __restrict__ W,
                                 __nv_bfloat16* __restrict__ Phi,
                                 __nv_bfloat16* __restrict__ Plo, int permute) {
    __shared__ float tile[32][33];
    int n0 = blockIdx.x * 32, k0 = blockIdx.y * 32, l = blockIdx.z;
    const float* Wl = W + (size_t)l * H_DIM * G_COLS;
    int tx = threadIdx.x, ty = threadIdx.y;
#pragma unroll
    for (int it = 0; it < 4; it++)
        tile[ty + it * 8][tx] = Wl[(size_t)(k0 + ty + it * 8) * G_COLS + n0 + tx];
    __syncthreads();
    int s = n0 >> 9, cbb = (n0 >> 5) & 15;
    int np0 = permute ? (cbb * 128 + s * 32) : n0;
    __nv_bfloat16* ph = Phi + (size_t)l * G_COLS * H_DIM;
    __nv_bfloat16* pl = Plo + (size_t)l * G_COLS * H_DIM;
#pragma unroll
    for (int it = 0; it < 4; it++) {
        int nn = ty + it * 8;
        float v = tile[tx][nn];
        __nv_bfloat16 hi = __float2bfloat16(v);
        __nv_bfloat16 lo = __float2bfloat16(v - __bfloat162float(hi));
        ph[(size_t)(np0 + nn) * H_DIM + k0 + tx] = hi;
        pl[(size_t)(np0 + nn) * H_DIM + k0 + tx] = lo;
    }
}

// ---------------- HMMA 64-row GEMM (vocab table only) ---------------------------
__global__ void __launch_bounds__(256, 2)
clstm_gemm_mma(const __nv_bfloat16* __restrict__ Ahi, const __nv_bfloat16* __restrict__ Alo,
               const __nv_bfloat16* __restrict__ Bhi, const __nv_bfloat16* __restrict__ Blo,
               const float* __restrict__ bias, float* __restrict__ G) {
    extern __shared__ char smem[];
    const uint32_t sb = smem_to_u32(smem);
    const int tid = threadIdx.x, lane = tid & 31, w = tid >> 5;
    const int cb = blockIdx.x;
    const size_t bm = (size_t)blockIdx.y * 64;
    const __nv_bfloat16* asrc[2] = { Ahi + bm * H_DIM, Alo + bm * H_DIM };
    const __nv_bfloat16* bsrc[2] = { Bhi + (size_t)(cb * 128) * H_DIM,
                                     Blo + (size_t)(cb * 128) * H_DIM };
    const int lr = tid >> 3, lq = tid & 7;

    auto load_chunk = [&](int c, int s) {
        uint32_t stg = sb + (uint32_t)s * STAGE_B;
#pragma unroll
        for (int p = 0; p < 2; p++) {
            const __nv_bfloat16* gb = asrc[p] + c * 64;
            uint32_t sd = stg + p * 9216;
#pragma unroll
            for (int i = 0; i < 2; i++) {
                int r = lr + i * 32;
                CP_ASYNC16(sd + r * 144 + lq * 16,
                           (const void*)(gb + (size_t)r * H_DIM + lq * 8));
            }
        }
#pragma unroll
        for (int p = 0; p < 2; p++) {
            const __nv_bfloat16* gb = bsrc[p] + c * 64;
            uint32_t sd = stg + 18432 + p * 18432;
#pragma unroll
            for (int i = 0; i < 4; i++) {
                int r = lr + i * 32;
                CP_ASYNC16(sd + r * 144 + lq * 16,
                           (const void*)(gb + (size_t)r * H_DIM + lq * 8));
            }
        }
        CP_COMMIT();
    };

    const int m0 = (w >> 1) * 16, n0 = (w & 1) * 64;
    const int arow = (lane & 7) + ((lane & 8) ? 8 : 0);
    const int akq  = (lane & 16) ? 16 : 0;
    const int brow = (lane & 7) + ((lane & 16) ? 8 : 0);
    const int bkq  = (lane & 8) ? 16 : 0;

    float acc[8][4];
#pragma unroll
    for (int nt = 0; nt < 8; nt++)
#pragma unroll
        for (int e = 0; e < 4; e++) acc[nt][e] = 0.f;

    load_chunk(0, 0);
    for (int c = 0; c < 8; c++) {
        if (c < 7) { load_chunk(c + 1, (c + 1) & 1); CP_WAIT1(); }
        else       { CP_WAIT0(); }
        __syncthreads();
        uint32_t stg = sb + (uint32_t)(c & 1) * STAGE_B;
        uint32_t aH = stg, aL = stg + 9216, bH = stg + 18432, bL = stg + 36864;
#pragma unroll
        for (int ks = 0; ks < 4; ks++) {
            int kb = ks * 32;
            uint32_t ah[4], al[4], bh[4][4], bl[4][4];
            ldmx4(ah, aH + (m0 + arow) * 144 + kb + akq);
            ldmx4(al, aL + (m0 + arow) * 144 + kb + akq);
#pragma unroll
            for (int p = 0; p < 4; p++) {
                ldmx4(bh[p], bH + (n0 + p * 16 + brow) * 144 + kb + bkq);
                ldmx4(bl[p], bL + (n0 + p * 16 + brow) * 144 + kb + bkq);
            }
#pragma unroll
            for (int nt = 0; nt < 8; nt++)
                mma_bf16(acc[nt], ah, bh[nt >> 1][(nt & 1) * 2], bh[nt >> 1][(nt & 1) * 2 + 1]);
#pragma unroll
            for (int nt = 0; nt < 8; nt++)
                mma_bf16(acc[nt], ah, bl[nt >> 1][(nt & 1) * 2], bl[nt >> 1][(nt & 1) * 2 + 1]);
#pragma unroll
            for (int nt = 0; nt < 8; nt++)
                mma_bf16(acc[nt], al, bh[nt >> 1][(nt & 1) * 2], bh[nt >> 1][(nt & 1) * 2 + 1]);
        }
        __syncthreads();
    }

    float* gsm = (float*)smem;     // [64][132]
#pragma unroll
    for (int nt = 0; nt < 8; nt++) {
        int row = m0 + (lane >> 2);
        int col = n0 + nt * 8 + (lane & 3) * 2;
        gsm[row * 132 + col]     = acc[nt][0];
        gsm[row * 132 + col + 1] = acc[nt][1];
        gsm[(row + 8) * 132 + col]     = acc[nt][2];
        gsm[(row + 8) * 132 + col + 1] = acc[nt][3];
    }
    __syncthreads();

    int row = tid >> 2, c0 = (tid & 3) * 32;
    float* gp = G + (bm + row) * G_COLS + cb * 128;
#pragma unroll
    for (int q = 0; q < 8; q++) {
        int col = c0 + q * 4;
        float4 v = *(float4*)(gsm + row * 132 + col);
        float4 bv = *(const float4*)(bias + cb * 128 + col);
        v.x += bv.x; v.y += bv.y; v.z += bv.z; v.w += bv.w;
        *(float4*)(gp + col) = v;
    }
}

// =================== 96-row mainloop, 32x64 warp tiles + 2-way K-split ==========
// 12 warps: wk = w/6 selects k-half (ks = 2*wk..2*wk+1), wr = w%6 spatial tile
// (3m x 2n of 32x64). Per warp-ks: 12 ldmx4 -> 48 mma (0.25 ratio).
__device__ __forceinline__ void mma_tile96(
    uint32_t sb, int tid, int m0, int n0, int wk,
    int arow, int akq, int brow, int bkq,
    const __nv_bfloat16* __restrict__ aH0, const __nv_bfloat16* __restrict__ aL0,
    const __nv_bfloat16* __restrict__ bH0, const __nv_bfloat16* __restrict__ bL0,
    float acc[2][8][4])
{
    auto load96 = [&](int c, int s) {
        uint32_t stg = sb + (uint32_t)s * S96_STAGE;
#pragma unroll
        for (int i = 0; i < 10; i++) {
            int idx = tid + i * 384;
            if (idx < 3584) {
                uint32_t d; const __nv_bfloat16* g;
                if (idx < 1536) {
                    int p = idx >= 768, rem = idx - p * 768;
                    int r = rem >> 3, q = rem & 7;
                    d = stg + p * S96_AP + r * 144 + q * 16;
                    g = (p ? aL0 : aH0) + c * 64 + (size_t)r * H_DIM + q * 8;
                } else {
                    int j = idx - 1536;
                    int p = j >= 1024, rem = j - p * 1024;
                    int r = rem >> 3, q = rem & 7;
                    d = stg + 2 * S96_AP + p * S96_BP + r * 144 + q * 16;
                    g = (p ? bL0 : bH0) + c * 64 + (size_t)r * H_DIM + q * 8;
                }
                CP_ASYNC16(d, (const void*)g);
            }
        }
        CP_COMMIT();
    };
    load96(0, 0);
#pragma unroll 1
    for (int c = 0; c < 8; c++) {
        if (c < 7) { load96(c + 1, (c + 1) & 1); CP_WAIT1(); }
        else       { CP_WAIT0(); }
        __syncthreads();
        uint32_t stg = sb + (uint32_t)(c & 1) * S96_STAGE;
        uint32_t aH = stg, aL = stg + S96_AP;
        uint32_t bH = stg + 2 * S96_AP, bL = bH + S96_BP;
#pragma unroll
        for (int kk = 0; kk < 2; kk++) {
            int kb = (wk * 2 + kk) * 32;
            uint32_t ah[2][4], al[2][4], bh[4][4], bl[4][4];
#pragma unroll
            for (int mt = 0; mt < 2; mt++) {
                ldmx4(ah[mt], aH + (m0 + mt * 16 + arow) * 144 + kb + akq);
                ldmx4(al[mt], aL + (m0 + mt * 16 + arow) * 144 + kb + akq);
            }
#pragma unroll
            for (int p = 0; p < 4; p++) {
                ldmx4(bh[p], bH + (n0 + p * 16 + brow) * 144 + kb + bkq);
                ldmx4(bl[p], bL + (n0 + p * 16 + brow) * 144 + kb + bkq);
            }
#pragma unroll
            for (int mt = 0; mt < 2; mt++)
#pragma unroll
                for (int nt = 0; nt < 8; nt++)
                    mma_bf16(acc[mt][nt], ah[mt],
                             bh[nt >> 1][(nt & 1) * 2], bh[nt >> 1][(nt & 1) * 2 + 1]);
#pragma unroll
            for (int mt = 0; mt < 2; mt++)
#pragma unroll
                for (int nt = 0; nt < 8; nt++)
                    mma_bf16(acc[mt][nt], ah[mt],
                             bl[nt >> 1][(nt & 1) * 2], bl[nt >> 1][(nt & 1) * 2 + 1]);
#pragma unroll
            for (int mt = 0; mt < 2; mt++)
#pragma unroll
                for (int nt = 0; nt < 8; nt++)
                    mma_bf16(acc[mt][nt], al[mt],
                             bh[nt >> 1][(nt & 1) * 2], bh[nt >> 1][(nt & 1) * 2 + 1]);
        }
        __syncthreads();
    }
}

// stash: k-half wk writes its own gate buffer [96][132] at smem + wk*GSM_HALF*4
#define STASH96KS(ACC)                                                           \
    float* gks = (float*)smem + (size_t)wk * GSM_HALF;                           \
    _Pragma("unroll")                                                            \
    for (int mt = 0; mt < 2; mt++)                                               \
        _Pragma("unroll")                                                        \
        for (int nt = 0; nt < 8; nt++) {                                         \
            int row = m0 + mt * 16 + (lane >> 2);                                \
            int col = n0 + nt * 8 + (lane & 3) * 2;                              \
            gks[row * 132 + col]     = ACC[mt][nt][0];                           \
            gks[row * 132 + col + 1] = ACC[mt][nt][1];                           \
            gks[(row + 8) * 132 + col]     = ACC[mt][nt][2];                     \
            gks[(row + 8) * 132 + col + 1] = ACC[mt][nt][3];                     \
        }                                                                        \
    __syncthreads();

// ---------------- 96-row batched GEMM (gate precompute, layers 2-3) -------------
__global__ void __launch_bounds__(384, 1)
clstm_gemm96(const __nv_bfloat16* __restrict__ Ahi, const __nv_bfloat16* __restrict__ Alo,
             const __nv_bfloat16* __restrict__ Bhi, const __nv_bfloat16* __restrict__ Blo,
             const float* __restrict__ bias, float* __restrict__ G) {
    extern __shared__ char smem[];
    const uint32_t sb = smem_to_u32(smem);
    const int tid = threadIdx.x, lane = tid & 31, w = tid >> 5;
    const int cb = blockIdx.x;
    const size_t bm = (size_t)blockIdx.y * 96;
    const int wk = w / 6, wr = w % 6;
    const int m0 = (wr >> 1) * 32, n0 = (wr & 1) * 64;
    const int arow = (lane & 7) + ((lane & 8) ? 8 : 0);
    const int akq  = (lane & 16) ? 16 : 0;
    const int brow = (lane & 7) + ((lane & 16) ? 8 : 0);
    const int bkq  = (lane & 8) ? 16 : 0;

    float acc[2][8][4];
#pragma unroll
    for (int mt = 0; mt < 2; mt++)
#pragma unroll
        for (int nt = 0; nt < 8; nt++)
#pragma unroll
            for (int e = 0; e < 4; e++) acc[mt][nt][e] = 0.f;

    mma_tile96(sb, tid, m0, n0, wk, arow, akq, brow, bkq,
               Ahi + bm * H_DIM, Alo + bm * H_DIM,
               Bhi + (size_t)(cb * 128) * H_DIM, Blo + (size_t)(cb * 128) * H_DIM,
               acc);

    STASH96KS(acc)

    float* gsm = (float*)smem;
    int row = tid >> 2, c0 = (tid & 3) * 32;
    float* gp = G + (bm + row) * G_COLS + cb * 128;
#pragma unroll
    for (int q = 0; q < 8; q++) {
        int col = c0 + q * 4;
        float4 v  = *(float4*)(gsm + row * 132 + col);
        float4 v2 = *(float4*)(gsm + GSM_HALF + row * 132 + col);
        float4 bv = *(const float4*)(bias + cb * 128 + col);
        v.x += v2.x + bv.x; v.y += v2.y + bv.y;
        v.z += v2.z + bv.z; v.w += v2.w + bv.w;
        *(float4*)(gp + col) = v;
    }
}

// ---------------- cheap generation grid barrier (128 CTAs, co-resident) ---------
__device__ __forceinline__ void grid_bar128() {
    __syncthreads();
    if (threadIdx.x == 0) {
        unsigned g;
        asm volatile("ld.acquire.gpu.u32 %0, [%1];" : "=r"(g) : "l"(&d_barGen));
        unsigned a;
        asm volatile("atom.acq_rel.gpu.add.u32 %0, [%1], 1;"
                     : "=r"(a) : "l"(&d_barCnt) : "memory");
        if (a == 127u) {
            asm volatile("st.relaxed.gpu.u32 [%0], 0;" :: "l"(&d_barCnt) : "memory");
            asm volatile("red.release.gpu.add.u32 [%0], 1;" :: "l"(&d_barGen) : "memory");
        } else {
            unsigned cur;
            do {
                asm volatile("nanosleep.u32 128;");
                asm volatile("ld.acquire.gpu.u32 %0, [%1];" : "=r"(cur) : "l"(&d_barGen));
            } while (cur == g);
        }
    }
    __syncthreads();
}

// ---------------- persistent recurrent sequence kernel --------------------------
// grid (16, 8) = 128 CTAs. Loops t = 0..255 with grid barrier between steps.
// Gates + c state for step t prefetched into smem before the MMA mainloop.
__global__ void __launch_bounds__(384, 1)
clstm_seq96(const float* __restrict__ Gbase,
            const int* __restrict__ toks, const float* __restrict__ tab,
            const __nv_bfloat16* __restrict__ WhH, const __nv_bfloat16* __restrict__ WhL,
            float* __restrict__ cst,
            __nv_bfloat16* __restrict__ Hh, __nv_bfloat16* __restrict__ Hl) {
    extern __shared__ char smem[];
    const uint32_t sb = smem_to_u32(smem);
    const int tid = threadIdx.x, lane = tid & 31, w = tid >> 5;
    const int cb = blockIdx.x;
    const size_t bm = (size_t)blockIdx.y * 96;
    const int wk = w / 6, wr = w % 6;
    const int m0 = (wr >> 1) * 32, n0 = (wr & 1) * 64;
    const int arow = (lane & 7) + ((lane & 8) ? 8 : 0);
    const int akq  = (lane & 16) ? 16 : 0;
    const int brow = (lane & 7) + ((lane & 16) ? 8 : 0);
    const int bkq  = (lane & 8) ? 16 : 0;
    const __nv_bfloat16* bH0 = WhH + (size_t)(cb * 128) * H_DIM;
    const __nv_bfloat16* bL0 = WhL + (size_t)(cb * 128) * H_DIM;
    const int erow = tid >> 2, hb = (tid & 3) * 8;
    const size_t grow = bm + erow;
    const int hc0 = cb * 32 + hb;
    float* cp = cst + grow * H_DIM + hc0;
    float* gsm = (float*)smem;
    const float* gsm2 = (const float*)(smem + GOFF);
    const float* csm  = (const float*)(smem + COFF);

#pragma unroll 1
    for (int t = 0; t < T_LEN; t++) {
        // ---- prefetch gates (+ c) for this step into smem ----
        {
#pragma unroll
            for (int i = 0; i < 8; i++) {
                int f = tid + i * 384;          // 0..3071 float4s
                int r = f >> 5, rem = f & 31;
                int g = rem >> 3, jj = (rem & 7) << 2;
                const float* rowp;
                int rr = (int)bm + r;
                if (toks) {
                    int tk = __ldg(toks + ((rr >> 8) << 16) + ((rr & 255) << 8) + t);
                    rowp = tab + (size_t)tk * G_COLS;
                } else {
                    rowp = Gbase + (size_t)t * R_ROWS * G_COLS + (size_t)rr * G_COLS;
                }
                CP_ASYNC16(sb + GOFF + (uint32_t)((r * 128 + g * 32 + jj) * 4),
                           (const void*)(rowp + g * H_DIM + cb * 32 + jj));
            }
            if (t > 0) {
#pragma unroll
                for (int i = 0; i < 2; i++) {
                    int f = tid + i * 384;      // 0..767 float4s
                    int r = f >> 3, jj = (f & 7) << 2;
                    CP_ASYNC16(sb + COFF + (uint32_t)((r * 32 + jj) * 4),
                               (const void*)(cst + (bm + r) * H_DIM + cb * 32 + jj));
                }
            }
            CP_COMMIT();
        }

        float acc[2][8][4];
#pragma unroll
        for (int mt = 0; mt < 2; mt++)
#pragma unroll
            for (int nt = 0; nt < 8; nt++)
#pragma unroll
                for (int e = 0; e < 4; e++) acc[mt][nt][e] = 0.f;

        if (t > 0) {
            const __nv_bfloat16* aH0 = Hh + (size_t)(t - 1) * RH + bm * H_DIM;
            const __nv_bfloat16* aL0 = Hl + (size_t)(t - 1) * RH + bm * H_DIM;
            mma_tile96(sb, tid, m0, n0, wk, arow, akq, brow, bkq,
                       aH0, aL0, bH0, bL0, acc);
        } else {
            CP_WAIT0();
            __syncthreads();
        }

        // stash accumulators (k-split halves; stage smem reuse)
        STASH96KS(acc)

        // fused LSTM epilogue (gates + c from smem; sum the two k-halves)
        __nv_bfloat16* hhp = Hh + (size_t)t * RH + grow * H_DIM + hc0;
        __nv_bfloat16* hlp = Hl + (size_t)t * RH + grow * H_DIM + hc0;
#pragma unroll
        for (int q = 0; q < 2; q++) {
            float4 gi = *(const float4*)(gsm2 + erow * 128 +       hb + q * 4);
            float4 gf = *(const float4*)(gsm2 + erow * 128 +  32 + hb + q * 4);
            float4 gg = *(const float4*)(gsm2 + erow * 128 +  64 + hb + q * 4);
            float4 go = *(const float4*)(gsm2 + erow * 128 +  96 + hb + q * 4);
            float4 co = make_float4(0.f, 0.f, 0.f, 0.f);
            if (t > 0) co = *(const float4*)(csm + erow * 32 + hb + q * 4);
            float4 cv;
            __nv_bfloat16 bh4[4], bl4[4];
#pragma unroll
            for (int e = 0; e < 4; e++) {
                int li = erow * 132 + hb + q * 4 + e;
                float xi = gsm[li]            + gsm[GSM_HALF + li]            + ((const float*)&gi)[e];
                float xf = gsm[li + 32]       + gsm[GSM_HALF + li + 32]       + ((const float*)&gf)[e];
                float xg = gsm[li + 64]       + gsm[GSM_HALF + li + 64]       + ((const float*)&gg)[e];
                float xo = gsm[li + 96]       + gsm[GSM_HALF + li + 96]       + ((const float*)&go)[e];
                float I = 1.f / (1.f + __expf(-xi));
                float F = 1.f / (1.f + __expf(-xf));
                float Gv = tanhf(xg);
                float O = 1.f / (1.f + __expf(-xo));
                float cn = F * ((const float*)&co)[e] + I * Gv;
                float hn = O * tanhf(cn);
                ((float*)&cv)[e] = cn;
                bh4[e] = __float2bfloat16(hn);
                bl4[e] = __float2bfloat16(hn - __bfloat162float(bh4[e]));
            }
            *(float4*)(cp + q * 4) = cv;
            __nv_bfloat162 p0; p0.x = bh4[0]; p0.y = bh4[1];
            __nv_bfloat162 p1; p1.x = bh4[2]; p1.y = bh4[3];
            __nv_bfloat162 q0; q0.x = bl4[0]; q0.y = bl4[1];
            __nv_bfloat162 q1; q1.x = bl4[2]; q1.y = bl4[3];
            *(__nv_bfloat162*)(hhp + q * 4)     = p0;
            *(__nv_bfloat162*)(hhp + q * 4 + 2) = p1;
            *(__nv_bfloat162*)(hlp + q * 4)     = q0;
            *(__nv_bfloat162*)(hlp + q * 4 + 2) = q1;
        }
        grid_bar128();
    }
}

// ---------------- head kernels -------------------------------------------------
__global__ void clstm_gather_r(const __nv_bfloat16* __restrict__ Hhi,
                               const __nv_bfloat16* __restrict__ Hlo,
                               float* __restrict__ r) {
    int b = blockIdx.x, i = blockIdx.y, h = threadIdx.x;
    size_t idx = ((size_t)(T_LEN - 1) * R_ROWS + i * B_SZ + b) * H_DIM + h;
    r[(size_t)b * 1536 + i * H_DIM + h] =
        __bfloat162float(Hhi[idx]) + __bfloat162float(Hlo[idx]);
}

__global__ void clstm_bn(float* __restrict__ x, const float* __restrict__ gamma,
                         const float* __restrict__ beta, int N) {
    __shared__ float s1[256], s2[256];
    int col = blockIdx.x;
    float v = x[(size_t)threadIdx.x * N + col];
    s1[threadIdx.x] = v; s2[threadIdx.x] = v * v;
    __syncthreads();
    for (int s = 128; s > 0; s >>= 1) {
        if (threadIdx.x < s) {
            s1[threadIdx.x] += s1[threadIdx.x + s];
            s2[threadIdx.x] += s2[threadIdx.x + s];
        }
        __syncthreads();
    }
    float m = s1[0] * (1.f / 256.f);
    float var = s2[0] * (1.f / 256.f) - m * m;
    float inv = rsqrtf(var + 1e-3f);
    x[(size_t)threadIdx.x * N + col] = gamma[col] * (v - m) * inv + beta[col];
}

__global__ void clstm_gemm_head(const float* __restrict__ A, const float* __restrict__ W,
                                const float* __restrict__ bias, float* __restrict__ C,
                                int K, int N, int act) {
    int n = blockIdx.x * 128 + threadIdx.x;
    int m0 = blockIdx.y * 16;
    if (n >= N) return;
    float s[16];
#pragma unroll
    for (int mm = 0; mm < 16; mm++) s[mm] = bias[n];
    for (int k = 0; k < K; k++) {
        float w = W[(size_t)k * N + n];
#pragma unroll
        for (int mm = 0; mm < 16; mm++)
            s[mm] += A[(size_t)(m0 + mm) * K + k] * w;
    }
    const float alpha = 1.6732632423543772f, scale = 1.0507009873554805f;
#pragma unroll
    for (int mm = 0; mm < 16; mm++) {
        float v = s[mm];
        if (act) v = scale * (v > 0.f ? v : alpha * expm1f(v));
        C[(size_t)(m0 + mm) * N + n] = v;
    }
}

// ---------------- launch --------------------------------------------------------
extern "C" void kernel_launch(void* const* d_in, const int* in_sizes, int n_in,
                              void* d_out, int out_size) {
    const int* t1 = (const int*)d_in[0];
    const int* t2 = (const int*)d_in[1];
    const int* t3 = (const int*)d_in[2];
    const float* emb = (const float*)d_in[3];
    const float* Wx = (const float*)d_in[4];
    const float* Wh = (const float*)d_in[5];
    const float* bb = (const float*)d_in[6];
    const float* g1 = (const float*)d_in[7];
    const float* be1 = (const float*)d_in[8];
    const float* W1 = (const float*)d_in[9];
    const float* bd1 = (const float*)d_in[10];
    const float* g2 = (const float*)d_in[11];
    const float* be2 = (const float*)d_in[12];
    const float* W2 = (const float*)d_in[13];
    const float* bd2 = (const float*)d_in[14];
    const float* g3 = (const float*)d_in[15];
    const float* be3 = (const float*)d_in[16];
    const float* W3 = (const float*)d_in[17];
    const float* bd3 = (const float*)d_in[18];
    float* out = (float*)d_out;

    float *G, *TAB, *C, *R, *H1, *H2;
    int* TOK;
    __nv_bfloat16 *Eh, *El, *WhPh, *WhPl, *WxTh, *WxTl, *sAh, *sAl, *sBh, *sBl;
    cudaGetSymbolAddress((void**)&G, d_Gbuf);
    cudaGetSymbolAddress((void**)&TAB, d_tab);
    cudaGetSymbolAddress((void**)&C, d_cst);
    cudaGetSymbolAddress((void**)&R, d_rbuf);
    cudaGetSymbolAddress((void**)&H1, d_h1buf);
    cudaGetSymbolAddress((void**)&H2, d_h2buf);
    cudaGetSymbolAddress((void**)&TOK, d_toks);
    cudaGetSymbolAddress((void**)&Eh, d_Ehi);
    cudaGetSymbolAddress((void**)&El, d_Elo);
    cudaGetSymbolAddress((void**)&WhPh, d_WhPhi);
    cudaGetSymbolAddress((void**)&WhPl, d_WhPlo);
    cudaGetSymbolAddress((void**)&WxTh, d_WxThi);
    cudaGetSymbolAddress((void**)&WxTl, d_WxTlo);
    cudaGetSymbolAddress((void**)&sAh, d_sAhi);
    cudaGetSymbolAddress((void**)&sAl, d_sAlo);
    cudaGetSymbolAddress((void**)&sBh, d_sBhi);
    cudaGetSymbolAddress((void**)&sBl, d_sBlo);

    cudaFuncSetAttribute(clstm_gemm_mma, cudaFuncAttributeMaxDynamicSharedMemorySize,
                         MMA_SMEM);
    cudaFuncSetAttribute(clstm_gemm96, cudaFuncAttributeMaxDynamicSharedMemorySize,
                         GEMM96_SMEM);
    cudaFuncSetAttribute(clstm_seq96, cudaFuncAttributeMaxDynamicSharedMemorySize,
                         SEQ_SMEM);

    // preprocessing
    cudaMemcpyAsync(TOK,          t1, 65536 * sizeof(int), cudaMemcpyDeviceToDevice, 0);
    cudaMemcpyAsync(TOK + 65536,  t2, 65536 * sizeof(int), cudaMemcpyDeviceToDevice, 0);
    cudaMemcpyAsync(TOK + 131072, t3, 65536 * sizeof(int), cudaMemcpyDeviceToDevice, 0);
    clstm_splitemb<<<V_SZ, 128>>>(emb, Eh, El);
    clstm_makeWsplit<<<dim3(64, 16, 3), dim3(32, 8)>>>(Wh, WhPh, WhPl, 1);
    clstm_makeWsplit<<<dim3(64, 16, 3), dim3(32, 8)>>>(Wx, WxTh, WxTl, 0);
    // vocab gate table: tab = emb @ Wx0 + b0   [32000, 2048]
    clstm_gemm_mma<<<dim3(16, V_SZ / 64), 256, MMA_SMEM>>>(
        Eh, El, WxTh, WxTl, bb, TAB);

    // layer 1: persistent sequence, gates from tab[token]; output h seq -> sB
    clstm_seq96<<<dim3(16, 8), 384, SEQ_SMEM>>>(
        (const float*)0, TOK, TAB, WhPh, WhPl, C, sBh, sBl);

    // layers 2,3
    __nv_bfloat16 *inH = sBh, *inL = sBl, *outH = sAh, *outL = sAl;
    for (int l = 1; l < 3; l++) {
        size_t woff = (size_t)l * G_COLS * H_DIM;
        clstm_gemm96<<<dim3(16, M_ALL / 96), 384, GEMM96_SMEM>>>(
            inH, inL, WxTh + woff, WxTl + woff, bb + (size_t)l * G_COLS, G);
        clstm_seq96<<<dim3(16, 8), 384, SEQ_SMEM>>>(
            G, (const int*)0, (const float*)0,
            WhPh + woff, WhPl + woff, C, outH, outL);
        __nv_bfloat16* tm;
        tm = inH; inH = outH; outH = tm;
        tm = inL; inL = outL; outL = tm;
    }

    // head
    clstm_gather_r<<<dim3(B_SZ, 3), H_DIM>>>(inH, inL, R);
    clstm_bn<<<1536, 256>>>(R, g1, be1, 1536);
    clstm_gemm_head<<<dim3(8, 16), 128>>>(R, W1, bd1, H1, 1536, 1024, 1);
    clstm_bn<<<1024, 256>>>(H1, g2, be2, 1024);
    clstm_gemm_head<<<dim3(1, 16), 128>>>(H1, W2, bd2, H2, 1024, H5, 1);
    clstm_bn<<<H5, 256>>>(H2, g3, be3, H5);
    clstm_gemm_head<<<dim3(1, 16), 128>>>(H2, W3, bd3, out, H5, 4, 0);
}

// round 12
// speedup vs baseline: 1.0271x; 1.0271x over previous
#include <cuda_runtime.h>
#include <cuda_bf16.h>
#include <math.h>
#include <stdint.h>
#include <stddef.h>

#define T_LEN 256
#define B_SZ  256
#define H_DIM 512
#define R_ROWS 768
#define G_COLS 2048
#define M_ALL  196608
#define V_SZ   32000
#define H5 102
#define RH 393216            // R_ROWS * H_DIM

// ---------------- static device scratch --------------------------------------
__device__ float d_Gbuf[402653184];   // [T][768][2048] h@Wx + b (layers 2,3)
__device__ float d_tab[65536000];     // [32000][2048] emb@Wx0 + b0
__device__ float d_cst[393216];
__device__ float d_rbuf[393216];
__device__ float d_h1buf[262144];
__device__ float d_h2buf[26112];
__device__ int   d_toks[196608];      // [3][256][256]
__device__ unsigned d_barGenL[256];   // 8 groups, stride 32 (128B apart)
__device__ unsigned d_barCntL[256];
__device__ __nv_bfloat16 d_Ehi[16384000];           // emb split [32000][512]
__device__ __nv_bfloat16 d_Elo[16384000];
__device__ __nv_bfloat16 d_WhPhi[3 * 2048 * 512];   // Wh permuted [n'][k] hi
__device__ __nv_bfloat16 d_WhPlo[3 * 2048 * 512];
__device__ __nv_bfloat16 d_WxThi[3 * 2048 * 512];   // Wx transposed [n][k] hi
__device__ __nv_bfloat16 d_WxTlo[3 * 2048 * 512];
__device__ __nv_bfloat16 d_sAhi[100663296];         // h seq splits (ping)
__device__ __nv_bfloat16 d_sAlo[100663296];
__device__ __nv_bfloat16 d_sBhi[100663296];         // (pong)
__device__ __nv_bfloat16 d_sBlo[100663296];

// ---------------- helpers ------------------------------------------------------
__device__ __forceinline__ uint32_t smem_to_u32(const void* p) {
    uint32_t a;
    asm("{ .reg .u64 t; cvta.to.shared.u64 t, %1; cvt.u32.u64 %0, t; }"
        : "=r"(a) : "l"(p));
    return a;
}
__device__ __forceinline__ void ldmx4(uint32_t* r, uint32_t addr) {
    asm volatile("ldmatrix.sync.aligned.m8n8.x4.shared.b16 {%0,%1,%2,%3}, [%4];"
                 : "=r"(r[0]), "=r"(r[1]), "=r"(r[2]), "=r"(r[3]) : "r"(addr));
}
__device__ __forceinline__ void mma_bf16(float* c, const uint32_t* a,
                                         uint32_t b0, uint32_t b1) {
    asm volatile(
        "mma.sync.aligned.m16n8k16.row.col.f32.bf16.bf16.f32 "
        "{%0,%1,%2,%3}, {%4,%5,%6,%7}, {%8,%9}, {%0,%1,%2,%3};"
        : "+f"(c[0]), "+f"(c[1]), "+f"(c[2]), "+f"(c[3])
        : "r"(a[0]), "r"(a[1]), "r"(a[2]), "r"(a[3]), "r"(b0), "r"(b1));
}
#define CP_ASYNC16(dst, src) \
    asm volatile("cp.async.cg.shared.global [%0], [%1], 16;" :: "r"(dst), "l"(src))
#define CP_COMMIT()  asm volatile("cp.async.commit_group;" ::: "memory")
#define CP_WAIT0()   asm volatile("cp.async.wait_group 0;" ::: "memory")
#define CP_WAIT1()   asm volatile("cp.async.wait_group 1;" ::: "memory")

// ---- 64-row kernel smem (vocab table GEMM) ----
#define STAGE_B 55296
#define MMA_SMEM 110592
// ---- 96-row kernels ----
#define S96_AP 13824          // 96*144
#define S96_BP 18432          // 128*144
#define S96_STAGE 64512       // 2*AP + 2*BP
#define GSM_HALF 12672        // 96*132 floats per k-split gate buffer
#define GEMM96_SMEM 129024    // 2 stages (>= 2*GSM_HALF*4 = 101376)
#define GOFF 129024           // gates prefetch region (96*128 f32 = 49152 B)
#define COFF 178176           // c state prefetch (96*32 f32 = 12288 B)
#define SEQ_SMEM 190464

// ---------------- emb -> bf16 split ---------------------------------------------
__global__ void clstm_splitemb(const float* __restrict__ emb,
                               __nv_bfloat16* __restrict__ Ehi,
                               __nv_bfloat16* __restrict__ Elo) {
    size_t base = (size_t)blockIdx.x * H_DIM + threadIdx.x * 4;
    float4 v = *(const float4*)(emb + base);
    float vv[4] = { v.x, v.y, v.z, v.w };
#pragma unroll
    for (int e = 0; e < 4; e++) {
        __nv_bfloat16 h = __float2bfloat16(vv[e]);
        Ehi[base + e] = h;
        Elo[base + e] = __float2bfloat16(vv[e] - __bfloat162float(h));
    }
}

// ---------------- W [k][n] -> [n'][k] bf16 split (optional gate permute) --------
__global__ void clstm_makeWsplit(const float* __restrict__ W,
                                 __nv_bfloat16* __restrict__ Phi,
                                 __nv_bfloat16* __restrict__ Plo, int permute) {
    __shared__ float tile[32][33];
    int n0 = blockIdx.x * 32, k0 = blockIdx.y * 32, l = blockIdx.z;
    const float* Wl = W + (size_t)l * H_DIM * G_COLS;
    int tx = threadIdx.x, ty = threadIdx.y;
#pragma unroll
    for (int it = 0; it < 4; it++)
        tile[ty + it * 8][tx] = Wl[(size_t)(k0 + ty + it * 8) * G_COLS + n0 + tx];
    __syncthreads();
    int s = n0 >> 9, cbb = (n0 >> 5) & 15;
    int np0 = permute ? (cbb * 128 + s * 32) : n0;
    __nv_bfloat16* ph = Phi + (size_t)l * G_COLS * H_DIM;
    __nv_bfloat16* pl = Plo + (size_t)l * G_COLS * H_DIM;
#pragma unroll
    for (int it = 0; it < 4; it++) {
        int nn = ty + it * 8;
        float v = tile[tx][nn];
        __nv_bfloat16 hi = __float2bfloat16(v);
        __nv_bfloat16 lo = __float2bfloat16(v - __bfloat162float(hi));
        ph[(size_t)(np0 + nn) * H_DIM + k0 + tx] = hi;
        pl[(size_t)(np0 + nn) * H_DIM + k0 + tx] = lo;
    }
}

// ---------------- HMMA 64-row GEMM (vocab table only) ---------------------------
__global__ void __launch_bounds__(256, 2)
clstm_gemm_mma(const __nv_bfloat16* __restrict__ Ahi, const __nv_bfloat16* __restrict__ Alo,
               const __nv_bfloat16* __restrict__ Bhi, const __nv_bfloat16* __restrict__ Blo,
               const float* __restrict__ bias, float* __restrict__ G) {
    extern __shared__ char smem[];
    const uint32_t sb = smem_to_u32(smem);
    const int tid = threadIdx.x, lane = tid & 31, w = tid >> 5;
    const int cb = blockIdx.x;
    const size_t bm = (size_t)blockIdx.y * 64;
    const __nv_bfloat16* asrc[2] = { Ahi + bm * H_DIM, Alo + bm * H_DIM };
    const __nv_bfloat16* bsrc[2] = { Bhi + (size_t)(cb * 128) * H_DIM,
                                     Blo + (size_t)(cb * 128) * H_DIM };
    const int lr = tid >> 3, lq = tid & 7;

    auto load_chunk = [&](int c, int s) {
        uint32_t stg = sb + (uint32_t)s * STAGE_B;
#pragma unroll
        for (int p = 0; p < 2; p++) {
            const __nv_bfloat16* gb = asrc[p] + c * 64;
            uint32_t sd = stg + p * 9216;
#pragma unroll
            for (int i = 0; i < 2; i++) {
                int r = lr + i * 32;
                CP_ASYNC16(sd + r * 144 + lq * 16,
                           (const void*)(gb + (size_t)r * H_DIM + lq * 8));
            }
        }
#pragma unroll
        for (int p = 0; p < 2; p++) {
            const __nv_bfloat16* gb = bsrc[p] + c * 64;
            uint32_t sd = stg + 18432 + p * 18432;
#pragma unroll
            for (int i = 0; i < 4; i++) {
                int r = lr + i * 32;
                CP_ASYNC16(sd + r * 144 + lq * 16,
                           (const void*)(gb + (size_t)r * H_DIM + lq * 8));
            }
        }
        CP_COMMIT();
    };

    const int m0 = (w >> 1) * 16, n0 = (w & 1) * 64;
    const int arow = (lane & 7) + ((lane & 8) ? 8 : 0);
    const int akq  = (lane & 16) ? 16 : 0;
    const int brow = (lane & 7) + ((lane & 16) ? 8 : 0);
    const int bkq  = (lane & 8) ? 16 : 0;

    float acc[8][4];
#pragma unroll
    for (int nt = 0; nt < 8; nt++)
#pragma unroll
        for (int e = 0; e < 4; e++) acc[nt][e] = 0.f;

    load_chunk(0, 0);
    for (int c = 0; c < 8; c++) {
        if (c < 7) { load_chunk(c + 1, (c + 1) & 1); CP_WAIT1(); }
        else       { CP_WAIT0(); }
        __syncthreads();
        uint32_t stg = sb + (uint32_t)(c & 1) * STAGE_B;
        uint32_t aH = stg, aL = stg + 9216, bH = stg + 18432, bL = stg + 36864;
#pragma unroll
        for (int ks = 0; ks < 4; ks++) {
            int kb = ks * 32;
            uint32_t ah[4], al[4], bh[4][4], bl[4][4];
            ldmx4(ah, aH + (m0 + arow) * 144 + kb + akq);
            ldmx4(al, aL + (m0 + arow) * 144 + kb + akq);
#pragma unroll
            for (int p = 0; p < 4; p++) {
                ldmx4(bh[p], bH + (n0 + p * 16 + brow) * 144 + kb + bkq);
                ldmx4(bl[p], bL + (n0 + p * 16 + brow) * 144 + kb + bkq);
            }
#pragma unroll
            for (int nt = 0; nt < 8; nt++)
                mma_bf16(acc[nt], ah, bh[nt >> 1][(nt & 1) * 2], bh[nt >> 1][(nt & 1) * 2 + 1]);
#pragma unroll
            for (int nt = 0; nt < 8; nt++)
                mma_bf16(acc[nt], ah, bl[nt >> 1][(nt & 1) * 2], bl[nt >> 1][(nt & 1) * 2 + 1]);
#pragma unroll
            for (int nt = 0; nt < 8; nt++)
                mma_bf16(acc[nt], al, bh[nt >> 1][(nt & 1) * 2], bh[nt >> 1][(nt & 1) * 2 + 1]);
        }
        __syncthreads();
    }

    float* gsm = (float*)smem;     // [64][132]
#pragma unroll
    for (int nt = 0; nt < 8; nt++) {
        int row = m0 + (lane >> 2);
        int col = n0 + nt * 8 + (lane & 3) * 2;
        gsm[row * 132 + col]     = acc[nt][0];
        gsm[row * 132 + col + 1] = acc[nt][1];
        gsm[(row + 8) * 132 + col]     = acc[nt][2];
        gsm[(row + 8) * 132 + col + 1] = acc[nt][3];
    }
    __syncthreads();

    int row = tid >> 2, c0 = (tid & 3) * 32;
    float* gp = G + (bm + row) * G_COLS + cb * 128;
#pragma unroll
    for (int q = 0; q < 8; q++) {
        int col = c0 + q * 4;
        float4 v = *(float4*)(gsm + row * 132 + col);
        float4 bv = *(const float4*)(bias + cb * 128 + col);
        v.x += bv.x; v.y += bv.y; v.z += bv.z; v.w += bv.w;
        *(float4*)(gp + col) = v;
    }
}

// ---------------- shared 96-row chunk loader -------------------------------------
__device__ __forceinline__ void load96_chunk(
    uint32_t sb, int tid, int c, int s,
    const __nv_bfloat16* __restrict__ aH0, const __nv_bfloat16* __restrict__ aL0,
    const __nv_bfloat16* __restrict__ bH0, const __nv_bfloat16* __restrict__ bL0)
{
    uint32_t stg = sb + (uint32_t)s * S96_STAGE;
#pragma unroll
    for (int i = 0; i < 10; i++) {
        int idx = tid + i * 384;
        if (idx < 3584) {
            uint32_t d; const __nv_bfloat16* g;
            if (idx < 1536) {
                int p = idx >= 768, rem = idx - p * 768;
                int r = rem >> 3, q = rem & 7;
                d = stg + p * S96_AP + r * 144 + q * 16;
                g = (p ? aL0 : aH0) + c * 64 + (size_t)r * H_DIM + q * 8;
            } else {
                int j = idx - 1536;
                int p = j >= 1024, rem = j - p * 1024;
                int r = rem >> 3, q = rem & 7;
                d = stg + 2 * S96_AP + p * S96_BP + r * 144 + q * 16;
                g = (p ? bL0 : bH0) + c * 64 + (size_t)r * H_DIM + q * 8;
            }
            CP_ASYNC16(d, (const void*)g);
        }
    }
    CP_COMMIT();
}

// =================== 96-row mainloop, 32x32 warp tiles (seq kernel) =============
__device__ __forceinline__ void mma_tile96(
    uint32_t sb, int tid, int m0, int n0,
    int arow, int akq, int brow, int bkq,
    const __nv_bfloat16* __restrict__ aH0, const __nv_bfloat16* __restrict__ aL0,
    const __nv_bfloat16* __restrict__ bH0, const __nv_bfloat16* __restrict__ bL0,
    float acc[2][4][4])
{
    load96_chunk(sb, tid, 0, 0, aH0, aL0, bH0, bL0);
#pragma unroll 1
    for (int c = 0; c < 8; c++) {
        if (c < 7) { load96_chunk(sb, tid, c + 1, (c + 1) & 1, aH0, aL0, bH0, bL0); CP_WAIT1(); }
        else       { CP_WAIT0(); }
        __syncthreads();
        uint32_t stg = sb + (uint32_t)(c & 1) * S96_STAGE;
        uint32_t aH = stg, aL = stg + S96_AP;
        uint32_t bH = stg + 2 * S96_AP, bL = bH + S96_BP;
#pragma unroll
        for (int ks = 0; ks < 4; ks++) {
            int kb = ks * 32;
            uint32_t ah[2][4], al[2][4], bh[2][4], bl[2][4];
#pragma unroll
            for (int mt = 0; mt < 2; mt++) {
                ldmx4(ah[mt], aH + (m0 + mt * 16 + arow) * 144 + kb + akq);
                ldmx4(al[mt], aL + (m0 + mt * 16 + arow) * 144 + kb + akq);
            }
#pragma unroll
            for (int p = 0; p < 2; p++) {
                ldmx4(bh[p], bH + (n0 + p * 16 + brow) * 144 + kb + bkq);
                ldmx4(bl[p], bL + (n0 + p * 16 + brow) * 144 + kb + bkq);
            }
#pragma unroll
            for (int mt = 0; mt < 2; mt++)
#pragma unroll
                for (int nt = 0; nt < 4; nt++)
                    mma_bf16(acc[mt][nt], ah[mt],
                             bh[nt >> 1][(nt & 1) * 2], bh[nt >> 1][(nt & 1) * 2 + 1]);
#pragma unroll
            for (int mt = 0; mt < 2; mt++)
#pragma unroll
                for (int nt = 0; nt < 4; nt++)
                    mma_bf16(acc[mt][nt], ah[mt],
                             bl[nt >> 1][(nt & 1) * 2], bl[nt >> 1][(nt & 1) * 2 + 1]);
#pragma unroll
            for (int mt = 0; mt < 2; mt++)
#pragma unroll
                for (int nt = 0; nt < 4; nt++)
                    mma_bf16(acc[mt][nt], al[mt],
                             bh[nt >> 1][(nt & 1) * 2], bh[nt >> 1][(nt & 1) * 2 + 1]);
        }
        __syncthreads();
    }
}

// ---------------- 96-row batched GEMM: 32x64 warp tiles + 2-way K-split ----------
// 12 warps: wk = w/6 (k-half), wr = w%6 spatial (3m x 2n of 32x64).
// Inner loop loads B fragments in 32-col halves to bound live registers.
__global__ void __launch_bounds__(384, 1)
clstm_gemm96(const __nv_bfloat16* __restrict__ Ahi, const __nv_bfloat16* __restrict__ Alo,
             const __nv_bfloat16* __restrict__ Bhi, const __nv_bfloat16* __restrict__ Blo,
             const float* __restrict__ bias, float* __restrict__ G) {
    extern __shared__ char smem[];
    const uint32_t sb = smem_to_u32(smem);
    const int tid = threadIdx.x, lane = tid & 31, w = tid >> 5;
    const int cb = blockIdx.x;
    const size_t bm = (size_t)blockIdx.y * 96;
    const int wk = w / 6, wr = w % 6;
    const int m0 = (wr >> 1) * 32, n0 = (wr & 1) * 64;
    const int arow = (lane & 7) + ((lane & 8) ? 8 : 0);
    const int akq  = (lane & 16) ? 16 : 0;
    const int brow = (lane & 7) + ((lane & 16) ? 8 : 0);
    const int bkq  = (lane & 8) ? 16 : 0;
    const __nv_bfloat16* aH0 = Ahi + bm * H_DIM;
    const __nv_bfloat16* aL0 = Alo + bm * H_DIM;
    const __nv_bfloat16* bH0 = Bhi + (size_t)(cb * 128) * H_DIM;
    const __nv_bfloat16* bL0 = Blo + (size_t)(cb * 128) * H_DIM;

    float acc[2][8][4];
#pragma unroll
    for (int mt = 0; mt < 2; mt++)
#pragma unroll
        for (int nt = 0; nt < 8; nt++)
#pragma unroll
            for (int e = 0; e < 4; e++) acc[mt][nt][e] = 0.f;

    load96_chunk(sb, tid, 0, 0, aH0, aL0, bH0, bL0);
#pragma unroll 1
    for (int c = 0; c < 8; c++) {
        if (c < 7) { load96_chunk(sb, tid, c + 1, (c + 1) & 1, aH0, aL0, bH0, bL0); CP_WAIT1(); }
        else       { CP_WAIT0(); }
        __syncthreads();
        uint32_t stg = sb + (uint32_t)(c & 1) * S96_STAGE;
        uint32_t aH = stg, aL = stg + S96_AP;
        uint32_t bH = stg + 2 * S96_AP, bL = bH + S96_BP;
#pragma unroll
        for (int kk = 0; kk < 2; kk++) {
            int kb = (wk * 2 + kk) * 32;
            uint32_t ah[2][4], al[2][4];
#pragma unroll
            for (int mt = 0; mt < 2; mt++) {
                ldmx4(ah[mt], aH + (m0 + mt * 16 + arow) * 144 + kb + akq);
                ldmx4(al[mt], aL + (m0 + mt * 16 + arow) * 144 + kb + akq);
            }
#pragma unroll
            for (int nh = 0; nh < 2; nh++) {       // 32-col halves of the 64 n
                int nb = n0 + nh * 32;
                uint32_t bh[2][4], bl[2][4];
#pragma unroll
                for (int p = 0; p < 2; p++) {
                    ldmx4(bh[p], bH + (nb + p * 16 + brow) * 144 + kb + bkq);
                    ldmx4(bl[p], bL + (nb + p * 16 + brow) * 144 + kb + bkq);
                }
#pragma unroll
                for (int mt = 0; mt < 2; mt++)
#pragma unroll
                    for (int nt = 0; nt < 4; nt++)
                        mma_bf16(acc[mt][nh * 4 + nt], ah[mt],
                                 bh[nt >> 1][(nt & 1) * 2], bh[nt >> 1][(nt & 1) * 2 + 1]);
#pragma unroll
                for (int mt = 0; mt < 2; mt++)
#pragma unroll
                    for (int nt = 0; nt < 4; nt++)
                        mma_bf16(acc[mt][nh * 4 + nt], ah[mt],
                                 bl[nt >> 1][(nt & 1) * 2], bl[nt >> 1][(nt & 1) * 2 + 1]);
#pragma unroll
                for (int mt = 0; mt < 2; mt++)
#pragma unroll
                    for (int nt = 0; nt < 4; nt++)
                        mma_bf16(acc[mt][nh * 4 + nt], al[mt],
                                 bh[nt >> 1][(nt & 1) * 2], bh[nt >> 1][(nt & 1) * 2 + 1]);
            }
        }
        __syncthreads();
    }

    // stash: k-half wk writes its own buffer, epilogue sums the two
    float* gks = (float*)smem + (size_t)wk * GSM_HALF;
#pragma unroll
    for (int mt = 0; mt < 2; mt++)
#pragma unroll
        for (int nt = 0; nt < 8; nt++) {
            int row = m0 + mt * 16 + (lane >> 2);
            int col = n0 + nt * 8 + (lane & 3) * 2;
            gks[row * 132 + col]     = acc[mt][nt][0];
            gks[row * 132 + col + 1] = acc[mt][nt][1];
            gks[(row + 8) * 132 + col]     = acc[mt][nt][2];
            gks[(row + 8) * 132 + col + 1] = acc[mt][nt][3];
        }
    __syncthreads();

    float* gsm = (float*)smem;
    int row = tid >> 2, c0 = (tid & 3) * 32;
    float* gp = G + (bm + row) * G_COLS + cb * 128;
#pragma unroll
    for (int q = 0; q < 8; q++) {
        int col = c0 + q * 4;
        float4 v  = *(float4*)(gsm + row * 132 + col);
        float4 v2 = *(float4*)(gsm + GSM_HALF + row * 132 + col);
        float4 bv = *(const float4*)(bias + cb * 128 + col);
        v.x += v2.x + bv.x; v.y += v2.y + bv.y;
        v.z += v2.z + bv.z; v.w += v2.w + bv.w;
        *(float4*)(gp + col) = v;
    }
}

// ---------------- row-block-local barrier (16 CTAs per group) --------------------
__device__ __forceinline__ void grid_bar_local(int grp) {
    __syncthreads();
    if (threadIdx.x == 0) {
        unsigned* genp = &d_barGenL[grp * 32];
        unsigned* cntp = &d_barCntL[grp * 32];
        unsigned g;
        asm volatile("ld.acquire.gpu.u32 %0, [%1];" : "=r"(g) : "l"(genp));
        unsigned a;
        asm volatile("atom.acq_rel.gpu.add.u32 %0, [%1], 1;"
                     : "=r"(a) : "l"(cntp) : "memory");
        if (a == 15u) {
            asm volatile("st.relaxed.gpu.u32 [%0], 0;" :: "l"(cntp) : "memory");
            asm volatile("red.release.gpu.add.u32 [%0], 1;" :: "l"(genp) : "memory");
        } else {
            unsigned cur;
            do {
                asm volatile("nanosleep.u32 64;");
                asm volatile("ld.acquire.gpu.u32 %0, [%1];" : "=r"(cur) : "l"(genp));
            } while (cur == g);
        }
    }
    __syncthreads();
}

// ---------------- persistent recurrent sequence kernel --------------------------
// grid (16, 8) = 128 CTAs. Loops t = 0..255; barrier only among the 16 CTAs
// sharing a row block (the only cross-CTA dependency). Gates + c prefetched.
__global__ void __launch_bounds__(384, 1)
clstm_seq96(const float* __restrict__ Gbase,
            const int* __restrict__ toks, const float* __restrict__ tab,
            const __nv_bfloat16* __restrict__ WhH, const __nv_bfloat16* __restrict__ WhL,
            float* __restrict__ cst,
            __nv_bfloat16* __restrict__ Hh, __nv_bfloat16* __restrict__ Hl) {
    extern __shared__ char smem[];
    const uint32_t sb = smem_to_u32(smem);
    const int tid = threadIdx.x, lane = tid & 31, w = tid >> 5;
    const int cb = blockIdx.x;
    const size_t bm = (size_t)blockIdx.y * 96;
    const int m0 = (w >> 2) * 32, n0 = (w & 3) * 32;
    const int arow = (lane & 7) + ((lane & 8) ? 8 : 0);
    const int akq  = (lane & 16) ? 16 : 0;
    const int brow = (lane & 7) + ((lane & 16) ? 8 : 0);
    const int bkq  = (lane & 8) ? 16 : 0;
    const __nv_bfloat16* bH0 = WhH + (size_t)(cb * 128) * H_DIM;
    const __nv_bfloat16* bL0 = WhL + (size_t)(cb * 128) * H_DIM;
    const int erow = tid >> 2, hb = (tid & 3) * 8;
    const size_t grow = bm + erow;
    const int hc0 = cb * 32 + hb;
    float* cp = cst + grow * H_DIM + hc0;
    float* gsm = (float*)smem;
    const float* gsm2 = (const float*)(smem + GOFF);
    const float* csm  = (const float*)(smem + COFF);

#pragma unroll 1
    for (int t = 0; t < T_LEN; t++) {
        // ---- prefetch gates (+ c) for this step into smem ----
        {
#pragma unroll
            for (int i = 0; i < 8; i++) {
                int f = tid + i * 384;          // 0..3071 float4s
                int r = f >> 5, rem = f & 31;
                int g = rem >> 3, jj = (rem & 7) << 2;
                const float* rowp;
                int rr = (int)bm + r;
                if (toks) {
                    int tk = __ldg(toks + ((rr >> 8) << 16) + ((rr & 255) << 8) + t);
                    rowp = tab + (size_t)tk * G_COLS;
                } else {
                    rowp = Gbase + (size_t)t * R_ROWS * G_COLS + (size_t)rr * G_COLS;
                }
                CP_ASYNC16(sb + GOFF + (uint32_t)((r * 128 + g * 32 + jj) * 4),
                           (const void*)(rowp + g * H_DIM + cb * 32 + jj));
            }
            if (t > 0) {
#pragma unroll
                for (int i = 0; i < 2; i++) {
                    int f = tid + i * 384;      // 0..767 float4s
                    int r = f >> 3, jj = (f & 7) << 2;
                    CP_ASYNC16(sb + COFF + (uint32_t)((r * 32 + jj) * 4),
                               (const void*)(cst + (bm + r) * H_DIM + cb * 32 + jj));
                }
            }
            CP_COMMIT();
        }

        float acc[2][4][4];
#pragma unroll
        for (int mt = 0; mt < 2; mt++)
#pragma unroll
            for (int nt = 0; nt < 4; nt++)
#pragma unroll
                for (int e = 0; e < 4; e++) acc[mt][nt][e] = 0.f;

        if (t > 0) {
            const __nv_bfloat16* aH0 = Hh + (size_t)(t - 1) * RH + bm * H_DIM;
            const __nv_bfloat16* aL0 = Hl + (size_t)(t - 1) * RH + bm * H_DIM;
            mma_tile96(sb, tid, m0, n0, arow, akq, brow, bkq, aH0, aL0, bH0, bL0, acc);
        } else {
            CP_WAIT0();
            __syncthreads();
        }

        // stash accumulators (stage0 smem reuse)
#pragma unroll
        for (int mt = 0; mt < 2; mt++)
#pragma unroll
            for (int nt = 0; nt < 4; nt++) {
                int row = m0 + mt * 16 + (lane >> 2);
                int col = n0 + nt * 8 + (lane & 3) * 2;
                gsm[row * 132 + col]     = acc[mt][nt][0];
                gsm[row * 132 + col + 1] = acc[mt][nt][1];
                gsm[(row + 8) * 132 + col]     = acc[mt][nt][2];
                gsm[(row + 8) * 132 + col + 1] = acc[mt][nt][3];
            }
        __syncthreads();

        // fused LSTM epilogue (gates + c from smem)
        __nv_bfloat16* hhp = Hh + (size_t)t * RH + grow * H_DIM + hc0;
        __nv_bfloat16* hlp = Hl + (size_t)t * RH + grow * H_DIM + hc0;
#pragma unroll
        for (int q = 0; q < 2; q++) {
            float4 gi = *(const float4*)(gsm2 + erow * 128 +       hb + q * 4);
            float4 gf = *(const float4*)(gsm2 + erow * 128 +  32 + hb + q * 4);
            float4 gg = *(const float4*)(gsm2 + erow * 128 +  64 + hb + q * 4);
            float4 go = *(const float4*)(gsm2 + erow * 128 +  96 + hb + q * 4);
            float4 co = make_float4(0.f, 0.f, 0.f, 0.f);
            if (t > 0) co = *(const float4*)(csm + erow * 32 + hb + q * 4);
            float4 cv;
            __nv_bfloat16 bh4[4], bl4[4];
#pragma unroll
            for (int e = 0; e < 4; e++) {
                int li = erow * 132 + hb + q * 4 + e;
                float xi = gsm[li]       + ((const float*)&gi)[e];
                float xf = gsm[li + 32]  + ((const float*)&gf)[e];
                float xg = gsm[li + 64]  + ((const float*)&gg)[e];
                float xo = gsm[li + 96]  + ((const float*)&go)[e];
                float I = 1.f / (1.f + __expf(-xi));
                float F = 1.f / (1.f + __expf(-xf));
                float Gv = tanhf(xg);
                float O = 1.f / (1.f + __expf(-xo));
                float cn = F * ((const float*)&co)[e] + I * Gv;
                float hn = O * tanhf(cn);
                ((float*)&cv)[e] = cn;
                bh4[e] = __float2bfloat16(hn);
                bl4[e] = __float2bfloat16(hn - __bfloat162float(bh4[e]));
            }
            *(float4*)(cp + q * 4) = cv;
            __nv_bfloat162 p0; p0.x = bh4[0]; p0.y = bh4[1];
            __nv_bfloat162 p1; p1.x = bh4[2]; p1.y = bh4[3];
            __nv_bfloat162 q0; q0.x = bl4[0]; q0.y = bl4[1];
            __nv_bfloat162 q1; q1.x = bl4[2]; q1.y = bl4[3];
            *(__nv_bfloat162*)(hhp + q * 4)     = p0;
            *(__nv_bfloat162*)(hhp + q * 4 + 2) = p1;
            *(__nv_bfloat162*)(hlp + q * 4)     = q0;
            *(__nv_bfloat162*)(hlp + q * 4 + 2) = q1;
        }
        grid_bar_local(blockIdx.y);
    }
}

// ---------------- head kernels -------------------------------------------------
__global__ void clstm_gather_r(const __nv_bfloat16* __restrict__ Hhi,
                               const __nv_bfloat16* __restrict__ Hlo,
                               float* __restrict__ r) {
    int b = blockIdx.x, i = blockIdx.y, h = threadIdx.x;
    size_t idx = ((size_t)(T_LEN - 1) * R_ROWS + i * B_SZ + b) * H_DIM + h;
    r[(size_t)b * 1536 + i * H_DIM + h] =
        __bfloat162float(Hhi[idx]) + __bfloat162float(Hlo[idx]);
}

__global__ void clstm_bn(float* __restrict__ x, const float* __restrict__ gamma,
                         const float* __restrict__ beta, int N) {
    __shared__ float s1[256], s2[256];
    int col = blockIdx.x;
    float v = x[(size_t)threadIdx.x * N + col];
    s1[threadIdx.x] = v; s2[threadIdx.x] = v * v;
    __syncthreads();
    for (int s = 128; s > 0; s >>= 1) {
        if (threadIdx.x < s) {
            s1[threadIdx.x] += s1[threadIdx.x + s];
            s2[threadIdx.x] += s2[threadIdx.x + s];
        }
        __syncthreads();
    }
    float m = s1[0] * (1.f / 256.f);
    float var = s2[0] * (1.f / 256.f) - m * m;
    float inv = rsqrtf(var + 1e-3f);
    x[(size_t)threadIdx.x * N + col] = gamma[col] * (v - m) * inv + beta[col];
}

__global__ void clstm_gemm_head(const float* __restrict__ A, const float* __restrict__ W,
                                const float* __restrict__ bias, float* __restrict__ C,
                                int K, int N, int act) {
    int n = blockIdx.x * 128 + threadIdx.x;
    int m0 = blockIdx.y * 16;
    if (n >= N) return;
    float s[16];
#pragma unroll
    for (int mm = 0; mm < 16; mm++) s[mm] = bias[n];
    for (int k = 0; k < K; k++) {
        float w = W[(size_t)k * N + n];
#pragma unroll
        for (int mm = 0; mm < 16; mm++)
            s[mm] += A[(size_t)(m0 + mm) * K + k] * w;
    }
    const float alpha = 1.6732632423543772f, scale = 1.0507009873554805f;
#pragma unroll
    for (int mm = 0; mm < 16; mm++) {
        float v = s[mm];
        if (act) v = scale * (v > 0.f ? v : alpha * expm1f(v));
        C[(size_t)(m0 + mm) * N + n] = v;
    }
}

// ---------------- launch --------------------------------------------------------
extern "C" void kernel_launch(void* const* d_in, const int* in_sizes, int n_in,
                              void* d_out, int out_size) {
    const int* t1 = (const int*)d_in[0];
    const int* t2 = (const int*)d_in[1];
    const int* t3 = (const int*)d_in[2];
    const float* emb = (const float*)d_in[3];
    const float* Wx = (const float*)d_in[4];
    const float* Wh = (const float*)d_in[5];
    const float* bb = (const float*)d_in[6];
    const float* g1 = (const float*)d_in[7];
    const float* be1 = (const float*)d_in[8];
    const float* W1 = (const float*)d_in[9];
    const float* bd1 = (const float*)d_in[10];
    const float* g2 = (const float*)d_in[11];
    const float* be2 = (const float*)d_in[12];
    const float* W2 = (const float*)d_in[13];
    const float* bd2 = (const float*)d_in[14];
    const float* g3 = (const float*)d_in[15];
    const float* be3 = (const float*)d_in[16];
    const float* W3 = (const float*)d_in[17];
    const float* bd3 = (const float*)d_in[18];
    float* out = (float*)d_out;

    float *G, *TAB, *C, *R, *H1, *H2;
    int* TOK;
    __nv_bfloat16 *Eh, *El, *WhPh, *WhPl, *WxTh, *WxTl, *sAh, *sAl, *sBh, *sBl;
    cudaGetSymbolAddress((void**)&G, d_Gbuf);
    cudaGetSymbolAddress((void**)&TAB, d_tab);
    cudaGetSymbolAddress((void**)&C, d_cst);
    cudaGetSymbolAddress((void**)&R, d_rbuf);
    cudaGetSymbolAddress((void**)&H1, d_h1buf);
    cudaGetSymbolAddress((void**)&H2, d_h2buf);
    cudaGetSymbolAddress((void**)&TOK, d_toks);
    cudaGetSymbolAddress((void**)&Eh, d_Ehi);
    cudaGetSymbolAddress((void**)&El, d_Elo);
    cudaGetSymbolAddress((void**)&WhPh, d_WhPhi);
    cudaGetSymbolAddress((void**)&WhPl, d_WhPlo);
    cudaGetSymbolAddress((void**)&WxTh, d_WxThi);
    cudaGetSymbolAddress((void**)&WxTl, d_WxTlo);
    cudaGetSymbolAddress((void**)&sAh, d_sAhi);
    cudaGetSymbolAddress((void**)&sAl, d_sAlo);
    cudaGetSymbolAddress((void**)&sBh, d_sBhi);
    cudaGetSymbolAddress((void**)&sBl, d_sBlo);

    cudaFuncSetAttribute(clstm_gemm_mma, cudaFuncAttributeMaxDynamicSharedMemorySize,
                         MMA_SMEM);
    cudaFuncSetAttribute(clstm_gemm96, cudaFuncAttributeMaxDynamicSharedMemorySize,
                         GEMM96_SMEM);
    cudaFuncSetAttribute(clstm_seq96, cudaFuncAttributeMaxDynamicSharedMemorySize,
                         SEQ_SMEM);

    // preprocessing
    cudaMemcpyAsync(TOK,          t1, 65536 * sizeof(int), cudaMemcpyDeviceToDevice, 0);
    cudaMemcpyAsync(TOK + 65536,  t2, 65536 * sizeof(int), cudaMemcpyDeviceToDevice, 0);
    cudaMemcpyAsync(TOK + 131072, t3, 65536 * sizeof(int), cudaMemcpyDeviceToDevice, 0);
    clstm_splitemb<<<V_SZ, 128>>>(emb, Eh, El);
    clstm_makeWsplit<<<dim3(64, 16, 3), dim3(32, 8)>>>(Wh, WhPh, WhPl, 1);
    clstm_makeWsplit<<<dim3(64, 16, 3), dim3(32, 8)>>>(Wx, WxTh, WxTl, 0);
    // vocab gate table: tab = emb @ Wx0 + b0   [32000, 2048]
    clstm_gemm_mma<<<dim3(16, V_SZ / 64), 256, MMA_SMEM>>>(
        Eh, El, WxTh, WxTl, bb, TAB);

    // layer 1: persistent sequence, gates from tab[token]; output h seq -> sB
    clstm_seq96<<<dim3(16, 8), 384, SEQ_SMEM>>>(
        (const float*)0, TOK, TAB, WhPh, WhPl, C, sBh, sBl);

    // layers 2,3
    __nv_bfloat16 *inH = sBh, *inL = sBl, *outH = sAh, *outL = sAl;
    for (int l = 1; l < 3; l++) {
        size_t woff = (size_t)l * G_COLS * H_DIM;
        clstm_gemm96<<<dim3(16, M_ALL / 96), 384, GEMM96_SMEM>>>(
            inH, inL, WxTh + woff, WxTl + woff, bb + (size_t)l * G_COLS, G);
        clstm_seq96<<<dim3(16, 8), 384, SEQ_SMEM>>>(
            G, (const int*)0, (const float*)0,
            WhPh + woff, WhPl + woff, C, outH, outL);
        __nv_bfloat16* tm;
        tm = inH; inH = outH; outH = tm;
        tm = inL; inL = outL; outL = tm;
    }

    // head
    clstm_gather_r<<<dim3(B_SZ, 3), H_DIM>>>(inH, inL, R);
    clstm_bn<<<1536, 256>>>(R, g1, be1, 1536);
    clstm_gemm_head<<<dim3(8, 16), 128>>>(R, W1, bd1, H1, 1536, 1024, 1);
    clstm_bn<<<1024, 256>>>(H1, g2, be2, 1024);
    clstm_gemm_head<<<dim3(1, 16), 128>>>(H1, W2, bd2, H2, 1024, H5, 1);
    clstm_bn<<<H5, 256>>>(H2, g3, be3, H5);
    clstm_gemm_head<<<dim3(1, 16), 128>>>(H2, W3, bd3, out, H5, 4, 0);
}

// round 14
// speedup vs baseline: 1.0553x; 1.0275x over previous
#include <cuda_runtime.h>
#include <cuda_bf16.h>
#include <math.h>
#include <stdint.h>
#include <stddef.h>

#define T_LEN 256
#define B_SZ  256
#define H_DIM 512
#define R_ROWS 768
#define G_COLS 2048
#define M_ALL  196608
#define V_SZ   32000
#define H5 102
#define RH 393216            // R_ROWS * H_DIM

// ---------------- static device scratch --------------------------------------
// NOTE: single G buffer; the fused kernel reads gates[t] and overwrites
// gates[t-1] in place (safe: slot t read at iter t, overwritten at iter t+1,
// ordered by the per-group barrier). Keeps .bss < 4GB (AArch64 reloc limit).
__device__ float d_Gbuf[402653184];   // [T][768][2048]
__device__ float d_tab[65536000];     // [32000][2048] emb@Wx0 + b0
__device__ float d_cst[393216];
__device__ float d_rbuf[393216];
__device__ float d_h1buf[262144];
__device__ float d_h2buf[26112];
__device__ int   d_toks[196608];      // [3][256][256]
__device__ unsigned d_barGenL[256];   // 8 groups, stride 32
__device__ unsigned d_barCntL[256];
__device__ __nv_bfloat16 d_Ehi[16384000];           // emb split [32000][512]
__device__ __nv_bfloat16 d_Elo[16384000];
__device__ __nv_bfloat16 d_WhPhi[3 * 2048 * 512];   // Wh permuted [n'][k] hi
__device__ __nv_bfloat16 d_WhPlo[3 * 2048 * 512];
__device__ __nv_bfloat16 d_WxThi[3 * 2048 * 512];   // Wx transposed [n][k] hi
__device__ __nv_bfloat16 d_WxTlo[3 * 2048 * 512];
__device__ __nv_bfloat16 d_sAhi[100663296];         // h seq splits (ping)
__device__ __nv_bfloat16 d_sAlo[100663296];
__device__ __nv_bfloat16 d_sBhi[100663296];         // (pong)
__device__ __nv_bfloat16 d_sBlo[100663296];

// ---------------- helpers ------------------------------------------------------
__device__ __forceinline__ uint32_t smem_to_u32(const void* p) {
    uint32_t a;
    asm("{ .reg .u64 t; cvta.to.shared.u64 t, %1; cvt.u32.u64 %0, t; }"
        : "=r"(a) : "l"(p));
    return a;
}
__device__ __forceinline__ void ldmx4(uint32_t* r, uint32_t addr) {
    asm volatile("ldmatrix.sync.aligned.m8n8.x4.shared.b16 {%0,%1,%2,%3}, [%4];"
                 : "=r"(r[0]), "=r"(r[1]), "=r"(r[2]), "=r"(r[3]) : "r"(addr));
}
__device__ __forceinline__ void mma_bf16(float* c, const uint32_t* a,
                                         uint32_t b0, uint32_t b1) {
    asm volatile(
        "mma.sync.aligned.m16n8k16.row.col.f32.bf16.bf16.f32 "
        "{%0,%1,%2,%3}, {%4,%5,%6,%7}, {%8,%9}, {%0,%1,%2,%3};"
        : "+f"(c[0]), "+f"(c[1]), "+f"(c[2]), "+f"(c[3])
        : "r"(a[0]), "r"(a[1]), "r"(a[2]), "r"(a[3]), "r"(b0), "r"(b1));
}
#define CP_ASYNC16(dst, src) \
    asm volatile("cp.async.cg.shared.global [%0], [%1], 16;" :: "r"(dst), "l"(src))
#define CP_COMMIT()  asm volatile("cp.async.commit_group;" ::: "memory")
#define CP_WAIT0()   asm volatile("cp.async.wait_group 0;" ::: "memory")
#define CP_WAIT1()   asm volatile("cp.async.wait_group 1;" ::: "memory")

// ---- 64-row kernel smem (vocab table GEMM) ----
#define STAGE_B 55296
#define MMA_SMEM 110592
// ---- 96-row plain seq kernel ----
#define S96_AP 13824          // 96*144
#define S96_BP 18432          // 128*144
#define S96_STAGE 64512       // 2*AP + 2*BP
#define GOFF 129024           // gates prefetch (96*128 f32)
#define COFF 178176           // c prefetch (96*32 f32)
#define SEQ_SMEM 190464
// ---- fused seq kernel: stage = 2*AP + 4*BP ----
#define FSTAGE 101376
#define SEQF_SMEM 202752      // 2 stages; gates/c prefetch reuses stage0 region

// ---------------- emb -> bf16 split ---------------------------------------------
__global__ void clstm_splitemb(const float* __restrict__ emb,
                               __nv_bfloat16* __restrict__ Ehi,
                               __nv_bfloat16* __restrict__ Elo) {
    size_t base = (size_t)blockIdx.x * H_DIM + threadIdx.x * 4;
    float4 v = *(const float4*)(emb + base);
    float vv[4] = { v.x, v.y, v.z, v.w };
#pragma unroll
    for (int e = 0; e < 4; e++) {
        __nv_bfloat16 h = __float2bfloat16(vv[e]);
        Ehi[base + e] = h;
        Elo[base + e] = __float2bfloat16(vv[e] - __bfloat162float(h));
    }
}

// ---------------- W [k][n] -> [n'][k] bf16 split (optional gate permute) --------
__global__ void clstm_makeWsplit(const float* __restrict__ W,
                                 __nv_bfloat16* __restrict__ Phi,
                                 __nv_bfloat16* __restrict__ Plo, int permute) {
    __shared__ float tile[32][33];
    int n0 = blockIdx.x * 32, k0 = blockIdx.y * 32, l = blockIdx.z;
    const float* Wl = W + (size_t)l * H_DIM * G_COLS;
    int tx = threadIdx.x, ty = threadIdx.y;
#pragma unroll
    for (int it = 0; it < 4; it++)
        tile[ty + it * 8][tx] = Wl[(size_t)(k0 + ty + it * 8) * G_COLS + n0 + tx];
    __syncthreads();
    int s = n0 >> 9, cbb = (n0 >> 5) & 15;
    int np0 = permute ? (cbb * 128 + s * 32) : n0;
    __nv_bfloat16* ph = Phi + (size_t)l * G_COLS * H_DIM;
    __nv_bfloat16* pl = Plo + (size_t)l * G_COLS * H_DIM;
#pragma unroll
    for (int it = 0; it < 4; it++) {
        int nn = ty + it * 8;
        float v = tile[tx][nn];
        __nv_bfloat16 hi = __float2bfloat16(v);
        __nv_bfloat16 lo = __float2bfloat16(v - __bfloat162float(hi));
        ph[(size_t)(np0 + nn) * H_DIM + k0 + tx] = hi;
        pl[(size_t)(np0 + nn) * H_DIM + k0 + tx] = lo;
    }
}

// ---------------- HMMA 64-row GEMM (vocab table only) ---------------------------
__global__ void __launch_bounds__(256, 2)
clstm_gemm_mma(const __nv_bfloat16* __restrict__ Ahi, const __nv_bfloat16* __restrict__ Alo,
               const __nv_bfloat16* __restrict__ Bhi, const __nv_bfloat16* __restrict__ Blo,
               const float* __restrict__ bias, float* __restrict__ G) {
    extern __shared__ char smem[];
    const uint32_t sb = smem_to_u32(smem);
    const int tid = threadIdx.x, lane = tid & 31, w = tid >> 5;
    const int cb = blockIdx.x;
    const size_t bm = (size_t)blockIdx.y * 64;
    const __nv_bfloat16* asrc[2] = { Ahi + bm * H_DIM, Alo + bm * H_DIM };
    const __nv_bfloat16* bsrc[2] = { Bhi + (size_t)(cb * 128) * H_DIM,
                                     Blo + (size_t)(cb * 128) * H_DIM };
    const int lr = tid >> 3, lq = tid & 7;

    auto load_chunk = [&](int c, int s) {
        uint32_t stg = sb + (uint32_t)s * STAGE_B;
#pragma unroll
        for (int p = 0; p < 2; p++) {
            const __nv_bfloat16* gb = asrc[p] + c * 64;
            uint32_t sd = stg + p * 9216;
#pragma unroll
            for (int i = 0; i < 2; i++) {
                int r = lr + i * 32;
                CP_ASYNC16(sd + r * 144 + lq * 16,
                           (const void*)(gb + (size_t)r * H_DIM + lq * 8));
            }
        }
#pragma unroll
        for (int p = 0; p < 2; p++) {
            const __nv_bfloat16* gb = bsrc[p] + c * 64;
            uint32_t sd = stg + 18432 + p * 18432;
#pragma unroll
            for (int i = 0; i < 4; i++) {
                int r = lr + i * 32;
                CP_ASYNC16(sd + r * 144 + lq * 16,
                           (const void*)(gb + (size_t)r * H_DIM + lq * 8));
            }
        }
        CP_COMMIT();
    };

    const int m0 = (w >> 1) * 16, n0 = (w & 1) * 64;
    const int arow = (lane & 7) + ((lane & 8) ? 8 : 0);
    const int akq  = (lane & 16) ? 16 : 0;
    const int brow = (lane & 7) + ((lane & 16) ? 8 : 0);
    const int bkq  = (lane & 8) ? 16 : 0;

    float acc[8][4];
#pragma unroll
    for (int nt = 0; nt < 8; nt++)
#pragma unroll
        for (int e = 0; e < 4; e++) acc[nt][e] = 0.f;

    load_chunk(0, 0);
    for (int c = 0; c < 8; c++) {
        if (c < 7) { load_chunk(c + 1, (c + 1) & 1); CP_WAIT1(); }
        else       { CP_WAIT0(); }
        __syncthreads();
        uint32_t stg = sb + (uint32_t)(c & 1) * STAGE_B;
        uint32_t aH = stg, aL = stg + 9216, bH = stg + 18432, bL = stg + 36864;
#pragma unroll
        for (int ks = 0; ks < 4; ks++) {
            int kb = ks * 32;
            uint32_t ah[4], al[4], bh[4][4], bl[4][4];
            ldmx4(ah, aH + (m0 + arow) * 144 + kb + akq);
            ldmx4(al, aL + (m0 + arow) * 144 + kb + akq);
#pragma unroll
            for (int p = 0; p < 4; p++) {
                ldmx4(bh[p], bH + (n0 + p * 16 + brow) * 144 + kb + bkq);
                ldmx4(bl[p], bL + (n0 + p * 16 + brow) * 144 + kb + bkq);
            }
#pragma unroll
            for (int nt = 0; nt < 8; nt++)
                mma_bf16(acc[nt], ah, bh[nt >> 1][(nt & 1) * 2], bh[nt >> 1][(nt & 1) * 2 + 1]);
#pragma unroll
            for (int nt = 0; nt < 8; nt++)
                mma_bf16(acc[nt], ah, bl[nt >> 1][(nt & 1) * 2], bl[nt >> 1][(nt & 1) * 2 + 1]);
#pragma unroll
            for (int nt = 0; nt < 8; nt++)
                mma_bf16(acc[nt], al, bh[nt >> 1][(nt & 1) * 2], bh[nt >> 1][(nt & 1) * 2 + 1]);
        }
        __syncthreads();
    }

    float* gsm = (float*)smem;     // [64][132]
#pragma unroll
    for (int nt = 0; nt < 8; nt++) {
        int row = m0 + (lane >> 2);
        int col = n0 + nt * 8 + (lane & 3) * 2;
        gsm[row * 132 + col]     = acc[nt][0];
        gsm[row * 132 + col + 1] = acc[nt][1];
        gsm[(row + 8) * 132 + col]     = acc[nt][2];
        gsm[(row + 8) * 132 + col + 1] = acc[nt][3];
    }
    __syncthreads();

    int row = tid >> 2, c0 = (tid & 3) * 32;
    float* gp = G + (bm + row) * G_COLS + cb * 128;
#pragma unroll
    for (int q = 0; q < 8; q++) {
        int col = c0 + q * 4;
        float4 v = *(float4*)(gsm + row * 132 + col);
        float4 bv = *(const float4*)(bias + cb * 128 + col);
        v.x += bv.x; v.y += bv.y; v.z += bv.z; v.w += bv.w;
        *(float4*)(gp + col) = v;
    }
}

// ---------------- row-block-local barrier (16 CTAs per group) --------------------
__device__ __forceinline__ void grid_bar_local(int grp) {
    __syncthreads();
    if (threadIdx.x == 0) {
        unsigned* genp = &d_barGenL[grp * 32];
        unsigned* cntp = &d_barCntL[grp * 32];
        unsigned g;
        asm volatile("ld.acquire.gpu.u32 %0, [%1];" : "=r"(g) : "l"(genp));
        unsigned a;
        asm volatile("atom.acq_rel.gpu.add.u32 %0, [%1], 1;"
                     : "=r"(a) : "l"(cntp) : "memory");
        if (a == 15u) {
            asm volatile("st.relaxed.gpu.u32 [%0], 0;" :: "l"(cntp) : "memory");
            asm volatile("red.release.gpu.add.u32 [%0], 1;" :: "l"(genp) : "memory");
        } else {
            unsigned cur;
            do {
                asm volatile("nanosleep.u32 64;");
                asm volatile("ld.acquire.gpu.u32 %0, [%1];" : "=r"(cur) : "l"(genp));
            } while (cur == g);
        }
    }
    __syncthreads();
}

// ---------------- plain 96-row seq (layer 3) -------------------------------------
__device__ __forceinline__ void load96_chunk(
    uint32_t sb, int tid, int c, int s,
    const __nv_bfloat16* __restrict__ aH0, const __nv_bfloat16* __restrict__ aL0,
    const __nv_bfloat16* __restrict__ bH0, const __nv_bfloat16* __restrict__ bL0)
{
    uint32_t stg = sb + (uint32_t)s * S96_STAGE;
#pragma unroll
    for (int i = 0; i < 10; i++) {
        int idx = tid + i * 384;
        if (idx < 3584) {
            uint32_t d; const __nv_bfloat16* g;
            if (idx < 1536) {
                int p = idx >= 768, rem = idx - p * 768;
                int r = rem >> 3, q = rem & 7;
                d = stg + p * S96_AP + r * 144 + q * 16;
                g = (p ? aL0 : aH0) + c * 64 + (size_t)r * H_DIM + q * 8;
            } else {
                int j = idx - 1536;
                int p = j >= 1024, rem = j - p * 1024;
                int r = rem >> 3, q = rem & 7;
                d = stg + 2 * S96_AP + p * S96_BP + r * 144 + q * 16;
                g = (p ? bL0 : bH0) + c * 64 + (size_t)r * H_DIM + q * 8;
            }
            CP_ASYNC16(d, (const void*)g);
        }
    }
    CP_COMMIT();
}

__device__ __forceinline__ void mma_tile96(
    uint32_t sb, int tid, int m0, int n0,
    int arow, int akq, int brow, int bkq,
    const __nv_bfloat16* __restrict__ aH0, const __nv_bfloat16* __restrict__ aL0,
    const __nv_bfloat16* __restrict__ bH0, const __nv_bfloat16* __restrict__ bL0,
    float acc[2][4][4])
{
    load96_chunk(sb, tid, 0, 0, aH0, aL0, bH0, bL0);
#pragma unroll 1
    for (int c = 0; c < 8; c++) {
        if (c < 7) { load96_chunk(sb, tid, c + 1, (c + 1) & 1, aH0, aL0, bH0, bL0); CP_WAIT1(); }
        else       { CP_WAIT0(); }
        __syncthreads();
        uint32_t stg = sb + (uint32_t)(c & 1) * S96_STAGE;
        uint32_t aH = stg, aL = stg + S96_AP;
        uint32_t bH = stg + 2 * S96_AP, bL = bH + S96_BP;
#pragma unroll
        for (int ks = 0; ks < 4; ks++) {
            int kb = ks * 32;
            uint32_t ah[2][4], al[2][4], bh[2][4], bl[2][4];
#pragma unroll
            for (int mt = 0; mt < 2; mt++) {
                ldmx4(ah[mt], aH + (m0 + mt * 16 + arow) * 144 + kb + akq);
                ldmx4(al[mt], aL + (m0 + mt * 16 + arow) * 144 + kb + akq);
            }
#pragma unroll
            for (int p = 0; p < 2; p++) {
                ldmx4(bh[p], bH + (n0 + p * 16 + brow) * 144 + kb + bkq);
                ldmx4(bl[p], bL + (n0 + p * 16 + brow) * 144 + kb + bkq);
            }
#pragma unroll
            for (int mt = 0; mt < 2; mt++)
#pragma unroll
                for (int nt = 0; nt < 4; nt++)
                    mma_bf16(acc[mt][nt], ah[mt],
                             bh[nt >> 1][(nt & 1) * 2], bh[nt >> 1][(nt & 1) * 2 + 1]);
#pragma unroll
            for (int mt = 0; mt < 2; mt++)
#pragma unroll
                for (int nt = 0; nt < 4; nt++)
                    mma_bf16(acc[mt][nt], ah[mt],
                             bl[nt >> 1][(nt & 1) * 2], bl[nt >> 1][(nt & 1) * 2 + 1]);
#pragma unroll
            for (int mt = 0; mt < 2; mt++)
#pragma unroll
                for (int nt = 0; nt < 4; nt++)
                    mma_bf16(acc[mt][nt], al[mt],
                             bh[nt >> 1][(nt & 1) * 2], bh[nt >> 1][(nt & 1) * 2 + 1]);
        }
        __syncthreads();
    }
}

__global__ void __launch_bounds__(384, 1)
clstm_seq96(const float* __restrict__ Gbase,
            const int* __restrict__ toks, const float* __restrict__ tab,
            const __nv_bfloat16* __restrict__ WhH, const __nv_bfloat16* __restrict__ WhL,
            float* __restrict__ cst,
            __nv_bfloat16* __restrict__ Hh, __nv_bfloat16* __restrict__ Hl) {
    extern __shared__ char smem[];
    const uint32_t sb = smem_to_u32(smem);
    const int tid = threadIdx.x, lane = tid & 31, w = tid >> 5;
    const int cb = blockIdx.x;
    const size_t bm = (size_t)blockIdx.y * 96;
    const int m0 = (w >> 2) * 32, n0 = (w & 3) * 32;
    const int arow = (lane & 7) + ((lane & 8) ? 8 : 0);
    const int akq  = (lane & 16) ? 16 : 0;
    const int brow = (lane & 7) + ((lane & 16) ? 8 : 0);
    const int bkq  = (lane & 8) ? 16 : 0;
    const __nv_bfloat16* bH0 = WhH + (size_t)(cb * 128) * H_DIM;
    const __nv_bfloat16* bL0 = WhL + (size_t)(cb * 128) * H_DIM;
    const int erow = tid >> 2, hb = (tid & 3) * 8;
    const size_t grow = bm + erow;
    const int hc0 = cb * 32 + hb;
    float* cp = cst + grow * H_DIM + hc0;
    float* gsm = (float*)smem;
    const float* gsm2 = (const float*)(smem + GOFF);
    const float* csm  = (const float*)(smem + COFF);

#pragma unroll 1
    for (int t = 0; t < T_LEN; t++) {
        {
#pragma unroll
            for (int i = 0; i < 8; i++) {
                int f = tid + i * 384;
                int r = f >> 5, rem = f & 31;
                int g = rem >> 3, jj = (rem & 7) << 2;
                const float* rowp;
                int rr = (int)bm + r;
                if (toks) {
                    int tk = __ldg(toks + ((rr >> 8) << 16) + ((rr & 255) << 8) + t);
                    rowp = tab + (size_t)tk * G_COLS;
                } else {
                    rowp = Gbase + (size_t)t * R_ROWS * G_COLS + (size_t)rr * G_COLS;
                }
                CP_ASYNC16(sb + GOFF + (uint32_t)((r * 128 + g * 32 + jj) * 4),
                           (const void*)(rowp + g * H_DIM + cb * 32 + jj));
            }
            if (t > 0) {
#pragma unroll
                for (int i = 0; i < 2; i++) {
                    int f = tid + i * 384;
                    int r = f >> 3, jj = (f & 7) << 2;
                    CP_ASYNC16(sb + COFF + (uint32_t)((r * 32 + jj) * 4),
                               (const void*)(cst + (bm + r) * H_DIM + cb * 32 + jj));
                }
            }
            CP_COMMIT();
        }

        float acc[2][4][4];
#pragma unroll
        for (int mt = 0; mt < 2; mt++)
#pragma unroll
            for (int nt = 0; nt < 4; nt++)
#pragma unroll
                for (int e = 0; e < 4; e++) acc[mt][nt][e] = 0.f;

        if (t > 0) {
            const __nv_bfloat16* aH0 = Hh + (size_t)(t - 1) * RH + bm * H_DIM;
            const __nv_bfloat16* aL0 = Hl + (size_t)(t - 1) * RH + bm * H_DIM;
            mma_tile96(sb, tid, m0, n0, arow, akq, brow, bkq, aH0, aL0, bH0, bL0, acc);
        } else {
            CP_WAIT0();
            __syncthreads();
        }

#pragma unroll
        for (int mt = 0; mt < 2; mt++)
#pragma unroll
            for (int nt = 0; nt < 4; nt++) {
                int row = m0 + mt * 16 + (lane >> 2);
                int col = n0 + nt * 8 + (lane & 3) * 2;
                gsm[row * 132 + col]     = acc[mt][nt][0];
                gsm[row * 132 + col + 1] = acc[mt][nt][1];
                gsm[(row + 8) * 132 + col]     = acc[mt][nt][2];
                gsm[(row + 8) * 132 + col + 1] = acc[mt][nt][3];
            }
        __syncthreads();

        __nv_bfloat16* hhp = Hh + (size_t)t * RH + grow * H_DIM + hc0;
        __nv_bfloat16* hlp = Hl + (size_t)t * RH + grow * H_DIM + hc0;
#pragma unroll
        for (int q = 0; q < 2; q++) {
            float4 gi = *(const float4*)(gsm2 + erow * 128 +       hb + q * 4);
            float4 gf = *(const float4*)(gsm2 + erow * 128 +  32 + hb + q * 4);
            float4 gg = *(const float4*)(gsm2 + erow * 128 +  64 + hb + q * 4);
            float4 go = *(const float4*)(gsm2 + erow * 128 +  96 + hb + q * 4);
            float4 co = make_float4(0.f, 0.f, 0.f, 0.f);
            if (t > 0) co = *(const float4*)(csm + erow * 32 + hb + q * 4);
            float4 cv;
            __nv_bfloat16 bh4[4], bl4[4];
#pragma unroll
            for (int e = 0; e < 4; e++) {
                int li = erow * 132 + hb + q * 4 + e;
                float xi = gsm[li]       + ((const float*)&gi)[e];
                float xf = gsm[li + 32]  + ((const float*)&gf)[e];
                float xg = gsm[li + 64]  + ((const float*)&gg)[e];
                float xo = gsm[li + 96]  + ((const float*)&go)[e];
                float I = 1.f / (1.f + __expf(-xi));
                float F = 1.f / (1.f + __expf(-xf));
                float Gv = tanhf(xg);
                float O = 1.f / (1.f + __expf(-xo));
                float cn = F * ((const float*)&co)[e] + I * Gv;
                float hn = O * tanhf(cn);
                ((float*)&cv)[e] = cn;
                bh4[e] = __float2bfloat16(hn);
                bl4[e] = __float2bfloat16(hn - __bfloat162float(bh4[e]));
            }
            *(float4*)(cp + q * 4) = cv;
            __nv_bfloat162 p0; p0.x = bh4[0]; p0.y = bh4[1];
            __nv_bfloat162 p1; p1.x = bh4[2]; p1.y = bh4[3];
            __nv_bfloat162 q0; q0.x = bl4[0]; q0.y = bl4[1];
            __nv_bfloat162 q1; q1.x = bl4[2]; q1.y = bl4[3];
            *(__nv_bfloat162*)(hhp + q * 4)     = p0;
            *(__nv_bfloat162*)(hhp + q * 4 + 2) = p1;
            *(__nv_bfloat162*)(hlp + q * 4)     = q0;
            *(__nv_bfloat162*)(hlp + q * 4 + 2) = q1;
        }
        grid_bar_local(blockIdx.y);
    }
}

// ---------------- FUSED seq: recurrence + next-layer gate GEMM -------------------
// Per iteration i (A = h[i-1], staged once): recurrent gates for step i AND
// G_next[i-1] = h[i-1]@Wx_next + nbias. Iteration 256 finishes G_next[255].
// Gout may alias Gbase (slot i read at iter i, overwritten at iter i+1).
__device__ __forceinline__ void loadF_chunk(
    uint32_t sb, int tid, int c, int s,
    const __nv_bfloat16* __restrict__ aH0, const __nv_bfloat16* __restrict__ aL0,
    const __nv_bfloat16* __restrict__ wh, const __nv_bfloat16* __restrict__ wl,
    const __nv_bfloat16* __restrict__ xh, const __nv_bfloat16* __restrict__ xl)
{
    uint32_t stg = sb + (uint32_t)s * FSTAGE;
#pragma unroll
    for (int i = 0; i < 15; i++) {
        int idx = tid + i * 384;
        if (idx < 5632) {
            uint32_t d; const __nv_bfloat16* g;
            if (idx < 1536) {
                int p = idx >= 768, rem = idx - p * 768;
                int r = rem >> 3, q = rem & 7;
                d = stg + p * S96_AP + r * 144 + q * 16;
                g = (p ? aL0 : aH0) + c * 64 + (size_t)r * H_DIM + q * 8;
            } else {
                int j = idx - 1536;
                int pp = j >> 10, rem = j & 1023;
                int r = rem >> 3, q = rem & 7;
                d = stg + 2 * S96_AP + pp * S96_BP + r * 144 + q * 16;
                const __nv_bfloat16* bsel = (pp == 0) ? wh : (pp == 1) ? wl
                                          : (pp == 2) ? xh : xl;
                g = bsel + c * 64 + (size_t)r * H_DIM + q * 8;
            }
            CP_ASYNC16(d, (const void*)g);
        }
    }
    CP_COMMIT();
}

__global__ void __launch_bounds__(384, 1)
clstm_seqf(const float* __restrict__ Gbase,
           const int* __restrict__ toks, const float* __restrict__ tab,
           const __nv_bfloat16* __restrict__ WhH, const __nv_bfloat16* __restrict__ WhL,
           const __nv_bfloat16* __restrict__ WxH, const __nv_bfloat16* __restrict__ WxL,
           const float* __restrict__ nbias, float* __restrict__ Gout,
           float* __restrict__ cst,
           __nv_bfloat16* __restrict__ Hh, __nv_bfloat16* __restrict__ Hl) {
    extern __shared__ char smem[];
    const uint32_t sb = smem_to_u32(smem);
    const int tid = threadIdx.x, lane = tid & 31, w = tid >> 5;
    const int cb = blockIdx.x;
    const size_t bm = (size_t)blockIdx.y * 96;
    const int m0 = (w >> 2) * 32, n0 = (w & 3) * 32;
    const int arow = (lane & 7) + ((lane & 8) ? 8 : 0);
    const int akq  = (lane & 16) ? 16 : 0;
    const int brow = (lane & 7) + ((lane & 16) ? 8 : 0);
    const int bkq  = (lane & 8) ? 16 : 0;
    const __nv_bfloat16* whs = WhH + (size_t)(cb * 128) * H_DIM;
    const __nv_bfloat16* wls = WhL + (size_t)(cb * 128) * H_DIM;
    const __nv_bfloat16* xhs = WxH + (size_t)(cb * 128) * H_DIM;
    const __nv_bfloat16* xls = WxL + (size_t)(cb * 128) * H_DIM;
    const int erow = tid >> 2, hb = (tid & 3) * 8;
    const size_t grow = bm + erow;
    const int hc0 = cb * 32 + hb;
    float* cp = cst + grow * H_DIM + hc0;
    float* gpre  = (float*)smem;              // gates 96x128 (stage0 region)
    float* cpre  = (float*)(smem + 49152);    // c 96x32
    float* stash = (float*)(smem + FSTAGE);   // stage1 region

    auto prefetch_gc = [&](int t) {
#pragma unroll
        for (int iq = 0; iq < 8; iq++) {
            int f = tid + iq * 384;
            int r = f >> 5, rem = f & 31;
            int g = rem >> 3, jj = (rem & 7) << 2;
            const float* rowp;
            int rr = (int)bm + r;
            if (toks) {
                int tk = __ldg(toks + ((rr >> 8) << 16) + ((rr & 255) << 8) + t);
                rowp = tab + (size_t)tk * G_COLS;
            } else {
                rowp = Gbase + (size_t)t * R_ROWS * G_COLS + (size_t)rr * G_COLS;
            }
            CP_ASYNC16(sb + (uint32_t)((r * 128 + g * 32 + jj) * 4),
                       (const void*)(rowp + g * H_DIM + cb * 32 + jj));
        }
        if (t > 0) {
#pragma unroll
            for (int iq = 0; iq < 2; iq++) {
                int f = tid + iq * 384;
                int r = f >> 3, jj = (f & 7) << 2;
                CP_ASYNC16(sb + 49152 + (uint32_t)((r * 32 + jj) * 4),
                           (const void*)(cst + (bm + r) * H_DIM + cb * 32 + jj));
            }
        }
        CP_COMMIT();
    };

#pragma unroll 1
    for (int i = 0; i <= 256; i++) {
        const int do_rec = (i >= 1) && (i <= 255);
        const int do_epi = (i <= 255);
        float racc[2][4][4], gacc[2][4][4];
#pragma unroll
        for (int mt = 0; mt < 2; mt++)
#pragma unroll
            for (int nt = 0; nt < 4; nt++)
#pragma unroll
                for (int e = 0; e < 4; e++) { racc[mt][nt][e] = 0.f; gacc[mt][nt][e] = 0.f; }

        if (i >= 1) {
            const __nv_bfloat16* aH0 = Hh + (size_t)(i - 1) * RH + bm * H_DIM;
            const __nv_bfloat16* aL0 = Hl + (size_t)(i - 1) * RH + bm * H_DIM;
            loadF_chunk(sb, tid, 0, 0, aH0, aL0, whs, wls, xhs, xls);
#pragma unroll 1
            for (int c = 0; c < 8; c++) {
                if (c < 7)      { loadF_chunk(sb, tid, c + 1, (c + 1) & 1,
                                              aH0, aL0, whs, wls, xhs, xls); CP_WAIT1(); }
                else if (do_epi) { prefetch_gc(i); CP_WAIT1(); }
                else             { CP_WAIT0(); }
                __syncthreads();
                uint32_t stg = sb + (uint32_t)(c & 1) * FSTAGE;
                uint32_t aH = stg, aL = stg + S96_AP;
                uint32_t bWh = stg + 2 * S96_AP, bWl = bWh + S96_BP;
                uint32_t bXh = bWl + S96_BP, bXl = bXh + S96_BP;
#pragma unroll
                for (int ks = 0; ks < 4; ks++) {
                    int kb = ks * 32;
                    uint32_t ah[2][4], al[2][4], bh[2][4], bl[2][4];
#pragma unroll
                    for (int mt = 0; mt < 2; mt++) {
                        ldmx4(ah[mt], aH + (m0 + mt * 16 + arow) * 144 + kb + akq);
                        ldmx4(al[mt], aL + (m0 + mt * 16 + arow) * 144 + kb + akq);
                    }
                    if (do_rec) {
#pragma unroll
                        for (int p = 0; p < 2; p++) {
                            ldmx4(bh[p], bWh + (n0 + p * 16 + brow) * 144 + kb + bkq);
                            ldmx4(bl[p], bWl + (n0 + p * 16 + brow) * 144 + kb + bkq);
                        }
#pragma unroll
                        for (int mt = 0; mt < 2; mt++)
#pragma unroll
                            for (int nt = 0; nt < 4; nt++)
                                mma_bf16(racc[mt][nt], ah[mt],
                                         bh[nt >> 1][(nt & 1) * 2], bh[nt >> 1][(nt & 1) * 2 + 1]);
#pragma unroll
                        for (int mt = 0; mt < 2; mt++)
#pragma unroll
                            for (int nt = 0; nt < 4; nt++)
                                mma_bf16(racc[mt][nt], ah[mt],
                                         bl[nt >> 1][(nt & 1) * 2], bl[nt >> 1][(nt & 1) * 2 + 1]);
#pragma unroll
                        for (int mt = 0; mt < 2; mt++)
#pragma unroll
                            for (int nt = 0; nt < 4; nt++)
                                mma_bf16(racc[mt][nt], al[mt],
                                         bh[nt >> 1][(nt & 1) * 2], bh[nt >> 1][(nt & 1) * 2 + 1]);
                    }
                    // gate plane (Wx_next)
#pragma unroll
                    for (int p = 0; p < 2; p++) {
                        ldmx4(bh[p], bXh + (n0 + p * 16 + brow) * 144 + kb + bkq);
                        ldmx4(bl[p], bXl + (n0 + p * 16 + brow) * 144 + kb + bkq);
                    }
#pragma unroll
                    for (int mt = 0; mt < 2; mt++)
#pragma unroll
                        for (int nt = 0; nt < 4; nt++)
                            mma_bf16(gacc[mt][nt], ah[mt],
                                     bh[nt >> 1][(nt & 1) * 2], bh[nt >> 1][(nt & 1) * 2 + 1]);
#pragma unroll
                    for (int mt = 0; mt < 2; mt++)
#pragma unroll
                        for (int nt = 0; nt < 4; nt++)
                            mma_bf16(gacc[mt][nt], ah[mt],
                                     bl[nt >> 1][(nt & 1) * 2], bl[nt >> 1][(nt & 1) * 2 + 1]);
#pragma unroll
                    for (int mt = 0; mt < 2; mt++)
#pragma unroll
                        for (int nt = 0; nt < 4; nt++)
                            mma_bf16(gacc[mt][nt], al[mt],
                                     bh[nt >> 1][(nt & 1) * 2], bh[nt >> 1][(nt & 1) * 2 + 1]);
                }
                __syncthreads();
            }
        } else {
            prefetch_gc(0);
        }

        if (do_epi) {
            CP_WAIT0();        // gates (+c) landed
            // stash recurrent acc
#pragma unroll
            for (int mt = 0; mt < 2; mt++)
#pragma unroll
                for (int nt = 0; nt < 4; nt++) {
                    int row = m0 + mt * 16 + (lane >> 2);
                    int col = n0 + nt * 8 + (lane & 3) * 2;
                    stash[row * 132 + col]     = racc[mt][nt][0];
                    stash[row * 132 + col + 1] = racc[mt][nt][1];
                    stash[(row + 8) * 132 + col]     = racc[mt][nt][2];
                    stash[(row + 8) * 132 + col + 1] = racc[mt][nt][3];
                }
            __syncthreads();

            __nv_bfloat16* hhp = Hh + (size_t)i * RH + grow * H_DIM + hc0;
            __nv_bfloat16* hlp = Hl + (size_t)i * RH + grow * H_DIM + hc0;
#pragma unroll
            for (int q = 0; q < 2; q++) {
                float4 gi = *(const float4*)(gpre + erow * 128 +       hb + q * 4);
                float4 gf = *(const float4*)(gpre + erow * 128 +  32 + hb + q * 4);
                float4 gg = *(const float4*)(gpre + erow * 128 +  64 + hb + q * 4);
                float4 go = *(const float4*)(gpre + erow * 128 +  96 + hb + q * 4);
                float4 co = make_float4(0.f, 0.f, 0.f, 0.f);
                if (i > 0) co = *(const float4*)(cpre + erow * 32 + hb + q * 4);
                float4 cv;
                __nv_bfloat16 bh4[4], bl4[4];
#pragma unroll
                for (int e = 0; e < 4; e++) {
                    int li = erow * 132 + hb + q * 4 + e;
                    float xi = stash[li]       + ((const float*)&gi)[e];
                    float xf = stash[li + 32]  + ((const float*)&gf)[e];
                    float xg = stash[li + 64]  + ((const float*)&gg)[e];
                    float xo = stash[li + 96]  + ((const float*)&go)[e];
                    float I = 1.f / (1.f + __expf(-xi));
                    float F = 1.f / (1.f + __expf(-xf));
                    float Gv = tanhf(xg);
                    float O = 1.f / (1.f + __expf(-xo));
                    float cn = F * ((const float*)&co)[e] + I * Gv;
                    float hn = O * tanhf(cn);
                    ((float*)&cv)[e] = cn;
                    bh4[e] = __float2bfloat16(hn);
                    bl4[e] = __float2bfloat16(hn - __bfloat162float(bh4[e]));
                }
                *(float4*)(cp + q * 4) = cv;
                __nv_bfloat162 p0; p0.x = bh4[0]; p0.y = bh4[1];
                __nv_bfloat162 p1; p1.x = bh4[2]; p1.y = bh4[3];
                __nv_bfloat162 q0; q0.x = bl4[0]; q0.y = bl4[1];
                __nv_bfloat162 q1; q1.x = bl4[2]; q1.y = bl4[3];
                *(__nv_bfloat162*)(hhp + q * 4)     = p0;
                *(__nv_bfloat162*)(hhp + q * 4 + 2) = p1;
                *(__nv_bfloat162*)(hlp + q * 4)     = q0;
                *(__nv_bfloat162*)(hlp + q * 4 + 2) = q1;
            }
            __syncthreads();
        }

        if (i >= 1) {
            // stash gate acc, then coalesced write of G_next[i-1] with bias
#pragma unroll
            for (int mt = 0; mt < 2; mt++)
#pragma unroll
                for (int nt = 0; nt < 4; nt++) {
                    int row = m0 + mt * 16 + (lane >> 2);
                    int col = n0 + nt * 8 + (lane & 3) * 2;
                    stash[row * 132 + col]     = gacc[mt][nt][0];
                    stash[row * 132 + col + 1] = gacc[mt][nt][1];
                    stash[(row + 8) * 132 + col]     = gacc[mt][nt][2];
                    stash[(row + 8) * 132 + col + 1] = gacc[mt][nt][3];
                }
            __syncthreads();
            int row = tid >> 2, c0 = (tid & 3) * 32;
            float* gp = Gout + ((size_t)(i - 1) * R_ROWS + bm + row) * G_COLS + cb * 128;
#pragma unroll
            for (int q = 0; q < 8; q++) {
                int col = c0 + q * 4;
                float4 v = *(float4*)(stash + row * 132 + col);
                float4 bv = *(const float4*)(nbias + cb * 128 + col);
                v.x += bv.x; v.y += bv.y; v.z += bv.z; v.w += bv.w;
                *(float4*)(gp + col) = v;
            }
        }

        if (do_epi) grid_bar_local(blockIdx.y);
    }
}

// ---------------- head kernels -------------------------------------------------
__global__ void clstm_gather_r(const __nv_bfloat16* __restrict__ Hhi,
                               const __nv_bfloat16* __restrict__ Hlo,
                               float* __restrict__ r) {
    int b = blockIdx.x, i = blockIdx.y, h = threadIdx.x;
    size_t idx = ((size_t)(T_LEN - 1) * R_ROWS + i * B_SZ + b) * H_DIM + h;
    r[(size_t)b * 1536 + i * H_DIM + h] =
        __bfloat162float(Hhi[idx]) + __bfloat162float(Hlo[idx]);
}

__global__ void clstm_bn(float* __restrict__ x, const float* __restrict__ gamma,
                         const float* __restrict__ beta, int N) {
    __shared__ float s1[256], s2[256];
    int col = blockIdx.x;
    float v = x[(size_t)threadIdx.x * N + col];
    s1[threadIdx.x] = v; s2[threadIdx.x] = v * v;
    __syncthreads();
    for (int s = 128; s > 0; s >>= 1) {
        if (threadIdx.x < s) {
            s1[threadIdx.x] += s1[threadIdx.x + s];
            s2[threadIdx.x] += s2[threadIdx.x + s];
        }
        __syncthreads();
    }
    float m = s1[0] * (1.f / 256.f);
    float var = s2[0] * (1.f / 256.f) - m * m;
    float inv = rsqrtf(var + 1e-3f);
    x[(size_t)threadIdx.x * N + col] = gamma[col] * (v - m) * inv + beta[col];
}

__global__ void clstm_gemm_head(const float* __restrict__ A, const float* __restrict__ W,
                                const float* __restrict__ bias, float* __restrict__ C,
                                int K, int N, int act) {
    int n = blockIdx.x * 128 + threadIdx.x;
    int m0 = blockIdx.y * 16;
    if (n >= N) return;
    float s[16];
#pragma unroll
    for (int mm = 0; mm < 16; mm++) s[mm] = bias[n];
    for (int k = 0; k < K; k++) {
        float w = W[(size_t)k * N + n];
#pragma unroll
        for (int mm = 0; mm < 16; mm++)
            s[mm] += A[(size_t)(m0 + mm) * K + k] * w;
    }
    const float alpha = 1.6732632423543772f, scale = 1.0507009873554805f;
#pragma unroll
    for (int mm = 0; mm < 16; mm++) {
        float v = s[mm];
        if (act) v = scale * (v > 0.f ? v : alpha * expm1f(v));
        C[(size_t)(m0 + mm) * N + n] = v;
    }
}

// ---------------- launch --------------------------------------------------------
extern "C" void kernel_launch(void* const* d_in, const int* in_sizes, int n_in,
                              void* d_out, int out_size) {
    const int* t1 = (const int*)d_in[0];
    const int* t2 = (const int*)d_in[1];
    const int* t3 = (const int*)d_in[2];
    const float* emb = (const float*)d_in[3];
    const float* Wx = (const float*)d_in[4];
    const float* Wh = (const float*)d_in[5];
    const float* bb = (const float*)d_in[6];
    const float* g1 = (const float*)d_in[7];
    const float* be1 = (const float*)d_in[8];
    const float* W1 = (const float*)d_in[9];
    const float* bd1 = (const float*)d_in[10];
    const float* g2 = (const float*)d_in[11];
    const float* be2 = (const float*)d_in[12];
    const float* W2 = (const float*)d_in[13];
    const float* bd2 = (const float*)d_in[14];
    const float* g3 = (const float*)d_in[15];
    const float* be3 = (const float*)d_in[16];
    const float* W3 = (const float*)d_in[17];
    const float* bd3 = (const float*)d_in[18];
    float* out = (float*)d_out;

    float *G, *TAB, *C, *R, *H1, *H2;
    int* TOK;
    __nv_bfloat16 *Eh, *El, *WhPh, *WhPl, *WxTh, *WxTl, *sAh, *sAl, *sBh, *sBl;
    cudaGetSymbolAddress((void**)&G, d_Gbuf);
    cudaGetSymbolAddress((void**)&TAB, d_tab);
    cudaGetSymbolAddress((void**)&C, d_cst);
    cudaGetSymbolAddress((void**)&R, d_rbuf);
    cudaGetSymbolAddress((void**)&H1, d_h1buf);
    cudaGetSymbolAddress((void**)&H2, d_h2buf);
    cudaGetSymbolAddress((void**)&TOK, d_toks);
    cudaGetSymbolAddress((void**)&Eh, d_Ehi);
    cudaGetSymbolAddress((void**)&El, d_Elo);
    cudaGetSymbolAddress((void**)&WhPh, d_WhPhi);
    cudaGetSymbolAddress((void**)&WhPl, d_WhPlo);
    cudaGetSymbolAddress((void**)&WxTh, d_WxThi);
    cudaGetSymbolAddress((void**)&WxTl, d_WxTlo);
    cudaGetSymbolAddress((void**)&sAh, d_sAhi);
    cudaGetSymbolAddress((void**)&sAl, d_sAlo);
    cudaGetSymbolAddress((void**)&sBh, d_sBhi);
    cudaGetSymbolAddress((void**)&sBl, d_sBlo);

    cudaFuncSetAttribute(clstm_gemm_mma, cudaFuncAttributeMaxDynamicSharedMemorySize,
                         MMA_SMEM);
    cudaFuncSetAttribute(clstm_seq96, cudaFuncAttributeMaxDynamicSharedMemorySize,
                         SEQ_SMEM);
    cudaFuncSetAttribute(clstm_seqf, cudaFuncAttributeMaxDynamicSharedMemorySize,
                         SEQF_SMEM);

    // preprocessing
    cudaMemcpyAsync(TOK,          t1, 65536 * sizeof(int), cudaMemcpyDeviceToDevice, 0);
    cudaMemcpyAsync(TOK + 65536,  t2, 65536 * sizeof(int), cudaMemcpyDeviceToDevice, 0);
    cudaMemcpyAsync(TOK + 131072, t3, 65536 * sizeof(int), cudaMemcpyDeviceToDevice, 0);
    clstm_splitemb<<<V_SZ, 128>>>(emb, Eh, El);
    clstm_makeWsplit<<<dim3(64, 16, 3), dim3(32, 8)>>>(Wh, WhPh, WhPl, 1);
    clstm_makeWsplit<<<dim3(64, 16, 3), dim3(32, 8)>>>(Wx, WxTh, WxTl, 0);
    // vocab gate table: tab = emb @ Wx0 + b0   [32000, 2048]
    clstm_gemm_mma<<<dim3(16, V_SZ / 64), 256, MMA_SMEM>>>(
        Eh, El, WxTh, WxTl, bb, TAB);

    const size_t woff = (size_t)G_COLS * H_DIM;
    // layer 1 (fused): gates from tab[token]; h1 -> sB; G2 gates -> G
    clstm_seqf<<<dim3(16, 8), 384, SEQF_SMEM>>>(
        (const float*)0, TOK, TAB, WhPh, WhPl,
        WxTh + woff, WxTl + woff, bb + G_COLS, G, C, sBh, sBl);
    // layer 2 (fused, G in-place): reads G2 gates from G[t], writes G3 gates to G[t-1]
    clstm_seqf<<<dim3(16, 8), 384, SEQF_SMEM>>>(
        G, (const int*)0, (const float*)0, WhPh + woff, WhPl + woff,
        WxTh + 2 * woff, WxTl + 2 * woff, bb + 2 * G_COLS, G, C, sAh, sAl);
    // layer 3 (plain): gates from G; h3 -> sB
    clstm_seq96<<<dim3(16, 8), 384, SEQ_SMEM>>>(
        G, (const int*)0, (const float*)0,
        WhPh + 2 * woff, WhPl + 2 * woff, C, sBh, sBl);

    // head
    clstm_gather_r<<<dim3(B_SZ, 3), H_DIM>>>(sBh, sBl, R);
    clstm_bn<<<1536, 256>>>(R, g1, be1, 1536);
    clstm_gemm_head<<<dim3(8, 16), 128>>>(R, W1, bd1, H1, 1536, 1024, 1);
    clstm_bn<<<1024, 256>>>(H1, g2, be2, 1024);
    clstm_gemm_head<<<dim3(1, 16), 128>>>(H1, W2, bd2, H2, 1024, H5, 1);
    clstm_bn<<<H5, 256>>>(H2, g3, be3, H5);
    clstm_gemm_head<<<dim3(1, 16), 128>>>(H2, W3, bd3, out, H5, 4, 0);
}

// round 15
// speedup vs baseline: 1.0772x; 1.0207x over previous
#include <cuda_runtime.h>
#include <cuda_bf16.h>
#include <math.h>
#include <stdint.h>
#include <stddef.h>

#define T_LEN 256
#define B_SZ  256
#define H_DIM 512
#define R_ROWS 768
#define G_COLS 2048
#define M_ALL  196608
#define V_SZ   32000
#define H5 102
#define RH 393216            // R_ROWS * H_DIM

// ---------------- static device scratch --------------------------------------
// Single G buffer; fused kernel reads gates[t] and overwrites gates[t-1] in
// place (slot t read at iter t, overwritten at iter t+1, ordered by the
// per-group barrier). Keeps .bss < 4GB (AArch64 reloc limit).
__device__ float d_Gbuf[402653184];   // [T][768][2048]
__device__ float d_tab[65536000];     // [32000][2048] emb@Wx0 + b0
__device__ float d_cst[393216];
__device__ float d_rbuf[393216];
__device__ float d_h1buf[262144];
__device__ float d_h2buf[26112];
__device__ int   d_toks[196608];      // [3][256][256]
__device__ unsigned d_barGenL[256];   // 8 groups, stride 32
__device__ unsigned d_barCntL[256];
__device__ __nv_bfloat16 d_Ehi[16384000];           // emb split [32000][512]
__device__ __nv_bfloat16 d_Elo[16384000];
__device__ __nv_bfloat16 d_WhPhi[3 * 2048 * 512];   // Wh permuted [n'][k] hi
__device__ __nv_bfloat16 d_WhPlo[3 * 2048 * 512];
__device__ __nv_bfloat16 d_WxThi[3 * 2048 * 512];   // Wx transposed [n][k] hi
__device__ __nv_bfloat16 d_WxTlo[3 * 2048 * 512];
__device__ __nv_bfloat16 d_sAhi[100663296];         // h seq splits (ping)
__device__ __nv_bfloat16 d_sAlo[100663296];
__device__ __nv_bfloat16 d_sBhi[100663296];         // (pong)
__device__ __nv_bfloat16 d_sBlo[100663296];

// ---------------- helpers ------------------------------------------------------
__device__ __forceinline__ uint32_t smem_to_u32(const void* p) {
    uint32_t a;
    asm("{ .reg .u64 t; cvta.to.shared.u64 t, %1; cvt.u32.u64 %0, t; }"
        : "=r"(a) : "l"(p));
    return a;
}
__device__ __forceinline__ void ldmx4(uint32_t* r, uint32_t addr) {
    asm volatile("ldmatrix.sync.aligned.m8n8.x4.shared.b16 {%0,%1,%2,%3}, [%4];"
                 : "=r"(r[0]), "=r"(r[1]), "=r"(r[2]), "=r"(r[3]) : "r"(addr));
}
__device__ __forceinline__ void mma_bf16(float* c, const uint32_t* a,
                                         uint32_t b0, uint32_t b1) {
    asm volatile(
        "mma.sync.aligned.m16n8k16.row.col.f32.bf16.bf16.f32 "
        "{%0,%1,%2,%3}, {%4,%5,%6,%7}, {%8,%9}, {%0,%1,%2,%3};"
        : "+f"(c[0]), "+f"(c[1]), "+f"(c[2]), "+f"(c[3])
        : "r"(a[0]), "r"(a[1]), "r"(a[2]), "r"(a[3]), "r"(b0), "r"(b1));
}
// fast activations: __expf-based (saturates correctly at +/-inf)
__device__ __forceinline__ float fsig(float x) {
    return __fdividef(1.f, 1.f + __expf(-x));
}
__device__ __forceinline__ float ftanh(float x) {
    return 1.f - __fdividef(2.f, __expf(2.f * x) + 1.f);
}
#define CP_ASYNC16(dst, src) \
    asm volatile("cp.async.cg.shared.global [%0], [%1], 16;" :: "r"(dst), "l"(src))
#define CP_COMMIT()  asm volatile("cp.async.commit_group;" ::: "memory")
#define CP_WAIT0()   asm volatile("cp.async.wait_group 0;" ::: "memory")
#define CP_WAIT1()   asm volatile("cp.async.wait_group 1;" ::: "memory")

// ---- 64-row kernel smem (vocab table GEMM) ----
#define STAGE_B 55296
#define MMA_SMEM 110592
// ---- 96-row plain seq kernel ----
#define S96_AP 13824          // 96*144
#define S96_BP 18432          // 128*144
#define S96_STAGE 64512       // 2*AP + 2*BP
#define GOFF 129024           // gates prefetch (96*128 f32)
#define COFF 178176           // c prefetch (96*32 f32)
#define SEQ_SMEM 190464
// ---- fused seq kernel: stage = 2*AP + 4*BP ----
#define FSTAGE 101376
#define GSMF 12672            // floats per stash half (96*132)
#define SEQF_SMEM 202752      // 2 stages; gates/c prefetch reuses stage0 region

// ---------------- emb -> bf16 split ---------------------------------------------
__global__ void clstm_splitemb(const float* __restrict__ emb,
                               __nv_bfloat16* __restrict__ Ehi,
                               __nv_bfloat16* __restrict__ Elo) {
    size_t base = (size_t)blockIdx.x * H_DIM + threadIdx.x * 4;
    float4 v = *(const float4*)(emb + base);
    float vv[4] = { v.x, v.y, v.z, v.w };
#pragma unroll
    for (int e = 0; e < 4; e++) {
        __nv_bfloat16 h = __float2bfloat16(vv[e]);
        Ehi[base + e] = h;
        Elo[base + e] = __float2bfloat16(vv[e] - __bfloat162float(h));
    }
}

// ---------------- W [k][n] -> [n'][k] bf16 split (optional gate permute) --------
__global__ void clstm_makeWsplit(const float* __restrict__ W,
                                 __nv_bfloat16* __restrict__ Phi,
                                 __nv_bfloat16* __restrict__ Plo, int permute) {
    __shared__ float tile[32][33];
    int n0 = blockIdx.x * 32, k0 = blockIdx.y * 32, l = blockIdx.z;
    const float* Wl = W + (size_t)l * H_DIM * G_COLS;
    int tx = threadIdx.x, ty = threadIdx.y;
#pragma unroll
    for (int it = 0; it < 4; it++)
        tile[ty + it * 8][tx] = Wl[(size_t)(k0 + ty + it * 8) * G_COLS + n0 + tx];
    __syncthreads();
    int s = n0 >> 9, cbb = (n0 >> 5) & 15;
    int np0 = permute ? (cbb * 128 + s * 32) : n0;
    __nv_bfloat16* ph = Phi + (size_t)l * G_COLS * H_DIM;
    __nv_bfloat16* pl = Plo + (size_t)l * G_COLS * H_DIM;
#pragma unroll
    for (int it = 0; it < 4; it++) {
        int nn = ty + it * 8;
        float v = tile[tx][nn];
        __nv_bfloat16 hi = __float2bfloat16(v);
        __nv_bfloat16 lo = __float2bfloat16(v - __bfloat162float(hi));
        ph[(size_t)(np0 + nn) * H_DIM + k0 + tx] = hi;
        pl[(size_t)(np0 + nn) * H_DIM + k0 + tx] = lo;
    }
}

// ---------------- HMMA 64-row GEMM (vocab table only) ---------------------------
__global__ void __launch_bounds__(256, 2)
clstm_gemm_mma(const __nv_bfloat16* __restrict__ Ahi, const __nv_bfloat16* __restrict__ Alo,
               const __nv_bfloat16* __restrict__ Bhi, const __nv_bfloat16* __restrict__ Blo,
               const float* __restrict__ bias, float* __restrict__ G) {
    extern __shared__ char smem[];
    const uint32_t sb = smem_to_u32(smem);
    const int tid = threadIdx.x, lane = tid & 31, w = tid >> 5;
    const int cb = blockIdx.x;
    const size_t bm = (size_t)blockIdx.y * 64;
    const __nv_bfloat16* asrc[2] = { Ahi + bm * H_DIM, Alo + bm * H_DIM };
    const __nv_bfloat16* bsrc[2] = { Bhi + (size_t)(cb * 128) * H_DIM,
                                     Blo + (size_t)(cb * 128) * H_DIM };
    const int lr = tid >> 3, lq = tid & 7;

    auto load_chunk = [&](int c, int s) {
        uint32_t stg = sb + (uint32_t)s * STAGE_B;
#pragma unroll
        for (int p = 0; p < 2; p++) {
            const __nv_bfloat16* gb = asrc[p] + c * 64;
            uint32_t sd = stg + p * 9216;
#pragma unroll
            for (int i = 0; i < 2; i++) {
                int r = lr + i * 32;
                CP_ASYNC16(sd + r * 144 + lq * 16,
                           (const void*)(gb + (size_t)r * H_DIM + lq * 8));
            }
        }
#pragma unroll
        for (int p = 0; p < 2; p++) {
            const __nv_bfloat16* gb = bsrc[p] + c * 64;
            uint32_t sd = stg + 18432 + p * 18432;
#pragma unroll
            for (int i = 0; i < 4; i++) {
                int r = lr + i * 32;
                CP_ASYNC16(sd + r * 144 + lq * 16,
                           (const void*)(gb + (size_t)r * H_DIM + lq * 8));
            }
        }
        CP_COMMIT();
    };

    const int m0 = (w >> 1) * 16, n0 = (w & 1) * 64;
    const int arow = (lane & 7) + ((lane & 8) ? 8 : 0);
    const int akq  = (lane & 16) ? 16 : 0;
    const int brow = (lane & 7) + ((lane & 16) ? 8 : 0);
    const int bkq  = (lane & 8) ? 16 : 0;

    float acc[8][4];
#pragma unroll
    for (int nt = 0; nt < 8; nt++)
#pragma unroll
        for (int e = 0; e < 4; e++) acc[nt][e] = 0.f;

    load_chunk(0, 0);
    for (int c = 0; c < 8; c++) {
        if (c < 7) { load_chunk(c + 1, (c + 1) & 1); CP_WAIT1(); }
        else       { CP_WAIT0(); }
        __syncthreads();
        uint32_t stg = sb + (uint32_t)(c & 1) * STAGE_B;
        uint32_t aH = stg, aL = stg + 9216, bH = stg + 18432, bL = stg + 36864;
#pragma unroll
        for (int ks = 0; ks < 4; ks++) {
            int kb = ks * 32;
            uint32_t ah[4], al[4], bh[4][4], bl[4][4];
            ldmx4(ah, aH + (m0 + arow) * 144 + kb + akq);
            ldmx4(al, aL + (m0 + arow) * 144 + kb + akq);
#pragma unroll
            for (int p = 0; p < 4; p++) {
                ldmx4(bh[p], bH + (n0 + p * 16 + brow) * 144 + kb + bkq);
                ldmx4(bl[p], bL + (n0 + p * 16 + brow) * 144 + kb + bkq);
            }
#pragma unroll
            for (int nt = 0; nt < 8; nt++)
                mma_bf16(acc[nt], ah, bh[nt >> 1][(nt & 1) * 2], bh[nt >> 1][(nt & 1) * 2 + 1]);
#pragma unroll
            for (int nt = 0; nt < 8; nt++)
                mma_bf16(acc[nt], ah, bl[nt >> 1][(nt & 1) * 2], bl[nt >> 1][(nt & 1) * 2 + 1]);
#pragma unroll
            for (int nt = 0; nt < 8; nt++)
                mma_bf16(acc[nt], al, bh[nt >> 1][(nt & 1) * 2], bh[nt >> 1][(nt & 1) * 2 + 1]);
        }
        __syncthreads();
    }

    float* gsm = (float*)smem;     // [64][132]
#pragma unroll
    for (int nt = 0; nt < 8; nt++) {
        int row = m0 + (lane >> 2);
        int col = n0 + nt * 8 + (lane & 3) * 2;
        gsm[row * 132 + col]     = acc[nt][0];
        gsm[row * 132 + col + 1] = acc[nt][1];
        gsm[(row + 8) * 132 + col]     = acc[nt][2];
        gsm[(row + 8) * 132 + col + 1] = acc[nt][3];
    }
    __syncthreads();

    int row = tid >> 2, c0 = (tid & 3) * 32;
    float* gp = G + (bm + row) * G_COLS + cb * 128;
#pragma unroll
    for (int q = 0; q < 8; q++) {
        int col = c0 + q * 4;
        float4 v = *(float4*)(gsm + row * 132 + col);
        float4 bv = *(const float4*)(bias + cb * 128 + col);
        v.x += bv.x; v.y += bv.y; v.z += bv.z; v.w += bv.w;
        *(float4*)(gp + col) = v;
    }
}

// ---------------- row-block-local barrier (16 CTAs per group) --------------------
__device__ __forceinline__ void grid_bar_local(int grp) {
    __syncthreads();
    if (threadIdx.x == 0) {
        unsigned* genp = &d_barGenL[grp * 32];
        unsigned* cntp = &d_barCntL[grp * 32];
        unsigned g;
        asm volatile("ld.acquire.gpu.u32 %0, [%1];" : "=r"(g) : "l"(genp));
        unsigned a;
        asm volatile("atom.acq_rel.gpu.add.u32 %0, [%1], 1;"
                     : "=r"(a) : "l"(cntp) : "memory");
        if (a == 15u) {
            asm volatile("st.relaxed.gpu.u32 [%0], 0;" :: "l"(cntp) : "memory");
            asm volatile("red.release.gpu.add.u32 [%0], 1;" :: "l"(genp) : "memory");
        } else {
            unsigned cur;
            do {
                asm volatile("nanosleep.u32 64;");
                asm volatile("ld.acquire.gpu.u32 %0, [%1];" : "=r"(cur) : "l"(genp));
            } while (cur == g);
        }
    }
    __syncthreads();
}

// ---------------- plain 96-row seq (layer 3) -------------------------------------
__device__ __forceinline__ void load96_chunk(
    uint32_t sb, int tid, int c, int s,
    const __nv_bfloat16* __restrict__ aH0, const __nv_bfloat16* __restrict__ aL0,
    const __nv_bfloat16* __restrict__ bH0, const __nv_bfloat16* __restrict__ bL0)
{
    uint32_t stg = sb + (uint32_t)s * S96_STAGE;
#pragma unroll
    for (int i = 0; i < 10; i++) {
        int idx = tid + i * 384;
        if (idx < 3584) {
            uint32_t d; const __nv_bfloat16* g;
            if (idx < 1536) {
                int p = idx >= 768, rem = idx - p * 768;
                int r = rem >> 3, q = rem & 7;
                d = stg + p * S96_AP + r * 144 + q * 16;
                g = (p ? aL0 : aH0) + c * 64 + (size_t)r * H_DIM + q * 8;
            } else {
                int j = idx - 1536;
                int p = j >= 1024, rem = j - p * 1024;
                int r = rem >> 3, q = rem & 7;
                d = stg + 2 * S96_AP + p * S96_BP + r * 144 + q * 16;
                g = (p ? bL0 : bH0) + c * 64 + (size_t)r * H_DIM + q * 8;
            }
            CP_ASYNC16(d, (const void*)g);
        }
    }
    CP_COMMIT();
}

__device__ __forceinline__ void mma_tile96(
    uint32_t sb, int tid, int m0, int n0,
    int arow, int akq, int brow, int bkq,
    const __nv_bfloat16* __restrict__ aH0, const __nv_bfloat16* __restrict__ aL0,
    const __nv_bfloat16* __restrict__ bH0, const __nv_bfloat16* __restrict__ bL0,
    float acc[2][4][4])
{
    load96_chunk(sb, tid, 0, 0, aH0, aL0, bH0, bL0);
#pragma unroll 1
    for (int c = 0; c < 8; c++) {
        if (c < 7) { load96_chunk(sb, tid, c + 1, (c + 1) & 1, aH0, aL0, bH0, bL0); CP_WAIT1(); }
        else       { CP_WAIT0(); }
        __syncthreads();
        uint32_t stg = sb + (uint32_t)(c & 1) * S96_STAGE;
        uint32_t aH = stg, aL = stg + S96_AP;
        uint32_t bH = stg + 2 * S96_AP, bL = bH + S96_BP;
#pragma unroll
        for (int ks = 0; ks < 4; ks++) {
            int kb = ks * 32;
            uint32_t ah[2][4], al[2][4], bh[2][4], bl[2][4];
#pragma unroll
            for (int mt = 0; mt < 2; mt++) {
                ldmx4(ah[mt], aH + (m0 + mt * 16 + arow) * 144 + kb + akq);
                ldmx4(al[mt], aL + (m0 + mt * 16 + arow) * 144 + kb + akq);
            }
#pragma unroll
            for (int p = 0; p < 2; p++) {
                ldmx4(bh[p], bH + (n0 + p * 16 + brow) * 144 + kb + bkq);
                ldmx4(bl[p], bL + (n0 + p * 16 + brow) * 144 + kb + bkq);
            }
#pragma unroll
            for (int mt = 0; mt < 2; mt++)
#pragma unroll
                for (int nt = 0; nt < 4; nt++)
                    mma_bf16(acc[mt][nt], ah[mt],
                             bh[nt >> 1][(nt & 1) * 2], bh[nt >> 1][(nt & 1) * 2 + 1]);
#pragma unroll
            for (int mt = 0; mt < 2; mt++)
#pragma unroll
                for (int nt = 0; nt < 4; nt++)
                    mma_bf16(acc[mt][nt], ah[mt],
                             bl[nt >> 1][(nt & 1) * 2], bl[nt >> 1][(nt & 1) * 2 + 1]);
#pragma unroll
            for (int mt = 0; mt < 2; mt++)
#pragma unroll
                for (int nt = 0; nt < 4; nt++)
                    mma_bf16(acc[mt][nt], al[mt],
                             bh[nt >> 1][(nt & 1) * 2], bh[nt >> 1][(nt & 1) * 2 + 1]);
        }
        __syncthreads();
    }
}

__global__ void __launch_bounds__(384, 1)
clstm_seq96(const float* __restrict__ Gbase,
            const int* __restrict__ toks, const float* __restrict__ tab,
            const __nv_bfloat16* __restrict__ WhH, const __nv_bfloat16* __restrict__ WhL,
            float* __restrict__ cst,
            __nv_bfloat16* __restrict__ Hh, __nv_bfloat16* __restrict__ Hl) {
    extern __shared__ char smem[];
    const uint32_t sb = smem_to_u32(smem);
    const int tid = threadIdx.x, lane = tid & 31, w = tid >> 5;
    const int cb = blockIdx.x;
    const size_t bm = (size_t)blockIdx.y * 96;
    const int m0 = (w >> 2) * 32, n0 = (w & 3) * 32;
    const int arow = (lane & 7) + ((lane & 8) ? 8 : 0);
    const int akq  = (lane & 16) ? 16 : 0;
    const int brow = (lane & 7) + ((lane & 16) ? 8 : 0);
    const int bkq  = (lane & 8) ? 16 : 0;
    const __nv_bfloat16* bH0 = WhH + (size_t)(cb * 128) * H_DIM;
    const __nv_bfloat16* bL0 = WhL + (size_t)(cb * 128) * H_DIM;
    const int erow = tid >> 2, hb = (tid & 3) * 8;
    const size_t grow = bm + erow;
    const int hc0 = cb * 32 + hb;
    float* cp = cst + grow * H_DIM + hc0;
    float* gsm = (float*)smem;
    const float* gsm2 = (const float*)(smem + GOFF);
    const float* csm  = (const float*)(smem + COFF);

#pragma unroll 1
    for (int t = 0; t < T_LEN; t++) {
        {
#pragma unroll
            for (int i = 0; i < 8; i++) {
                int f = tid + i * 384;
                int r = f >> 5, rem = f & 31;
                int g = rem >> 3, jj = (rem & 7) << 2;
                const float* rowp;
                int rr = (int)bm + r;
                if (toks) {
                    int tk = __ldg(toks + ((rr >> 8) << 16) + ((rr & 255) << 8) + t);
                    rowp = tab + (size_t)tk * G_COLS;
                } else {
                    rowp = Gbase + (size_t)t * R_ROWS * G_COLS + (size_t)rr * G_COLS;
                }
                CP_ASYNC16(sb + GOFF + (uint32_t)((r * 128 + g * 32 + jj) * 4),
                           (const void*)(rowp + g * H_DIM + cb * 32 + jj));
            }
            if (t > 0) {
#pragma unroll
                for (int i = 0; i < 2; i++) {
                    int f = tid + i * 384;
                    int r = f >> 3, jj = (f & 7) << 2;
                    CP_ASYNC16(sb + COFF + (uint32_t)((r * 32 + jj) * 4),
                               (const void*)(cst + (bm + r) * H_DIM + cb * 32 + jj));
                }
            }
            CP_COMMIT();
        }

        float acc[2][4][4];
#pragma unroll
        for (int mt = 0; mt < 2; mt++)
#pragma unroll
            for (int nt = 0; nt < 4; nt++)
#pragma unroll
                for (int e = 0; e < 4; e++) acc[mt][nt][e] = 0.f;

        if (t > 0) {
            const __nv_bfloat16* aH0 = Hh + (size_t)(t - 1) * RH + bm * H_DIM;
            const __nv_bfloat16* aL0 = Hl + (size_t)(t - 1) * RH + bm * H_DIM;
            mma_tile96(sb, tid, m0, n0, arow, akq, brow, bkq, aH0, aL0, bH0, bL0, acc);
        } else {
            CP_WAIT0();
            __syncthreads();
        }

#pragma unroll
        for (int mt = 0; mt < 2; mt++)
#pragma unroll
            for (int nt = 0; nt < 4; nt++) {
                int row = m0 + mt * 16 + (lane >> 2);
                int col = n0 + nt * 8 + (lane & 3) * 2;
                gsm[row * 132 + col]     = acc[mt][nt][0];
                gsm[row * 132 + col + 1] = acc[mt][nt][1];
                gsm[(row + 8) * 132 + col]     = acc[mt][nt][2];
                gsm[(row + 8) * 132 + col + 1] = acc[mt][nt][3];
            }
        __syncthreads();

        __nv_bfloat16* hhp = Hh + (size_t)t * RH + grow * H_DIM + hc0;
        __nv_bfloat16* hlp = Hl + (size_t)t * RH + grow * H_DIM + hc0;
#pragma unroll
        for (int q = 0; q < 2; q++) {
            float4 gi = *(const float4*)(gsm2 + erow * 128 +       hb + q * 4);
            float4 gf = *(const float4*)(gsm2 + erow * 128 +  32 + hb + q * 4);
            float4 gg = *(const float4*)(gsm2 + erow * 128 +  64 + hb + q * 4);
            float4 go = *(const float4*)(gsm2 + erow * 128 +  96 + hb + q * 4);
            float4 co = make_float4(0.f, 0.f, 0.f, 0.f);
            if (t > 0) co = *(const float4*)(csm + erow * 32 + hb + q * 4);
            float4 cv;
            __nv_bfloat16 bh4[4], bl4[4];
#pragma unroll
            for (int e = 0; e < 4; e++) {
                int li = erow * 132 + hb + q * 4 + e;
                float xi = gsm[li]       + ((const float*)&gi)[e];
                float xf = gsm[li + 32]  + ((const float*)&gf)[e];
                float xg = gsm[li + 64]  + ((const float*)&gg)[e];
                float xo = gsm[li + 96]  + ((const float*)&go)[e];
                float I = fsig(xi);
                float F = fsig(xf);
                float Gv = ftanh(xg);
                float O = fsig(xo);
                float cn = F * ((const float*)&co)[e] + I * Gv;
                float hn = O * ftanh(cn);
                ((float*)&cv)[e] = cn;
                bh4[e] = __float2bfloat16(hn);
                bl4[e] = __float2bfloat16(hn - __bfloat162float(bh4[e]));
            }
            *(float4*)(cp + q * 4) = cv;
            __nv_bfloat162 p0; p0.x = bh4[0]; p0.y = bh4[1];
            __nv_bfloat162 p1; p1.x = bh4[2]; p1.y = bh4[3];
            __nv_bfloat162 q0; q0.x = bl4[0]; q0.y = bl4[1];
            __nv_bfloat162 q1; q1.x = bl4[2]; q1.y = bl4[3];
            *(__nv_bfloat162*)(hhp + q * 4)     = p0;
            *(__nv_bfloat162*)(hhp + q * 4 + 2) = p1;
            *(__nv_bfloat162*)(hlp + q * 4)     = q0;
            *(__nv_bfloat162*)(hlp + q * 4 + 2) = q1;
        }
        grid_bar_local(blockIdx.y);
    }
}

// ---------------- FUSED seq: recurrence + next-layer gate GEMM -------------------
// Per iteration i (A = h[i-1], staged once): recurrent gates for step i AND
// G_next[i-1] = h[i-1]@Wx_next + nbias. Iteration 256 finishes G_next[255].
// Gout may alias Gbase (slot i read at iter i, overwritten at iter i+1).
__device__ __forceinline__ void loadF_chunk(
    uint32_t sb, int tid, int c, int s,
    const __nv_bfloat16* __restrict__ aH0, const __nv_bfloat16* __restrict__ aL0,
    const __nv_bfloat16* __restrict__ wh, const __nv_bfloat16* __restrict__ wl,
    const __nv_bfloat16* __restrict__ xh, const __nv_bfloat16* __restrict__ xl)
{
    uint32_t stg = sb + (uint32_t)s * FSTAGE;
#pragma unroll
    for (int i = 0; i < 15; i++) {
        int idx = tid + i * 384;
        if (idx < 5632) {
            uint32_t d; const __nv_bfloat16* g;
            if (idx < 1536) {
                int p = idx >= 768, rem = idx - p * 768;
                int r = rem >> 3, q = rem & 7;
                d = stg + p * S96_AP + r * 144 + q * 16;
                g = (p ? aL0 : aH0) + c * 64 + (size_t)r * H_DIM + q * 8;
            } else {
                int j = idx - 1536;
                int pp = j >> 10, rem = j & 1023;
                int r = rem >> 3, q = rem & 7;
                d = stg + 2 * S96_AP + pp * S96_BP + r * 144 + q * 16;
                const __nv_bfloat16* bsel = (pp == 0) ? wh : (pp == 1) ? wl
                                          : (pp == 2) ? xh : xl;
                g = bsel + c * 64 + (size_t)r * H_DIM + q * 8;
            }
            CP_ASYNC16(d, (const void*)g);
        }
    }
    CP_COMMIT();
}

__global__ void __launch_bounds__(384, 1)
clstm_seqf(const float* __restrict__ Gbase,
           const int* __restrict__ toks, const float* __restrict__ tab,
           const __nv_bfloat16* __restrict__ WhH, const __nv_bfloat16* __restrict__ WhL,
           const __nv_bfloat16* __restrict__ WxH, const __nv_bfloat16* __restrict__ WxL,
           const float* __restrict__ nbias, float* __restrict__ Gout,
           float* __restrict__ cst,
           __nv_bfloat16* __restrict__ Hh, __nv_bfloat16* __restrict__ Hl) {
    extern __shared__ char smem[];
    const uint32_t sb = smem_to_u32(smem);
    const int tid = threadIdx.x, lane = tid & 31, w = tid >> 5;
    const int cb = blockIdx.x;
    const size_t bm = (size_t)blockIdx.y * 96;
    const int m0 = (w >> 2) * 32, n0 = (w & 3) * 32;
    const int arow = (lane & 7) + ((lane & 8) ? 8 : 0);
    const int akq  = (lane & 16) ? 16 : 0;
    const int brow = (lane & 7) + ((lane & 16) ? 8 : 0);
    const int bkq  = (lane & 8) ? 16 : 0;
    const __nv_bfloat16* whs = WhH + (size_t)(cb * 128) * H_DIM;
    const __nv_bfloat16* wls = WhL + (size_t)(cb * 128) * H_DIM;
    const __nv_bfloat16* xhs = WxH + (size_t)(cb * 128) * H_DIM;
    const __nv_bfloat16* xls = WxL + (size_t)(cb * 128) * H_DIM;
    const int erow = tid >> 2, hb = (tid & 3) * 8;
    const size_t grow = bm + erow;
    const int hc0 = cb * 32 + hb;
    float* cp = cst + grow * H_DIM + hc0;
    float* gpre  = (float*)smem;              // gates 96x128 (stage0 region)
    float* cpre  = (float*)(smem + 49152);    // c 96x32
    float* stash = (float*)(smem + FSTAGE);   // stage1 region: racc | gacc halves

    auto prefetch_gc = [&](int t) {
#pragma unroll
        for (int iq = 0; iq < 8; iq++) {
            int f = tid + iq * 384;
            int r = f >> 5, rem = f & 31;
            int g = rem >> 3, jj = (rem & 7) << 2;
            const float* rowp;
            int rr = (int)bm + r;
            if (toks) {
                int tk = __ldg(toks + ((rr >> 8) << 16) + ((rr & 255) << 8) + t);
                rowp = tab + (size_t)tk * G_COLS;
            } else {
                rowp = Gbase + (size_t)t * R_ROWS * G_COLS + (size_t)rr * G_COLS;
            }
            CP_ASYNC16(sb + (uint32_t)((r * 128 + g * 32 + jj) * 4),
                       (const void*)(rowp + g * H_DIM + cb * 32 + jj));
        }
        if (t > 0) {
#pragma unroll
            for (int iq = 0; iq < 2; iq++) {
                int f = tid + iq * 384;
                int r = f >> 3, jj = (f & 7) << 2;
                CP_ASYNC16(sb + 49152 + (uint32_t)((r * 32 + jj) * 4),
                           (const void*)(cst + (bm + r) * H_DIM + cb * 32 + jj));
            }
        }
        CP_COMMIT();
    };

#pragma unroll 1
    for (int i = 0; i <= 256; i++) {
        const int do_rec = (i >= 1) && (i <= 255);
        const int do_epi = (i <= 255);
        float racc[2][4][4], gacc[2][4][4];
#pragma unroll
        for (int mt = 0; mt < 2; mt++)
#pragma unroll
            for (int nt = 0; nt < 4; nt++)
#pragma unroll
                for (int e = 0; e < 4; e++) { racc[mt][nt][e] = 0.f; gacc[mt][nt][e] = 0.f; }

        if (i >= 1) {
            const __nv_bfloat16* aH0 = Hh + (size_t)(i - 1) * RH + bm * H_DIM;
            const __nv_bfloat16* aL0 = Hl + (size_t)(i - 1) * RH + bm * H_DIM;
            loadF_chunk(sb, tid, 0, 0, aH0, aL0, whs, wls, xhs, xls);
#pragma unroll 1
            for (int c = 0; c < 8; c++) {
                if (c < 7)      { loadF_chunk(sb, tid, c + 1, (c + 1) & 1,
                                              aH0, aL0, whs, wls, xhs, xls); CP_WAIT1(); }
                else if (do_epi) { prefetch_gc(i); CP_WAIT1(); }
                else             { CP_WAIT0(); }
                __syncthreads();
                uint32_t stg = sb + (uint32_t)(c & 1) * FSTAGE;
                uint32_t aH = stg, aL = stg + S96_AP;
                uint32_t bWh = stg + 2 * S96_AP, bWl = bWh + S96_BP;
                uint32_t bXh = bWl + S96_BP, bXl = bXh + S96_BP;
#pragma unroll
                for (int ks = 0; ks < 4; ks++) {
                    int kb = ks * 32;
                    uint32_t ah[2][4], al[2][4], bh[2][4], bl[2][4];
#pragma unroll
                    for (int mt = 0; mt < 2; mt++) {
                        ldmx4(ah[mt], aH + (m0 + mt * 16 + arow) * 144 + kb + akq);
                        ldmx4(al[mt], aL + (m0 + mt * 16 + arow) * 144 + kb + akq);
                    }
                    if (do_rec) {
#pragma unroll
                        for (int p = 0; p < 2; p++) {
                            ldmx4(bh[p], bWh + (n0 + p * 16 + brow) * 144 + kb + bkq);
                            ldmx4(bl[p], bWl + (n0 + p * 16 + brow) * 144 + kb + bkq);
                        }
#pragma unroll
                        for (int mt = 0; mt < 2; mt++)
#pragma unroll
                            for (int nt = 0; nt < 4; nt++)
                                mma_bf16(racc[mt][nt], ah[mt],
                                         bh[nt >> 1][(nt & 1) * 2], bh[nt >> 1][(nt & 1) * 2 + 1]);
#pragma unroll
                        for (int mt = 0; mt < 2; mt++)
#pragma unroll
                            for (int nt = 0; nt < 4; nt++)
                                mma_bf16(racc[mt][nt], ah[mt],
                                         bl[nt >> 1][(nt & 1) * 2], bl[nt >> 1][(nt & 1) * 2 + 1]);
#pragma unroll
                        for (int mt = 0; mt < 2; mt++)
#pragma unroll
                            for (int nt = 0; nt < 4; nt++)
                                mma_bf16(racc[mt][nt], al[mt],
                                         bh[nt >> 1][(nt & 1) * 2], bh[nt >> 1][(nt & 1) * 2 + 1]);
                    }
                    // gate plane (Wx_next)
#pragma unroll
                    for (int p = 0; p < 2; p++) {
                        ldmx4(bh[p], bXh + (n0 + p * 16 + brow) * 144 + kb + bkq);
                        ldmx4(bl[p], bXl + (n0 + p * 16 + brow) * 144 + kb + bkq);
                    }
#pragma unroll
                    for (int mt = 0; mt < 2; mt++)
#pragma unroll
                        for (int nt = 0; nt < 4; nt++)
                            mma_bf16(gacc[mt][nt], ah[mt],
                                     bh[nt >> 1][(nt & 1) * 2], bh[nt >> 1][(nt & 1) * 2 + 1]);
#pragma unroll
                    for (int mt = 0; mt < 2; mt++)
#pragma unroll
                        for (int nt = 0; nt < 4; nt++)
                            mma_bf16(gacc[mt][nt], ah[mt],
                                     bl[nt >> 1][(nt & 1) * 2], bl[nt >> 1][(nt & 1) * 2 + 1]);
#pragma unroll
                    for (int mt = 0; mt < 2; mt++)
#pragma unroll
                        for (int nt = 0; nt < 4; nt++)
                            mma_bf16(gacc[mt][nt], al[mt],
                                     bh[nt >> 1][(nt & 1) * 2], bh[nt >> 1][(nt & 1) * 2 + 1]);
                }
                __syncthreads();
            }
        } else {
            prefetch_gc(0);
        }

        // combined stash: racc -> stash[0..), gacc -> stash[GSMF..), ONE sync
        CP_WAIT0();            // gates (+c) prefetch landed
#pragma unroll
        for (int mt = 0; mt < 2; mt++)
#pragma unroll
            for (int nt = 0; nt < 4; nt++) {
                int row = m0 + mt * 16 + (lane >> 2);
                int col = n0 + nt * 8 + (lane & 3) * 2;
                stash[row * 132 + col]     = racc[mt][nt][0];
                stash[row * 132 + col + 1] = racc[mt][nt][1];
                stash[(row + 8) * 132 + col]     = racc[mt][nt][2];
                stash[(row + 8) * 132 + col + 1] = racc[mt][nt][3];
                stash[GSMF + row * 132 + col]     = gacc[mt][nt][0];
                stash[GSMF + row * 132 + col + 1] = gacc[mt][nt][1];
                stash[GSMF + (row + 8) * 132 + col]     = gacc[mt][nt][2];
                stash[GSMF + (row + 8) * 132 + col + 1] = gacc[mt][nt][3];
            }
        __syncthreads();

        if (do_epi) {
            __nv_bfloat16* hhp = Hh + (size_t)i * RH + grow * H_DIM + hc0;
            __nv_bfloat16* hlp = Hl + (size_t)i * RH + grow * H_DIM + hc0;
#pragma unroll
            for (int q = 0; q < 2; q++) {
                float4 gi = *(const float4*)(gpre + erow * 128 +       hb + q * 4);
                float4 gf = *(const float4*)(gpre + erow * 128 +  32 + hb + q * 4);
                float4 gg = *(const float4*)(gpre + erow * 128 +  64 + hb + q * 4);
                float4 go = *(const float4*)(gpre + erow * 128 +  96 + hb + q * 4);
                float4 co = make_float4(0.f, 0.f, 0.f, 0.f);
                if (i > 0) co = *(const float4*)(cpre + erow * 32 + hb + q * 4);
                float4 cv;
                __nv_bfloat16 bh4[4], bl4[4];
#pragma unroll
                for (int e = 0; e < 4; e++) {
                    int li = erow * 132 + hb + q * 4 + e;
                    float xi = stash[li]       + ((const float*)&gi)[e];
                    float xf = stash[li + 32]  + ((const float*)&gf)[e];
                    float xg = stash[li + 64]  + ((const float*)&gg)[e];
                    float xo = stash[li + 96]  + ((const float*)&go)[e];
                    float I = fsig(xi);
                    float F = fsig(xf);
                    float Gv = ftanh(xg);
                    float O = fsig(xo);
                    float cn = F * ((const float*)&co)[e] + I * Gv;
                    float hn = O * ftanh(cn);
                    ((float*)&cv)[e] = cn;
                    bh4[e] = __float2bfloat16(hn);
                    bl4[e] = __float2bfloat16(hn - __bfloat162float(bh4[e]));
                }
                *(float4*)(cp + q * 4) = cv;
                __nv_bfloat162 p0; p0.x = bh4[0]; p0.y = bh4[1];
                __nv_bfloat162 p1; p1.x = bh4[2]; p1.y = bh4[3];
                __nv_bfloat162 q0; q0.x = bl4[0]; q0.y = bl4[1];
                __nv_bfloat162 q1; q1.x = bl4[2]; q1.y = bl4[3];
                *(__nv_bfloat162*)(hhp + q * 4)     = p0;
                *(__nv_bfloat162*)(hhp + q * 4 + 2) = p1;
                *(__nv_bfloat162*)(hlp + q * 4)     = q0;
                *(__nv_bfloat162*)(hlp + q * 4 + 2) = q1;
            }
        }

        if (i >= 1) {
            // coalesced write of G_next[i-1] with bias (reads gacc half)
            int row = tid >> 2, c0 = (tid & 3) * 32;
            float* gp = Gout + ((size_t)(i - 1) * R_ROWS + bm + row) * G_COLS + cb * 128;
#pragma unroll
            for (int q = 0; q < 8; q++) {
                int col = c0 + q * 4;
                float4 v = *(float4*)(stash + GSMF + row * 132 + col);
                float4 bv = *(const float4*)(nbias + cb * 128 + col);
                v.x += bv.x; v.y += bv.y; v.z += bv.z; v.w += bv.w;
                *(float4*)(gp + col) = v;
            }
        }

        if (do_epi) grid_bar_local(blockIdx.y);
    }
}

// ---------------- head kernels -------------------------------------------------
__global__ void clstm_gather_r(const __nv_bfloat16* __restrict__ Hhi,
                               const __nv_bfloat16* __restrict__ Hlo,
                               float* __restrict__ r) {
    int b = blockIdx.x, i = blockIdx.y, h = threadIdx.x;
    size_t idx = ((size_t)(T_LEN - 1) * R_ROWS + i * B_SZ + b) * H_DIM + h;
    r[(size_t)b * 1536 + i * H_DIM + h] =
        __bfloat162float(Hhi[idx]) + __bfloat162float(Hlo[idx]);
}

__global__ void clstm_bn(float* __restrict__ x, const float* __restrict__ gamma,
                         const float* __restrict__ beta, int N) {
    __shared__ float s1[256], s2[256];
    int col = blockIdx.x;
    float v = x[(size_t)threadIdx.x * N + col];
    s1[threadIdx.x] = v; s2[threadIdx.x] = v * v;
    __syncthreads();
    for (int s = 128; s > 0; s >>= 1) {
        if (threadIdx.x < s) {
            s1[threadIdx.x] += s1[threadIdx.x + s];
            s2[threadIdx.x] += s2[threadIdx.x + s];
        }
        __syncthreads();
    }
    float m = s1[0] * (1.f / 256.f);
    float var = s2[0] * (1.f / 256.f) - m * m;
    float inv = rsqrtf(var + 1e-3f);
    x[(size_t)threadIdx.x * N + col] = gamma[col] * (v - m) * inv + beta[col];
}

__global__ void clstm_gemm_head(const float* __restrict__ A, const float* __restrict__ W,
                                const float* __restrict__ bias, float* __restrict__ C,
                                int K, int N, int act) {
    int n = blockIdx.x * 128 + threadIdx.x;
    int m0 = blockIdx.y * 16;
    if (n >= N) return;
    float s[16];
#pragma unroll
    for (int mm = 0; mm < 16; mm++) s[mm] = bias[n];
    for (int k = 0; k < K; k++) {
        float w = W[(size_t)k * N + n];
#pragma unroll
        for (int mm = 0; mm < 16; mm++)
            s[mm] += A[(size_t)(m0 + mm) * K + k] * w;
    }
    const float alpha = 1.6732632423543772f, scale = 1.0507009873554805f;
#pragma unroll
    for (int mm = 0; mm < 16; mm++) {
        float v = s[mm];
        if (act) v = scale * (v > 0.f ? v : alpha * expm1f(v));
        C[(size_t)(m0 + mm) * N + n] = v;
    }
}

// ---------------- launch --------------------------------------------------------
extern "C" void kernel_launch(void* const* d_in, const int* in_sizes, int n_in,
                              void* d_out, int out_size) {
    const int* t1 = (const int*)d_in[0];
    const int* t2 = (const int*)d_in[1];
    const int* t3 = (const int*)d_in[2];
    const float* emb = (const float*)d_in[3];
    const float* Wx = (const float*)d_in[4];
    const float* Wh = (const float*)d_in[5];
    const float* bb = (const float*)d_in[6];
    const float* g1 = (const float*)d_in[7];
    const float* be1 = (const float*)d_in[8];
    const float* W1 = (const float*)d_in[9];
    const float* bd1 = (const float*)d_in[10];
    const float* g2 = (const float*)d_in[11];
    const float* be2 = (const float*)d_in[12];
    const float* W2 = (const float*)d_in[13];
    const float* bd2 = (const float*)d_in[14];
    const float* g3 = (const float*)d_in[15];
    const float* be3 = (const float*)d_in[16];
    const float* W3 = (const float*)d_in[17];
    const float* bd3 = (const float*)d_in[18];
    float* out = (float*)d_out;

    float *G, *TAB, *C, *R, *H1, *H2;
    int* TOK;
    __nv_bfloat16 *Eh, *El, *WhPh, *WhPl, *WxTh, *WxTl, *sAh, *sAl, *sBh, *sBl;
    cudaGetSymbolAddress((void**)&G, d_Gbuf);
    cudaGetSymbolAddress((void**)&TAB, d_tab);
    cudaGetSymbolAddress((void**)&C, d_cst);
    cudaGetSymbolAddress((void**)&R, d_rbuf);
    cudaGetSymbolAddress((void**)&H1, d_h1buf);
    cudaGetSymbolAddress((void**)&H2, d_h2buf);
    cudaGetSymbolAddress((void**)&TOK, d_toks);
    cudaGetSymbolAddress((void**)&Eh, d_Ehi);
    cudaGetSymbolAddress((void**)&El, d_Elo);
    cudaGetSymbolAddress((void**)&WhPh, d_WhPhi);
    cudaGetSymbolAddress((void**)&WhPl, d_WhPlo);
    cudaGetSymbolAddress((void**)&WxTh, d_WxThi);
    cudaGetSymbolAddress((void**)&WxTl, d_WxTlo);
    cudaGetSymbolAddress((void**)&sAh, d_sAhi);
    cudaGetSymbolAddress((void**)&sAl, d_sAlo);
    cudaGetSymbolAddress((void**)&sBh, d_sBhi);
    cudaGetSymbolAddress((void**)&sBl, d_sBlo);

    cudaFuncSetAttribute(clstm_gemm_mma, cudaFuncAttributeMaxDynamicSharedMemorySize,
                         MMA_SMEM);
    cudaFuncSetAttribute(clstm_seq96, cudaFuncAttributeMaxDynamicSharedMemorySize,
                         SEQ_SMEM);
    cudaFuncSetAttribute(clstm_seqf, cudaFuncAttributeMaxDynamicSharedMemorySize,
                         SEQF_SMEM);

    // preprocessing
    cudaMemcpyAsync(TOK,          t1, 65536 * sizeof(int), cudaMemcpyDeviceToDevice, 0);
    cudaMemcpyAsync(TOK + 65536,  t2, 65536 * sizeof(int), cudaMemcpyDeviceToDevice, 0);
    cudaMemcpyAsync(TOK + 131072, t3, 65536 * sizeof(int), cudaMemcpyDeviceToDevice, 0);
    clstm_splitemb<<<V_SZ, 128>>>(emb, Eh, El);
    clstm_makeWsplit<<<dim3(64, 16, 3), dim3(32, 8)>>>(Wh, WhPh, WhPl, 1);
    clstm_makeWsplit<<<dim3(64, 16, 3), dim3(32, 8)>>>(Wx, WxTh, WxTl, 0);
    // vocab gate table: tab = emb @ Wx0 + b0   [32000, 2048]
    clstm_gemm_mma<<<dim3(16, V_SZ / 64), 256, MMA_SMEM>>>(
        Eh, El, WxTh, WxTl, bb, TAB);

    const size_t woff = (size_t)G_COLS * H_DIM;
    // layer 1 (fused): gates from tab[token]; h1 -> sB; G2 gates -> G
    clstm_seqf<<<dim3(16, 8), 384, SEQF_SMEM>>>(
        (const float*)0, TOK, TAB, WhPh, WhPl,
        WxTh + woff, WxTl + woff, bb + G_COLS, G, C, sBh, sBl);
    // layer 2 (fused, G in-place): reads G2 gates from G[t], writes G3 to G[t-1]
    clstm_seqf<<<dim3(16, 8), 384, SEQF_SMEM>>>(
        G, (const int*)0, (const float*)0, WhPh + woff, WhPl + woff,
        WxTh + 2 * woff, WxTl + 2 * woff, bb + 2 * G_COLS, G, C, sAh, sAl);
    // layer 3 (plain): gates from G; h3 -> sB
    clstm_seq96<<<dim3(16, 8), 384, SEQ_SMEM>>>(
        G, (const int*)0, (const float*)0,
        WhPh + 2 * woff, WhPl + 2 * woff, C, sBh, sBl);

    // head
    clstm_gather_r<<<dim3(B_SZ, 3), H_DIM>>>(sBh, sBl, R);
    clstm_bn<<<1536, 256>>>(R, g1, be1, 1536);
    clstm_gemm_head<<<dim3(8, 16), 128>>>(R, W1, bd1, H1, 1536, 1024, 1);
    clstm_bn<<<1024, 256>>>(H1, g2, be2, 1024);
    clstm_gemm_head<<<dim3(1, 16), 128>>>(H1, W2, bd2, H2, 1024, H5, 1);
    clstm_bn<<<H5, 256>>>(H2, g3, be3, H5);
    clstm_gemm_head<<<dim3(1, 16), 128>>>(H2, W3, bd3, out, H5, 4, 0);
}

// round 16
// speedup vs baseline: 1.1535x; 1.0709x over previous
#include <cuda_runtime.h>
#include <cuda_fp16.h>
#include <math.h>
#include <stdint.h>
#include <stddef.h>

#define T_LEN 256
#define B_SZ  256
#define H_DIM 512
#define R_ROWS 768
#define G_COLS 2048
#define M_ALL  196608
#define V_SZ   32000
#define H5 102
#define RH 393216            // R_ROWS * H_DIM

// ---------------- static device scratch --------------------------------------
// Single G buffer; fused kernel reads gates[t] and overwrites gates[t-1] in
// place (slot t read at iter t, overwritten at iter t+1, ordered by the
// per-group barrier). Keeps .bss < 4GB (AArch64 reloc limit).
__device__ float d_Gbuf[402653184];   // [T][768][2048]
__device__ float d_tab[65536000];     // [32000][2048] emb@Wx0 + b0
__device__ float d_cst[393216];
__device__ float d_rbuf[393216];
__device__ float d_h1buf[262144];
__device__ float d_h2buf[26112];
__device__ int   d_toks[196608];      // [3][256][256]
__device__ unsigned d_barGenL[256];   // 8 groups, stride 32
__device__ unsigned d_barCntL[256];
__device__ __half d_Ehi[16384000];            // emb split [32000][512]
__device__ __half d_Elo[16384000];
__device__ __half d_WhPhi[3 * 2048 * 512];    // Wh permuted [n'][k] hi
__device__ __half d_WhPlo[3 * 2048 * 512];
__device__ __half d_WxThi[3 * 2048 * 512];    // Wx transposed [n][k] hi
__device__ __half d_WxTlo[3 * 2048 * 512];
__device__ __half d_sAhi[100663296];          // h seq splits (ping)
__device__ __half d_sAlo[100663296];
__device__ __half d_sBhi[100663296];          // (pong)
__device__ __half d_sBlo[100663296];

// ---------------- helpers ------------------------------------------------------
__device__ __forceinline__ uint32_t smem_to_u32(const void* p) {
    uint32_t a;
    asm("{ .reg .u64 t; cvta.to.shared.u64 t, %1; cvt.u32.u64 %0, t; }"
        : "=r"(a) : "l"(p));
    return a;
}
__device__ __forceinline__ void ldmx4(uint32_t* r, uint32_t addr) {
    asm volatile("ldmatrix.sync.aligned.m8n8.x4.shared.b16 {%0,%1,%2,%3}, [%4];"
                 : "=r"(r[0]), "=r"(r[1]), "=r"(r[2]), "=r"(r[3]) : "r"(addr));
}
__device__ __forceinline__ void mma_f16(float* c, const uint32_t* a,
                                        uint32_t b0, uint32_t b1) {
    asm volatile(
        "mma.sync.aligned.m16n8k16.row.col.f32.f16.f16.f32 "
        "{%0,%1,%2,%3}, {%4,%5,%6,%7}, {%8,%9}, {%0,%1,%2,%3};"
        : "+f"(c[0]), "+f"(c[1]), "+f"(c[2]), "+f"(c[3])
        : "r"(a[0]), "r"(a[1]), "r"(a[2]), "r"(a[3]), "r"(b0), "r"(b1));
}
// fast activations: __expf-based (saturates correctly at +/-inf)
__device__ __forceinline__ float fsig(float x) {
    return __fdividef(1.f, 1.f + __expf(-x));
}
__device__ __forceinline__ float ftanh(float x) {
    return 1.f - __fdividef(2.f, __expf(2.f * x) + 1.f);
}
#define CP_ASYNC16(dst, src) \
    asm volatile("cp.async.cg.shared.global [%0], [%1], 16;" :: "r"(dst), "l"(src))
#define CP_COMMIT()  asm volatile("cp.async.commit_group;" ::: "memory")
#define CP_WAIT0()   asm volatile("cp.async.wait_group 0;" ::: "memory")
#define CP_WAIT1()   asm volatile("cp.async.wait_group 1;" ::: "memory")

// ---- 64-row kernel smem (vocab table GEMM) ----
#define STAGE_B 55296
#define MMA_SMEM 110592
// ---- 96-row plain seq kernel ----
#define S96_AP 13824          // 96*144
#define S96_BP 18432          // 128*144
#define S96_STAGE 64512       // 2*AP + 2*BP
#define GOFF 129024           // gates prefetch (96*128 f32)
#define COFF 178176           // c prefetch (96*32 f32)
#define SEQ_SMEM 190464
// ---- fused seq kernel: stage = 2*AP + 4*BP ----
#define FSTAGE 101376
#define GSMF 12672            // floats per stash half (96*132)
#define SEQF_SMEM 202752      // 2 stages; gates/c prefetch reuses stage0 region

// ---------------- emb -> fp16 split ---------------------------------------------
__global__ void clstm_splitemb(const float* __restrict__ emb,
                               __half* __restrict__ Ehi,
                               __half* __restrict__ Elo) {
    size_t base = (size_t)blockIdx.x * H_DIM + threadIdx.x * 4;
    float4 v = *(const float4*)(emb + base);
    float vv[4] = { v.x, v.y, v.z, v.w };
#pragma unroll
    for (int e = 0; e < 4; e++) {
        __half h = __float2half_rn(vv[e]);
        Ehi[base + e] = h;
        Elo[base + e] = __float2half_rn(vv[e] - __half2float(h));
    }
}

// ---------------- W [k][n] -> [n'][k] fp16 split (optional gate permute) --------
__global__ void clstm_makeWsplit(const float* __restrict__ W,
                                 __half* __restrict__ Phi,
                                 __half* __restrict__ Plo, int permute) {
    __shared__ float tile[32][33];
    int n0 = blockIdx.x * 32, k0 = blockIdx.y * 32, l = blockIdx.z;
    const float* Wl = W + (size_t)l * H_DIM * G_COLS;
    int tx = threadIdx.x, ty = threadIdx.y;
#pragma unroll
    for (int it = 0; it < 4; it++)
        tile[ty + it * 8][tx] = Wl[(size_t)(k0 + ty + it * 8) * G_COLS + n0 + tx];
    __syncthreads();
    int s = n0 >> 9, cbb = (n0 >> 5) & 15;
    int np0 = permute ? (cbb * 128 + s * 32) : n0;
    __half* ph = Phi + (size_t)l * G_COLS * H_DIM;
    __half* pl = Plo + (size_t)l * G_COLS * H_DIM;
#pragma unroll
    for (int it = 0; it < 4; it++) {
        int nn = ty + it * 8;
        float v = tile[tx][nn];
        __half hi = __float2half_rn(v);
        __half lo = __float2half_rn(v - __half2float(hi));
        ph[(size_t)(np0 + nn) * H_DIM + k0 + tx] = hi;
        pl[(size_t)(np0 + nn) * H_DIM + k0 + tx] = lo;
    }
}

// ---------------- HMMA 64-row GEMM (vocab table only, 3 planes) ------------------
__global__ void __launch_bounds__(256, 2)
clstm_gemm_mma(const __half* __restrict__ Ahi, const __half* __restrict__ Alo,
               const __half* __restrict__ Bhi, const __half* __restrict__ Blo,
               const float* __restrict__ bias, float* __restrict__ G) {
    extern __shared__ char smem[];
    const uint32_t sb = smem_to_u32(smem);
    const int tid = threadIdx.x, lane = tid & 31, w = tid >> 5;
    const int cb = blockIdx.x;
    const size_t bm = (size_t)blockIdx.y * 64;
    const __half* asrc[2] = { Ahi + bm * H_DIM, Alo + bm * H_DIM };
    const __half* bsrc[2] = { Bhi + (size_t)(cb * 128) * H_DIM,
                              Blo + (size_t)(cb * 128) * H_DIM };
    const int lr = tid >> 3, lq = tid & 7;

    auto load_chunk = [&](int c, int s) {
        uint32_t stg = sb + (uint32_t)s * STAGE_B;
#pragma unroll
        for (int p = 0; p < 2; p++) {
            const __half* gb = asrc[p] + c * 64;
            uint32_t sd = stg + p * 9216;
#pragma unroll
            for (int i = 0; i < 2; i++) {
                int r = lr + i * 32;
                CP_ASYNC16(sd + r * 144 + lq * 16,
                           (const void*)(gb + (size_t)r * H_DIM + lq * 8));
            }
        }
#pragma unroll
        for (int p = 0; p < 2; p++) {
            const __half* gb = bsrc[p] + c * 64;
            uint32_t sd = stg + 18432 + p * 18432;
#pragma unroll
            for (int i = 0; i < 4; i++) {
                int r = lr + i * 32;
                CP_ASYNC16(sd + r * 144 + lq * 16,
                           (const void*)(gb + (size_t)r * H_DIM + lq * 8));
            }
        }
        CP_COMMIT();
    };

    const int m0 = (w >> 1) * 16, n0 = (w & 1) * 64;
    const int arow = (lane & 7) + ((lane & 8) ? 8 : 0);
    const int akq  = (lane & 16) ? 16 : 0;
    const int brow = (lane & 7) + ((lane & 16) ? 8 : 0);
    const int bkq  = (lane & 8) ? 16 : 0;

    float acc[8][4];
#pragma unroll
    for (int nt = 0; nt < 8; nt++)
#pragma unroll
        for (int e = 0; e < 4; e++) acc[nt][e] = 0.f;

    load_chunk(0, 0);
    for (int c = 0; c < 8; c++) {
        if (c < 7) { load_chunk(c + 1, (c + 1) & 1); CP_WAIT1(); }
        else       { CP_WAIT0(); }
        __syncthreads();
        uint32_t stg = sb + (uint32_t)(c & 1) * STAGE_B;
        uint32_t aH = stg, aL = stg + 9216, bH = stg + 18432, bL = stg + 36864;
#pragma unroll
        for (int ks = 0; ks < 4; ks++) {
            int kb = ks * 32;
            uint32_t ah[4], al[4], bh[4][4], bl[4][4];
            ldmx4(ah, aH + (m0 + arow) * 144 + kb + akq);
            ldmx4(al, aL + (m0 + arow) * 144 + kb + akq);
#pragma unroll
            for (int p = 0; p < 4; p++) {
                ldmx4(bh[p], bH + (n0 + p * 16 + brow) * 144 + kb + bkq);
                ldmx4(bl[p], bL + (n0 + p * 16 + brow) * 144 + kb + bkq);
            }
#pragma unroll
            for (int nt = 0; nt < 8; nt++)
                mma_f16(acc[nt], ah, bh[nt >> 1][(nt & 1) * 2], bh[nt >> 1][(nt & 1) * 2 + 1]);
#pragma unroll
            for (int nt = 0; nt < 8; nt++)
                mma_f16(acc[nt], ah, bl[nt >> 1][(nt & 1) * 2], bl[nt >> 1][(nt & 1) * 2 + 1]);
#pragma unroll
            for (int nt = 0; nt < 8; nt++)
                mma_f16(acc[nt], al, bh[nt >> 1][(nt & 1) * 2], bh[nt >> 1][(nt & 1) * 2 + 1]);
        }
        __syncthreads();
    }

    float* gsm = (float*)smem;     // [64][132]
#pragma unroll
    for (int nt = 0; nt < 8; nt++) {
        int row = m0 + (lane >> 2);
        int col = n0 + nt * 8 + (lane & 3) * 2;
        gsm[row * 132 + col]     = acc[nt][0];
        gsm[row * 132 + col + 1] = acc[nt][1];
        gsm[(row + 8) * 132 + col]     = acc[nt][2];
        gsm[(row + 8) * 132 + col + 1] = acc[nt][3];
    }
    __syncthreads();

    int row = tid >> 2, c0 = (tid & 3) * 32;
    float* gp = G + (bm + row) * G_COLS + cb * 128;
#pragma unroll
    for (int q = 0; q < 8; q++) {
        int col = c0 + q * 4;
        float4 v = *(float4*)(gsm + row * 132 + col);
        float4 bv = *(const float4*)(bias + cb * 128 + col);
        v.x += bv.x; v.y += bv.y; v.z += bv.z; v.w += bv.w;
        *(float4*)(gp + col) = v;
    }
}

// ---------------- row-block-local barrier (16 CTAs per group) --------------------
__device__ __forceinline__ void grid_bar_local(int grp) {
    __syncthreads();
    if (threadIdx.x == 0) {
        unsigned* genp = &d_barGenL[grp * 32];
        unsigned* cntp = &d_barCntL[grp * 32];
        unsigned g;
        asm volatile("ld.acquire.gpu.u32 %0, [%1];" : "=r"(g) : "l"(genp));
        unsigned a;
        asm volatile("atom.acq_rel.gpu.add.u32 %0, [%1], 1;"
                     : "=r"(a) : "l"(cntp) : "memory");
        if (a == 15u) {
            asm volatile("st.relaxed.gpu.u32 [%0], 0;" :: "l"(cntp) : "memory");
            asm volatile("red.release.gpu.add.u32 [%0], 1;" :: "l"(genp) : "memory");
        } else {
            unsigned cur;
            do {
                asm volatile("nanosleep.u32 64;");
                asm volatile("ld.acquire.gpu.u32 %0, [%1];" : "=r"(cur) : "l"(genp));
            } while (cur == g);
        }
    }
    __syncthreads();
}

// ---------------- plain 96-row seq (layer 3, 3 planes) ---------------------------
__device__ __forceinline__ void load96_chunk(
    uint32_t sb, int tid, int c, int s,
    const __half* __restrict__ aH0, const __half* __restrict__ aL0,
    const __half* __restrict__ bH0, const __half* __restrict__ bL0)
{
    uint32_t stg = sb + (uint32_t)s * S96_STAGE;
#pragma unroll
    for (int i = 0; i < 10; i++) {
        int idx = tid + i * 384;
        if (idx < 3584) {
            uint32_t d; const __half* g;
            if (idx < 1536) {
                int p = idx >= 768, rem = idx - p * 768;
                int r = rem >> 3, q = rem & 7;
                d = stg + p * S96_AP + r * 144 + q * 16;
                g = (p ? aL0 : aH0) + c * 64 + (size_t)r * H_DIM + q * 8;
            } else {
                int j = idx - 1536;
                int p = j >= 1024, rem = j - p * 1024;
                int r = rem >> 3, q = rem & 7;
                d = stg + 2 * S96_AP + p * S96_BP + r * 144 + q * 16;
                g = (p ? bL0 : bH0) + c * 64 + (size_t)r * H_DIM + q * 8;
            }
            CP_ASYNC16(d, (const void*)g);
        }
    }
    CP_COMMIT();
}

__device__ __forceinline__ void mma_tile96(
    uint32_t sb, int tid, int m0, int n0,
    int arow, int akq, int brow, int bkq,
    const __half* __restrict__ aH0, const __half* __restrict__ aL0,
    const __half* __restrict__ bH0, const __half* __restrict__ bL0,
    float acc[2][4][4])
{
    load96_chunk(sb, tid, 0, 0, aH0, aL0, bH0, bL0);
#pragma unroll 1
    for (int c = 0; c < 8; c++) {
        if (c < 7) { load96_chunk(sb, tid, c + 1, (c + 1) & 1, aH0, aL0, bH0, bL0); CP_WAIT1(); }
        else       { CP_WAIT0(); }
        __syncthreads();
        uint32_t stg = sb + (uint32_t)(c & 1) * S96_STAGE;
        uint32_t aH = stg, aL = stg + S96_AP;
        uint32_t bH = stg + 2 * S96_AP, bL = bH + S96_BP;
#pragma unroll
        for (int ks = 0; ks < 4; ks++) {
            int kb = ks * 32;
            uint32_t ah[2][4], al[2][4], bh[2][4], bl[2][4];
#pragma unroll
            for (int mt = 0; mt < 2; mt++) {
                ldmx4(ah[mt], aH + (m0 + mt * 16 + arow) * 144 + kb + akq);
                ldmx4(al[mt], aL + (m0 + mt * 16 + arow) * 144 + kb + akq);
            }
#pragma unroll
            for (int p = 0; p < 2; p++) {
                ldmx4(bh[p], bH + (n0 + p * 16 + brow) * 144 + kb + bkq);
                ldmx4(bl[p], bL + (n0 + p * 16 + brow) * 144 + kb + bkq);
            }
#pragma unroll
            for (int mt = 0; mt < 2; mt++)
#pragma unroll
                for (int nt = 0; nt < 4; nt++)
                    mma_f16(acc[mt][nt], ah[mt],
                            bh[nt >> 1][(nt & 1) * 2], bh[nt >> 1][(nt & 1) * 2 + 1]);
#pragma unroll
            for (int mt = 0; mt < 2; mt++)
#pragma unroll
                for (int nt = 0; nt < 4; nt++)
                    mma_f16(acc[mt][nt], ah[mt],
                            bl[nt >> 1][(nt & 1) * 2], bl[nt >> 1][(nt & 1) * 2 + 1]);
#pragma unroll
            for (int mt = 0; mt < 2; mt++)
#pragma unroll
                for (int nt = 0; nt < 4; nt++)
                    mma_f16(acc[mt][nt], al[mt],
                            bh[nt >> 1][(nt & 1) * 2], bh[nt >> 1][(nt & 1) * 2 + 1]);
        }
        __syncthreads();
    }
}

__global__ void __launch_bounds__(384, 1)
clstm_seq96(const float* __restrict__ Gbase,
            const int* __restrict__ toks, const float* __restrict__ tab,
            const __half* __restrict__ WhH, const __half* __restrict__ WhL,
            float* __restrict__ cst,
            __half* __restrict__ Hh, __half* __restrict__ Hl) {
    extern __shared__ char smem[];
    const uint32_t sb = smem_to_u32(smem);
    const int tid = threadIdx.x, lane = tid & 31, w = tid >> 5;
    const int cb = blockIdx.x;
    const size_t bm = (size_t)blockIdx.y * 96;
    const int m0 = (w >> 2) * 32, n0 = (w & 3) * 32;
    const int arow = (lane & 7) + ((lane & 8) ? 8 : 0);
    const int akq  = (lane & 16) ? 16 : 0;
    const int brow = (lane & 7) + ((lane & 16) ? 8 : 0);
    const int bkq  = (lane & 8) ? 16 : 0;
    const __half* bH0 = WhH + (size_t)(cb * 128) * H_DIM;
    const __half* bL0 = WhL + (size_t)(cb * 128) * H_DIM;
    const int erow = tid >> 2, hb = (tid & 3) * 8;
    const size_t grow = bm + erow;
    const int hc0 = cb * 32 + hb;
    float* cp = cst + grow * H_DIM + hc0;
    float* gsm = (float*)smem;
    const float* gsm2 = (const float*)(smem + GOFF);
    const float* csm  = (const float*)(smem + COFF);

#pragma unroll 1
    for (int t = 0; t < T_LEN; t++) {
        {
#pragma unroll
            for (int i = 0; i < 8; i++) {
                int f = tid + i * 384;
                int r = f >> 5, rem = f & 31;
                int g = rem >> 3, jj = (rem & 7) << 2;
                const float* rowp;
                int rr = (int)bm + r;
                if (toks) {
                    int tk = __ldg(toks + ((rr >> 8) << 16) + ((rr & 255) << 8) + t);
                    rowp = tab + (size_t)tk * G_COLS;
                } else {
                    rowp = Gbase + (size_t)t * R_ROWS * G_COLS + (size_t)rr * G_COLS;
                }
                CP_ASYNC16(sb + GOFF + (uint32_t)((r * 128 + g * 32 + jj) * 4),
                           (const void*)(rowp + g * H_DIM + cb * 32 + jj));
            }
            if (t > 0) {
#pragma unroll
                for (int i = 0; i < 2; i++) {
                    int f = tid + i * 384;
                    int r = f >> 3, jj = (f & 7) << 2;
                    CP_ASYNC16(sb + COFF + (uint32_t)((r * 32 + jj) * 4),
                               (const void*)(cst + (bm + r) * H_DIM + cb * 32 + jj));
                }
            }
            CP_COMMIT();
        }

        float acc[2][4][4];
#pragma unroll
        for (int mt = 0; mt < 2; mt++)
#pragma unroll
            for (int nt = 0; nt < 4; nt++)
#pragma unroll
                for (int e = 0; e < 4; e++) acc[mt][nt][e] = 0.f;

        if (t > 0) {
            const __half* aH0 = Hh + (size_t)(t - 1) * RH + bm * H_DIM;
            const __half* aL0 = Hl + (size_t)(t - 1) * RH + bm * H_DIM;
            mma_tile96(sb, tid, m0, n0, arow, akq, brow, bkq, aH0, aL0, bH0, bL0, acc);
        } else {
            CP_WAIT0();
            __syncthreads();
        }

#pragma unroll
        for (int mt = 0; mt < 2; mt++)
#pragma unroll
            for (int nt = 0; nt < 4; nt++) {
                int row = m0 + mt * 16 + (lane >> 2);
                int col = n0 + nt * 8 + (lane & 3) * 2;
                gsm[row * 132 + col]     = acc[mt][nt][0];
                gsm[row * 132 + col + 1] = acc[mt][nt][1];
                gsm[(row + 8) * 132 + col]     = acc[mt][nt][2];
                gsm[(row + 8) * 132 + col + 1] = acc[mt][nt][3];
            }
        __syncthreads();

        __half* hhp = Hh + (size_t)t * RH + grow * H_DIM + hc0;
        __half* hlp = Hl + (size_t)t * RH + grow * H_DIM + hc0;
#pragma unroll
        for (int q = 0; q < 2; q++) {
            float4 gi = *(const float4*)(gsm2 + erow * 128 +       hb + q * 4);
            float4 gf = *(const float4*)(gsm2 + erow * 128 +  32 + hb + q * 4);
            float4 gg = *(const float4*)(gsm2 + erow * 128 +  64 + hb + q * 4);
            float4 go = *(const float4*)(gsm2 + erow * 128 +  96 + hb + q * 4);
            float4 co = make_float4(0.f, 0.f, 0.f, 0.f);
            if (t > 0) co = *(const float4*)(csm + erow * 32 + hb + q * 4);
            float4 cv;
            __half bh4[4], bl4[4];
#pragma unroll
            for (int e = 0; e < 4; e++) {
                int li = erow * 132 + hb + q * 4 + e;
                float xi = gsm[li]       + ((const float*)&gi)[e];
                float xf = gsm[li + 32]  + ((const float*)&gf)[e];
                float xg = gsm[li + 64]  + ((const float*)&gg)[e];
                float xo = gsm[li + 96]  + ((const float*)&go)[e];
                float I = fsig(xi);
                float F = fsig(xf);
                float Gv = ftanh(xg);
                float O = fsig(xo);
                float cn = F * ((const float*)&co)[e] + I * Gv;
                float hn = O * ftanh(cn);
                ((float*)&cv)[e] = cn;
                bh4[e] = __float2half_rn(hn);
                bl4[e] = __float2half_rn(hn - __half2float(bh4[e]));
            }
            *(float4*)(cp + q * 4) = cv;
            __half2 p0; p0.x = bh4[0]; p0.y = bh4[1];
            __half2 p1; p1.x = bh4[2]; p1.y = bh4[3];
            __half2 q0; q0.x = bl4[0]; q0.y = bl4[1];
            __half2 q1; q1.x = bl4[2]; q1.y = bl4[3];
            *(__half2*)(hhp + q * 4)     = p0;
            *(__half2*)(hhp + q * 4 + 2) = p1;
            *(__half2*)(hlp + q * 4)     = q0;
            *(__half2*)(hlp + q * 4 + 2) = q1;
        }
        grid_bar_local(blockIdx.y);
    }
}

// ---------------- FUSED seq: recurrence(3 planes) + gate GEMM(2 planes) ----------
// Per iteration i (A = h[i-1], staged once): recurrent gates for step i AND
// G_next[i-1] = h_hi[i-1]@Wx_next(full) + nbias. Iteration 256 finishes G[255].
// Gout may alias Gbase (slot i read at iter i, overwritten at iter i+1).
__device__ __forceinline__ void loadF_chunk(
    uint32_t sb, int tid, int c, int s,
    const __half* __restrict__ aH0, const __half* __restrict__ aL0,
    const __half* __restrict__ wh, const __half* __restrict__ wl,
    const __half* __restrict__ xh, const __half* __restrict__ xl)
{
    uint32_t stg = sb + (uint32_t)s * FSTAGE;
#pragma unroll
    for (int i = 0; i < 15; i++) {
        int idx = tid + i * 384;
        if (idx < 5632) {
            uint32_t d; const __half* g;
            if (idx < 1536) {
                int p = idx >= 768, rem = idx - p * 768;
                int r = rem >> 3, q = rem & 7;
                d = stg + p * S96_AP + r * 144 + q * 16;
                g = (p ? aL0 : aH0) + c * 64 + (size_t)r * H_DIM + q * 8;
            } else {
                int j = idx - 1536;
                int pp = j >> 10, rem = j & 1023;
                int r = rem >> 3, q = rem & 7;
                d = stg + 2 * S96_AP + pp * S96_BP + r * 144 + q * 16;
                const __half* bsel = (pp == 0) ? wh : (pp == 1) ? wl
                                   : (pp == 2) ? xh : xl;
                g = bsel + c * 64 + (size_t)r * H_DIM + q * 8;
            }
            CP_ASYNC16(d, (const void*)g);
        }
    }
    CP_COMMIT();
}

__global__ void __launch_bounds__(384, 1)
clstm_seqf(const float* __restrict__ Gbase,
           const int* __restrict__ toks, const float* __restrict__ tab,
           const __half* __restrict__ WhH, const __half* __restrict__ WhL,
           const __half* __restrict__ WxH, const __half* __restrict__ WxL,
           const float* __restrict__ nbias, float* __restrict__ Gout,
           float* __restrict__ cst,
           __half* __restrict__ Hh, __half* __restrict__ Hl) {
    extern __shared__ char smem[];
    const uint32_t sb = smem_to_u32(smem);
    const int tid = threadIdx.x, lane = tid & 31, w = tid >> 5;
    const int cb = blockIdx.x;
    const size_t bm = (size_t)blockIdx.y * 96;
    const int m0 = (w >> 2) * 32, n0 = (w & 3) * 32;
    const int arow = (lane & 7) + ((lane & 8) ? 8 : 0);
    const int akq  = (lane & 16) ? 16 : 0;
    const int brow = (lane & 7) + ((lane & 16) ? 8 : 0);
    const int bkq  = (lane & 8) ? 16 : 0;
    const __half* whs = WhH + (size_t)(cb * 128) * H_DIM;
    const __half* wls = WhL + (size_t)(cb * 128) * H_DIM;
    const __half* xhs = WxH + (size_t)(cb * 128) * H_DIM;
    const __half* xls = WxL + (size_t)(cb * 128) * H_DIM;
    const int erow = tid >> 2, hb = (tid & 3) * 8;
    const size_t grow = bm + erow;
    const int hc0 = cb * 32 + hb;
    float* cp = cst + grow * H_DIM + hc0;
    float* gpre  = (float*)smem;              // gates 96x128 (stage0 region)
    float* cpre  = (float*)(smem + 49152);    // c 96x32
    float* stash = (float*)(smem + FSTAGE);   // stage1 region: racc | gacc halves

    auto prefetch_gc = [&](int t) {
#pragma unroll
        for (int iq = 0; iq < 8; iq++) {
            int f = tid + iq * 384;
            int r = f >> 5, rem = f & 31;
            int g = rem >> 3, jj = (rem & 7) << 2;
            const float* rowp;
            int rr = (int)bm + r;
            if (toks) {
                int tk = __ldg(toks + ((rr >> 8) << 16) + ((rr & 255) << 8) + t);
                rowp = tab + (size_t)tk * G_COLS;
            } else {
                rowp = Gbase + (size_t)t * R_ROWS * G_COLS + (size_t)rr * G_COLS;
            }
            CP_ASYNC16(sb + (uint32_t)((r * 128 + g * 32 + jj) * 4),
                       (const void*)(rowp + g * H_DIM + cb * 32 + jj));
        }
        if (t > 0) {
#pragma unroll
            for (int iq = 0; iq < 2; iq++) {
                int f = tid + iq * 384;
                int r = f >> 3, jj = (f & 7) << 2;
                CP_ASYNC16(sb + 49152 + (uint32_t)((r * 32 + jj) * 4),
                           (const void*)(cst + (bm + r) * H_DIM + cb * 32 + jj));
            }
        }
        CP_COMMIT();
    };

#pragma unroll 1
    for (int i = 0; i <= 256; i++) {
        const int do_rec = (i >= 1) && (i <= 255);
        const int do_epi = (i <= 255);
        float racc[2][4][4], gacc[2][4][4];
#pragma unroll
        for (int mt = 0; mt < 2; mt++)
#pragma unroll
            for (int nt = 0; nt < 4; nt++)
#pragma unroll
                for (int e = 0; e < 4; e++) { racc[mt][nt][e] = 0.f; gacc[mt][nt][e] = 0.f; }

        if (i >= 1) {
            const __half* aH0 = Hh + (size_t)(i - 1) * RH + bm * H_DIM;
            const __half* aL0 = Hl + (size_t)(i - 1) * RH + bm * H_DIM;
            loadF_chunk(sb, tid, 0, 0, aH0, aL0, whs, wls, xhs, xls);
#pragma unroll 1
            for (int c = 0; c < 8; c++) {
                if (c < 7)      { loadF_chunk(sb, tid, c + 1, (c + 1) & 1,
                                              aH0, aL0, whs, wls, xhs, xls); CP_WAIT1(); }
                else if (do_epi) { prefetch_gc(i); CP_WAIT1(); }
                else             { CP_WAIT0(); }
                __syncthreads();
                uint32_t stg = sb + (uint32_t)(c & 1) * FSTAGE;
                uint32_t aH = stg, aL = stg + S96_AP;
                uint32_t bWh = stg + 2 * S96_AP, bWl = bWh + S96_BP;
                uint32_t bXh = bWl + S96_BP, bXl = bXh + S96_BP;
#pragma unroll
                for (int ks = 0; ks < 4; ks++) {
                    int kb = ks * 32;
                    uint32_t ah[2][4], al[2][4], bh[2][4], bl[2][4];
#pragma unroll
                    for (int mt = 0; mt < 2; mt++) {
                        ldmx4(ah[mt], aH + (m0 + mt * 16 + arow) * 144 + kb + akq);
                        ldmx4(al[mt], aL + (m0 + mt * 16 + arow) * 144 + kb + akq);
                    }
                    if (do_rec) {
#pragma unroll
                        for (int p = 0; p < 2; p++) {
                            ldmx4(bh[p], bWh + (n0 + p * 16 + brow) * 144 + kb + bkq);
                            ldmx4(bl[p], bWl + (n0 + p * 16 + brow) * 144 + kb + bkq);
                        }
#pragma unroll
                        for (int mt = 0; mt < 2; mt++)
#pragma unroll
                            for (int nt = 0; nt < 4; nt++)
                                mma_f16(racc[mt][nt], ah[mt],
                                        bh[nt >> 1][(nt & 1) * 2], bh[nt >> 1][(nt & 1) * 2 + 1]);
#pragma unroll
                        for (int mt = 0; mt < 2; mt++)
#pragma unroll
                            for (int nt = 0; nt < 4; nt++)
                                mma_f16(racc[mt][nt], ah[mt],
                                        bl[nt >> 1][(nt & 1) * 2], bl[nt >> 1][(nt & 1) * 2 + 1]);
#pragma unroll
                        for (int mt = 0; mt < 2; mt++)
#pragma unroll
                            for (int nt = 0; nt < 4; nt++)
                                mma_f16(racc[mt][nt], al[mt],
                                        bh[nt >> 1][(nt & 1) * 2], bh[nt >> 1][(nt & 1) * 2 + 1]);
                    }
                    // gate planes (Wx_next): 2 planes = h_hi @ (Wx_hi + Wx_lo)
#pragma unroll
                    for (int p = 0; p < 2; p++) {
                        ldmx4(bh[p], bXh + (n0 + p * 16 + brow) * 144 + kb + bkq);
                        ldmx4(bl[p], bXl + (n0 + p * 16 + brow) * 144 + kb + bkq);
                    }
#pragma unroll
                    for (int mt = 0; mt < 2; mt++)
#pragma unroll
                        for (int nt = 0; nt < 4; nt++)
                            mma_f16(gacc[mt][nt], ah[mt],
                                    bh[nt >> 1][(nt & 1) * 2], bh[nt >> 1][(nt & 1) * 2 + 1]);
#pragma unroll
                    for (int mt = 0; mt < 2; mt++)
#pragma unroll
                        for (int nt = 0; nt < 4; nt++)
                            mma_f16(gacc[mt][nt], ah[mt],
                                    bl[nt >> 1][(nt & 1) * 2], bl[nt >> 1][(nt & 1) * 2 + 1]);
                }
                __syncthreads();
            }
        } else {
            prefetch_gc(0);
        }

        // combined stash: racc -> stash[0..), gacc -> stash[GSMF..), ONE sync
        CP_WAIT0();            // gates (+c) prefetch landed
#pragma unroll
        for (int mt = 0; mt < 2; mt++)
#pragma unroll
            for (int nt = 0; nt < 4; nt++) {
                int row = m0 + mt * 16 + (lane >> 2);
                int col = n0 + nt * 8 + (lane & 3) * 2;
                stash[row * 132 + col]     = racc[mt][nt][0];
                stash[row * 132 + col + 1] = racc[mt][nt][1];
                stash[(row + 8) * 132 + col]     = racc[mt][nt][2];
                stash[(row + 8) * 132 + col + 1] = racc[mt][nt][3];
                stash[GSMF + row * 132 + col]     = gacc[mt][nt][0];
                stash[GSMF + row * 132 + col + 1] = gacc[mt][nt][1];
                stash[GSMF + (row + 8) * 132 + col]     = gacc[mt][nt][2];
                stash[GSMF + (row + 8) * 132 + col + 1] = gacc[mt][nt][3];
            }
        __syncthreads();

        if (do_epi) {
            __half* hhp = Hh + (size_t)i * RH + grow * H_DIM + hc0;
            __half* hlp = Hl + (size_t)i * RH + grow * H_DIM + hc0;
#pragma unroll
            for (int q = 0; q < 2; q++) {
                float4 gi = *(const float4*)(gpre + erow * 128 +       hb + q * 4);
                float4 gf = *(const float4*)(gpre + erow * 128 +  32 + hb + q * 4);
                float4 gg = *(const float4*)(gpre + erow * 128 +  64 + hb + q * 4);
                float4 go = *(const float4*)(gpre + erow * 128 +  96 + hb + q * 4);
                float4 co = make_float4(0.f, 0.f, 0.f, 0.f);
                if (i > 0) co = *(const float4*)(cpre + erow * 32 + hb + q * 4);
                float4 cv;
                __half bh4[4], bl4[4];
#pragma unroll
                for (int e = 0; e < 4; e++) {
                    int li = erow * 132 + hb + q * 4 + e;
                    float xi = stash[li]       + ((const float*)&gi)[e];
                    float xf = stash[li + 32]  + ((const float*)&gf)[e];
                    float xg = stash[li + 64]  + ((const float*)&gg)[e];
                    float xo = stash[li + 96]  + ((const float*)&go)[e];
                    float I = fsig(xi);
                    float F = fsig(xf);
                    float Gv = ftanh(xg);
                    float O = fsig(xo);
                    float cn = F * ((const float*)&co)[e] + I * Gv;
                    float hn = O * ftanh(cn);
                    ((float*)&cv)[e] = cn;
                    bh4[e] = __float2half_rn(hn);
                    bl4[e] = __float2half_rn(hn - __half2float(bh4[e]));
                }
                *(float4*)(cp + q * 4) = cv;
                __half2 p0; p0.x = bh4[0]; p0.y = bh4[1];
                __half2 p1; p1.x = bh4[2]; p1.y = bh4[3];
                __half2 q0; q0.x = bl4[0]; q0.y = bl4[1];
                __half2 q1; q1.x = bl4[2]; q1.y = bl4[3];
                *(__half2*)(hhp + q * 4)     = p0;
                *(__half2*)(hhp + q * 4 + 2) = p1;
                *(__half2*)(hlp + q * 4)     = q0;
                *(__half2*)(hlp + q * 4 + 2) = q1;
            }
        }

        if (i >= 1) {
            // coalesced write of G_next[i-1] with bias (reads gacc half)
            int row = tid >> 2, c0 = (tid & 3) * 32;
            float* gp = Gout + ((size_t)(i - 1) * R_ROWS + bm + row) * G_COLS + cb * 128;
#pragma unroll
            for (int q = 0; q < 8; q++) {
                int col = c0 + q * 4;
                float4 v = *(float4*)(stash + GSMF + row * 132 + col);
                float4 bv = *(const float4*)(nbias + cb * 128 + col);
                v.x += bv.x; v.y += bv.y; v.z += bv.z; v.w += bv.w;
                *(float4*)(gp + col) = v;
            }
        }

        if (do_epi) grid_bar_local(blockIdx.y);
    }
}

// ---------------- head kernels -------------------------------------------------
__global__ void clstm_gather_r(const __half* __restrict__ Hhi,
                               const __half* __restrict__ Hlo,
                               float* __restrict__ r) {
    int b = blockIdx.x, i = blockIdx.y, h = threadIdx.x;
    size_t idx = ((size_t)(T_LEN - 1) * R_ROWS + i * B_SZ + b) * H_DIM + h;
    r[(size_t)b * 1536 + i * H_DIM + h] =
        __half2float(Hhi[idx]) + __half2float(Hlo[idx]);
}

__global__ void clstm_bn(float* __restrict__ x, const float* __restrict__ gamma,
                         const float* __restrict__ beta, int N) {
    __shared__ float s1[256], s2[256];
    int col = blockIdx.x;
    float v = x[(size_t)threadIdx.x * N + col];
    s1[threadIdx.x] = v; s2[threadIdx.x] = v * v;
    __syncthreads();
    for (int s = 128; s > 0; s >>= 1) {
        if (threadIdx.x < s) {
            s1[threadIdx.x] += s1[threadIdx.x + s];
            s2[threadIdx.x] += s2[threadIdx.x + s];
        }
        __syncthreads();
    }
    float m = s1[0] * (1.f / 256.f);
    float var = s2[0] * (1.f / 256.f) - m * m;
    float inv = rsqrtf(var + 1e-3f);
    x[(size_t)threadIdx.x * N + col] = gamma[col] * (v - m) * inv + beta[col];
}

__global__ void clstm_gemm_head(const float* __restrict__ A, const float* __restrict__ W,
                                const float* __restrict__ bias, float* __restrict__ C,
                                int K, int N, int act) {
    int n = blockIdx.x * 128 + threadIdx.x;
    int m0 = blockIdx.y * 16;
    if (n >= N) return;
    float s[16];
#pragma unroll
    for (int mm = 0; mm < 16; mm++) s[mm] = bias[n];
    for (int k = 0; k < K; k++) {
        float w = W[(size_t)k * N + n];
#pragma unroll
        for (int mm = 0; mm < 16; mm++)
            s[mm] += A[(size_t)(m0 + mm) * K + k] * w;
    }
    const float alpha = 1.6732632423543772f, scale = 1.0507009873554805f;
#pragma unroll
    for (int mm = 0; mm < 16; mm++) {
        float v = s[mm];
        if (act) v = scale * (v > 0.f ? v : alpha * expm1f(v));
        C[(size_t)(m0 + mm) * N + n] = v;
    }
}

// ---------------- launch --------------------------------------------------------
extern "C" void kernel_launch(void* const* d_in, const int* in_sizes, int n_in,
                              void* d_out, int out_size) {
    const int* t1 = (const int*)d_in[0];
    const int* t2 = (const int*)d_in[1];
    const int* t3 = (const int*)d_in[2];
    const float* emb = (const float*)d_in[3];
    const float* Wx = (const float*)d_in[4];
    const float* Wh = (const float*)d_in[5];
    const float* bb = (const float*)d_in[6];
    const float* g1 = (const float*)d_in[7];
    const float* be1 = (const float*)d_in[8];
    const float* W1 = (const float*)d_in[9];
    const float* bd1 = (const float*)d_in[10];
    const float* g2 = (const float*)d_in[11];
    const float* be2 = (const float*)d_in[12];
    const float* W2 = (const float*)d_in[13];
    const float* bd2 = (const float*)d_in[14];
    const float* g3 = (const float*)d_in[15];
    const float* be3 = (const float*)d_in[16];
    const float* W3 = (const float*)d_in[17];
    const float* bd3 = (const float*)d_in[18];
    float* out = (float*)d_out;

    float *G, *TAB, *C, *R, *H1, *H2;
    int* TOK;
    __half *Eh, *El, *WhPh, *WhPl, *WxTh, *WxTl, *sAh, *sAl, *sBh, *sBl;
    cudaGetSymbolAddress((void**)&G, d_Gbuf);
    cudaGetSymbolAddress((void**)&TAB, d_tab);
    cudaGetSymbolAddress((void**)&C, d_cst);
    cudaGetSymbolAddress((void**)&R, d_rbuf);
    cudaGetSymbolAddress((void**)&H1, d_h1buf);
    cudaGetSymbolAddress((void**)&H2, d_h2buf);
    cudaGetSymbolAddress((void**)&TOK, d_toks);
    cudaGetSymbolAddress((void**)&Eh, d_Ehi);
    cudaGetSymbolAddress((void**)&El, d_Elo);
    cudaGetSymbolAddress((void**)&WhPh, d_WhPhi);
    cudaGetSymbolAddress((void**)&WhPl, d_WhPlo);
    cudaGetSymbolAddress((void**)&WxTh, d_WxThi);
    cudaGetSymbolAddress((void**)&WxTl, d_WxTlo);
    cudaGetSymbolAddress((void**)&sAh, d_sAhi);
    cudaGetSymbolAddress((void**)&sAl, d_sAlo);
    cudaGetSymbolAddress((void**)&sBh, d_sBhi);
    cudaGetSymbolAddress((void**)&sBl, d_sBlo);

    cudaFuncSetAttribute(clstm_gemm_mma, cudaFuncAttributeMaxDynamicSharedMemorySize,
                         MMA_SMEM);
    cudaFuncSetAttribute(clstm_seq96, cudaFuncAttributeMaxDynamicSharedMemorySize,
                         SEQ_SMEM);
    cudaFuncSetAttribute(clstm_seqf, cudaFuncAttributeMaxDynamicSharedMemorySize,
                         SEQF_SMEM);

    // preprocessing
    cudaMemcpyAsync(TOK,          t1, 65536 * sizeof(int), cudaMemcpyDeviceToDevice, 0);
    cudaMemcpyAsync(TOK + 65536,  t2, 65536 * sizeof(int), cudaMemcpyDeviceToDevice, 0);
    cudaMemcpyAsync(TOK + 131072, t3, 65536 * sizeof(int), cudaMemcpyDeviceToDevice, 0);
    clstm_splitemb<<<V_SZ, 128>>>(emb, Eh, El);
    clstm_makeWsplit<<<dim3(64, 16, 3), dim3(32, 8)>>>(Wh, WhPh, WhPl, 1);
    clstm_makeWsplit<<<dim3(64, 16, 3), dim3(32, 8)>>>(Wx, WxTh, WxTl, 0);
    // vocab gate table: tab = emb @ Wx0 + b0   [32000, 2048] (3 planes, near-exact)
    clstm_gemm_mma<<<dim3(16, V_SZ / 64), 256, MMA_SMEM>>>(
        Eh, El, WxTh, WxTl, bb, TAB);

    const size_t woff = (size_t)G_COLS * H_DIM;
    // layer 1 (fused): gates from tab[token]; h1 -> sB; G2 gates -> G
    clstm_seqf<<<dim3(16, 8), 384, SEQF_SMEM>>>(
        (const float*)0, TOK, TAB, WhPh, WhPl,
        WxTh + woff, WxTl + woff, bb + G_COLS, G, C, sBh, sBl);
    // layer 2 (fused, G in-place): reads G2 gates from G[t], writes G3 to G[t-1]
    clstm_seqf<<<dim3(16, 8), 384, SEQF_SMEM>>>(
        G, (const int*)0, (const float*)0, WhPh + woff, WhPl + woff,
        WxTh + 2 * woff, WxTl + 2 * woff, bb + 2 * G_COLS, G, C, sAh, sAl);
    // layer 3 (plain): gates from G; h3 -> sB
    clstm_seq96<<<dim3(16, 8), 384, SEQ_SMEM>>>(
        G, (const int*)0, (const float*)0,
        WhPh + 2 * woff, WhPl + 2 * woff, C, sBh, sBl);

    // head
    clstm_gather_r<<<dim3(B_SZ, 3), H_DIM>>>(sBh, sBl, R);
    clstm_bn<<<1536, 256>>>(R, g1, be1, 1536);
    clstm_gemm_head<<<dim3(8, 16), 128>>>(R, W1, bd1, H1, 1536, 1024, 1);
    clstm_bn<<<1024, 256>>>(H1, g2, be2, 1024);
    clstm_gemm_head<<<dim3(1, 16), 128>>>(H1, W2, bd2, H2, 1024, H5, 1);
    clstm_bn<<<H5, 256>>>(H2, g3, be3, H5);
    clstm_gemm_head<<<dim3(1, 16), 128>>>(H2, W3, bd3, out, H5, 4, 0);
}